// round 3
// baseline (speedup 1.0000x reference)
#include <cuda_runtime.h>
#include <math.h>

// ---- problem dims ----
#define NSAMP 10000
#define LTOK  32
#define DD    300
#define HH    300
#define BB    256
#define NMX   128
#define ITERS 50

// ---- scratch ----
__device__ float g_enc [NSAMP*DD];
__device__ float g_h1  [NSAMP*HH];
__device__ float g_henc[NSAMP*HH];
__device__ float g_Hc  [2*NSAMP*HH];
__device__ float g_invh[NSAMP];
__device__ float g_Kmat[BB*NMX*NMX];
__device__ float g_Pmat[BB*NMX*NMX];
__device__ float g_cr  [BB*HH];
__device__ float g_cc  [BB*HH];

// ---- streams/events created at static init (pre-checkpoint) ----
struct HxStreams {
    cudaStream_t sB;
    cudaEvent_t eHenc, eHc;
    HxStreams() {
        cudaStreamCreateWithFlags(&sB, cudaStreamNonBlocking);
        cudaEventCreateWithFlags(&eHenc, cudaEventDisableTiming);
        cudaEventCreateWithFlags(&eHc,   cudaEventDisableTiming);
    }
};
static HxStreams g_hx;

// ============================================================
// 1) embedding + masked mean pool
// ============================================================
__global__ void k_embed(const int* __restrict__ data,
                        const float* __restrict__ emb,
                        float* __restrict__ enc) {
    int s = blockIdx.x;
    int t = threadIdx.x;            // 320 threads
    __shared__ int toks[LTOK];
    if (t < LTOK) toks[t] = data[s*LTOK + t];
    __syncthreads();
    int cnt = 0;
#pragma unroll
    for (int l = 0; l < LTOK; l++) cnt += (toks[l] != 0);
    float inv = 1.0f / (float)(cnt > 0 ? cnt : 1);
    if (t < DD) {
        float acc = 0.f;
#pragma unroll
        for (int l = 0; l < LTOK; l++) {
            int tok = toks[l];
            if (tok != 0) acc += emb[tok*DD + t];
        }
        enc[s*DD + t] = acc * inv;
    }
}

// ============================================================
// 2) SGEMM 128x128x16, double-buffered, TM=TN=8, 256 threads
// ============================================================
template<bool RELU>
__global__ void k_sgemm128(const float* __restrict__ A, const float* __restrict__ B,
                           const float* __restrict__ bias, float* __restrict__ C,
                           int M, int N, int K, long bStride, long cStride) {
    B += (long)blockIdx.z * bStride;
    C += (long)blockIdx.z * cStride;
    __shared__ float As[2][16*132];
    __shared__ float Bs[2][16*128];
    int t = threadIdx.x, tx = t & 15, ty = t >> 4;
    int mBase = blockIdx.y * 128, nBase = blockIdx.x * 128;
    float acc[8][8] = {};
    int nT = (K + 15) >> 4;

#define SG_LOAD(k0, buf)                                                    \
    {                                                                       \
        _Pragma("unroll")                                                   \
        for (int p = 0; p < 2; p++) {                                       \
            int id = p*256 + t;                                             \
            int m = id >> 2, kq = id & 3;                                   \
            int gm = mBase + m, gk = (k0) + kq*4;                           \
            float4 v = make_float4(0.f,0.f,0.f,0.f);                        \
            if (gm < M && gk < K) v = *(const float4*)&A[(size_t)gm*K + gk];\
            As[buf][(kq*4+0)*132 + m] = v.x;                                \
            As[buf][(kq*4+1)*132 + m] = v.y;                                \
            As[buf][(kq*4+2)*132 + m] = v.z;                                \
            As[buf][(kq*4+3)*132 + m] = v.w;                                \
        }                                                                   \
        _Pragma("unroll")                                                   \
        for (int p = 0; p < 2; p++) {                                       \
            int id = p*256 + t;                                             \
            int kr = id >> 5, nq = id & 31;                                 \
            int gk = (k0) + kr, gn = nBase + nq*4;                          \
            float4 v = make_float4(0.f,0.f,0.f,0.f);                        \
            if (gk < K && gn < N) v = *(const float4*)&B[(size_t)gk*N + gn];\
            *(float4*)&Bs[buf][kr*128 + nq*4] = v;                          \
        }                                                                   \
    }

    SG_LOAD(0, 0);
    __syncthreads();
    for (int ti = 0; ti < nT; ti++) {
        int cur = ti & 1;
        if (ti + 1 < nT) SG_LOAD((ti+1)*16, cur^1);
        const float* Asb = As[cur];
        const float* Bsb = Bs[cur];
#pragma unroll
        for (int kk = 0; kk < 16; kk++) {
            float4 a0 = *(const float4*)&Asb[kk*132 + ty*4];
            float4 a1 = *(const float4*)&Asb[kk*132 + 64 + ty*4];
            float4 b0 = *(const float4*)&Bsb[kk*128 + tx*4];
            float4 b1 = *(const float4*)&Bsb[kk*128 + 64 + tx*4];
            float av[8] = {a0.x,a0.y,a0.z,a0.w,a1.x,a1.y,a1.z,a1.w};
            float bv[8] = {b0.x,b0.y,b0.z,b0.w,b1.x,b1.y,b1.z,b1.w};
#pragma unroll
            for (int i = 0; i < 8; i++)
#pragma unroll
                for (int j = 0; j < 8; j++) acc[i][j] += av[i]*bv[j];
        }
        __syncthreads();
    }
#undef SG_LOAD
#pragma unroll
    for (int i = 0; i < 8; i++) {
        int gm = mBase + ((i < 4) ? ty*4 + i : 64 + ty*4 + i - 4);
        if (gm >= M) continue;
#pragma unroll
        for (int jh = 0; jh < 2; jh++) {
            int gn = nBase + jh*64 + tx*4;
            if (gn >= N) continue;
            float4 bb = bias ? *(const float4*)&bias[gn] : make_float4(0.f,0.f,0.f,0.f);
            float4 o;
            o.x = acc[i][jh*4+0] + bb.x;
            o.y = acc[i][jh*4+1] + bb.y;
            o.z = acc[i][jh*4+2] + bb.z;
            o.w = acc[i][jh*4+3] + bb.w;
            if (RELU) {
                o.x = fmaxf(o.x, 0.f); o.y = fmaxf(o.y, 0.f);
                o.z = fmaxf(o.z, 0.f); o.w = fmaxf(o.w, 0.f);
            }
            *(float4*)&C[(size_t)gm*N + gn] = o;
        }
    }
}

// ============================================================
// 3) per-sample inverse norm of henc
// ============================================================
__global__ void k_invnorm(const float* __restrict__ henc, float* __restrict__ invh) {
    int s = blockIdx.x * 8 + (threadIdx.x >> 5);
    int l = threadIdx.x & 31;
    if (s >= NSAMP) return;
    const float4* hp = (const float4*)(henc + (size_t)s*HH);
    float sq = 0.f;
    for (int d4 = l; d4 < 75; d4 += 32) {
        float4 v = hp[d4];
        sq += v.x*v.x + v.y*v.y + v.z*v.z + v.w*v.w;
    }
#pragma unroll
    for (int o = 16; o; o >>= 1) sq += __shfl_down_sync(0xffffffffu, sq, o);
    if (l == 0) invh[s] = 1.0f / (sqrtf(sq) + 1e-8f);
}

// ============================================================
// 4) fused gather + cosine cost + Gibbs kernel, double-buffered
// ============================================================
__global__ void k_cost(const float* __restrict__ henc, const float* __restrict__ invh,
                       const int* __restrict__ ridx, const int* __restrict__ cidx,
                       const int* __restrict__ rlen, const int* __restrict__ clen,
                       float* __restrict__ Kout) {
    int b = blockIdx.x;
    __shared__ float As[2][16*132], Bs[2][16*132];
    __shared__ int sr[128], sc[128];
    __shared__ float sir[128], sic[128];
    int t = threadIdx.x, tx = t & 15, ty = t >> 4;
    if (t < 128) {
        int i = ridx[b*128 + t];
        sr[t] = i; sir[t] = invh[i];
    } else {
        int i = cidx[b*128 + (t-128)];
        sc[t-128] = i; sic[t-128] = invh[i];
    }
    __syncthreads();

#define CO_LOAD(k0, buf)                                                      \
    {                                                                         \
        _Pragma("unroll")                                                     \
        for (int p = 0; p < 2; p++) {                                         \
            int id = p*256 + t;                                               \
            int m = id >> 2, kq = id & 3;                                     \
            int gk = (k0) + kq*4;                                             \
            float4 va = make_float4(0.f,0.f,0.f,0.f), vb = va;                \
            if (gk < 300) {                                                   \
                va = *(const float4*)&henc[(size_t)sr[m]*300 + gk];           \
                vb = *(const float4*)&henc[(size_t)sc[m]*300 + gk];           \
            }                                                                 \
            As[buf][(kq*4+0)*132 + m] = va.x; As[buf][(kq*4+1)*132 + m] = va.y;\
            As[buf][(kq*4+2)*132 + m] = va.z; As[buf][(kq*4+3)*132 + m] = va.w;\
            Bs[buf][(kq*4+0)*132 + m] = vb.x; Bs[buf][(kq*4+1)*132 + m] = vb.y;\
            Bs[buf][(kq*4+2)*132 + m] = vb.z; Bs[buf][(kq*4+3)*132 + m] = vb.w;\
        }                                                                     \
    }

    float acc[8][8] = {};
    CO_LOAD(0, 0);
    __syncthreads();
    for (int ti = 0; ti < 19; ti++) {
        int cur = ti & 1;
        if (ti + 1 < 19) CO_LOAD((ti+1)*16, cur^1);
        const float* Asb = As[cur];
        const float* Bsb = Bs[cur];
#pragma unroll
        for (int kk = 0; kk < 16; kk++) {
            float4 a0 = *(const float4*)&Asb[kk*132 + ty*4];
            float4 a1 = *(const float4*)&Asb[kk*132 + 64 + ty*4];
            float4 b0 = *(const float4*)&Bsb[kk*132 + tx*4];
            float4 b1 = *(const float4*)&Bsb[kk*132 + 64 + tx*4];
            float av[8] = {a0.x,a0.y,a0.z,a0.w,a1.x,a1.y,a1.z,a1.w};
            float bv[8] = {b0.x,b0.y,b0.z,b0.w,b1.x,b1.y,b1.z,b1.w};
#pragma unroll
            for (int i = 0; i < 8; i++)
#pragma unroll
                for (int j = 0; j < 8; j++) acc[i][j] += av[i]*bv[j];
        }
        __syncthreads();
    }
#undef CO_LOAD
    int rl = rlen[b], cl = clen[b];
    float* out = Kout + (size_t)b*NMX*NMX;
#pragma unroll
    for (int i = 0; i < 8; i++) {
        int n = (i < 4) ? ty*4 + i : 64 + ty*4 + i - 4;
        float ir = sir[n];
        bool nv = (n < rl);
#pragma unroll
        for (int jh = 0; jh < 2; jh++) {
            float4 kv;
            float r[4];
#pragma unroll
            for (int j = 0; j < 4; j++) {
                int m = jh*64 + tx*4 + j;
                float dn = acc[i][jh*4+j] * ir * sic[m];
                r[j] = (nv && m < cl) ? __expf((dn - 1.0f) * 10.0f) : 0.f;
            }
            kv.x = r[0]; kv.y = r[1]; kv.z = r[2]; kv.w = r[3];
            *(float4*)&out[n*128 + jh*64 + tx*4] = kv;
        }
    }
}

// ============================================================
// 5) Sinkhorn (multiplicative), K in SMEM pad-132
// ============================================================
__global__ void k_sinkhorn(const float* __restrict__ Kg,
                           const int* __restrict__ rlen,
                           const int* __restrict__ clen,
                           float* __restrict__ P) {
    extern __shared__ float sm[];
    float* Ks  = sm;               // 128*132
    float* u   = Ks + 128*132;     // 128
    float* v   = u + 128;          // 128
    float* red = v + 128;          // 4*128
    int b = blockIdx.x, t = threadIdx.x;
    const float* Kb = Kg + (size_t)b*NMX*NMX;
#pragma unroll 4
    for (int i = 0; i < 128; i++) Ks[i*132 + t] = Kb[i*128 + t];
    int rl = rlen[b], cl = clen[b];
    float ra = 1.0f / (float)rl, rb = 1.0f / (float)cl;
    u[t] = (t < cl) ? 1.0f : 0.0f;
    __syncthreads();

    int w = t >> 5, l = t & 31;
    const float4* Kr4 = (const float4*)(Ks + t*132);
    const float4* u4  = (const float4*)u;
    for (int it = 0; it < ITERS; it++) {
        float4 s4 = make_float4(0.f,0.f,0.f,0.f);
#pragma unroll
        for (int m = 0; m < 32; m++) {
            float4 k4 = Kr4[m], uu = u4[m];
            s4.x += k4.x*uu.x; s4.y += k4.y*uu.y;
            s4.z += k4.z*uu.z; s4.w += k4.w*uu.w;
        }
        float s = (s4.x + s4.y) + (s4.z + s4.w);
        v[t] = (t < rl) ? ra / s : 0.f;
        __syncthreads();
        float4 q4 = make_float4(0.f,0.f,0.f,0.f);
#pragma unroll
        for (int r = 0; r < 32; r++) {
            int n = w*32 + r;
            float vn = v[n];
            float4 k4 = *(const float4*)(Ks + n*132 + l*4);
            q4.x += k4.x*vn; q4.y += k4.y*vn;
            q4.z += k4.z*vn; q4.w += k4.w*vn;
        }
        *(float4*)(red + w*128 + l*4) = q4;
        __syncthreads();
        float q = red[t] + red[128 + t] + red[256 + t] + red[384 + t];
        u[t] = (t < cl) ? rb / q : 0.f;
        __syncthreads();
    }
    float ut = u[t];
    float* Pb = P + (size_t)b*NMX*NMX;
#pragma unroll 4
    for (int i = 0; i < 128; i++)
        Pb[i*128 + t] = v[i] * Ks[i*132 + t] * ut;
}

// ============================================================
// 6) P-GEMM + compare epilogue, 128x128 tiles, double-buffered
// ============================================================
__global__ void k_pcmp(const float* __restrict__ P,
                       const float* __restrict__ Hc1, const float* __restrict__ Hc2,
                       const float* __restrict__ bc,
                       const int* __restrict__ ridx, const int* __restrict__ cidx,
                       const int* __restrict__ rlen, const int* __restrict__ clen,
                       float* __restrict__ cr, float* __restrict__ cc) {
    int b = blockIdx.z, mode = blockIdx.y;
    int hBase = blockIdx.x * 128;
    const int* gidxA = mode ? (ridx + b*128) : (cidx + b*128);
    const int* gidxE = mode ? (cidx + b*128) : (ridx + b*128);
    int len = mode ? clen[b] : rlen[b];
    const float* Pb = P + (size_t)b*NMX*NMX;

    __shared__ float As[2][16*132];
    __shared__ float Bs[2][16*128];
    __shared__ int sA[128], sE[128];
    __shared__ float redsm[16*132];
    int t = threadIdx.x, tx = t & 15, ty = t >> 4;
    if (t < 128) sA[t] = gidxA[t];
    else sE[t-128] = gidxE[t-128];
    __syncthreads();

#define PC_LOAD(k0, buf)                                                      \
    {                                                                         \
        if (mode == 0) {                                                      \
            _Pragma("unroll")                                                 \
            for (int p = 0; p < 2; p++) {                                     \
                int id = p*256 + t;                                           \
                int n = id >> 2, kq = id & 3;                                 \
                float4 vv = *(const float4*)&Pb[n*128 + (k0) + kq*4];         \
                As[buf][(kq*4+0)*132 + n] = vv.x;                             \
                As[buf][(kq*4+1)*132 + n] = vv.y;                             \
                As[buf][(kq*4+2)*132 + n] = vv.z;                             \
                As[buf][(kq*4+3)*132 + n] = vv.w;                             \
            }                                                                 \
        } else {                                                              \
            _Pragma("unroll")                                                 \
            for (int p = 0; p < 2; p++) {                                     \
                int id = p*256 + t;                                           \
                int kr = id >> 5, mq = id & 31;                               \
                float4 vv = *(const float4*)&Pb[((k0) + kr)*128 + mq*4];      \
                *(float4*)&As[buf][kr*132 + mq*4] = vv;                       \
            }                                                                 \
        }                                                                     \
        _Pragma("unroll")                                                     \
        for (int p = 0; p < 2; p++) {                                         \
            int id = p*256 + t;                                               \
            int kr = id >> 5, hq = id & 31;                                   \
            int hg = hBase + hq*4;                                            \
            float4 vv = make_float4(0.f,0.f,0.f,0.f);                         \
            if (hg < 300) vv = *(const float4*)&Hc2[(size_t)sA[(k0)+kr]*300 + hg];\
            *(float4*)&Bs[buf][kr*128 + hq*4] = vv;                           \
        }                                                                     \
    }

    float acc[8][8] = {};
    PC_LOAD(0, 0);
    __syncthreads();
    for (int ti = 0; ti < 8; ti++) {
        int cur = ti & 1;
        if (ti + 1 < 8) PC_LOAD((ti+1)*16, cur^1);
        const float* Asb = As[cur];
        const float* Bsb = Bs[cur];
#pragma unroll
        for (int kk = 0; kk < 16; kk++) {
            float4 a0 = *(const float4*)&Asb[kk*132 + ty*4];
            float4 a1 = *(const float4*)&Asb[kk*132 + 64 + ty*4];
            float4 b0 = *(const float4*)&Bsb[kk*128 + tx*4];
            float4 b1 = *(const float4*)&Bsb[kk*128 + 64 + tx*4];
            float av[8] = {a0.x,a0.y,a0.z,a0.w,a1.x,a1.y,a1.z,a1.w};
            float bv[8] = {b0.x,b0.y,b0.z,b0.w,b1.x,b1.y,b1.z,b1.w};
#pragma unroll
            for (int i = 0; i < 8; i++)
#pragma unroll
                for (int j = 0; j < 8; j++) acc[i][j] += av[i]*bv[j];
        }
        __syncthreads();
    }
#undef PC_LOAD

    int hg0 = hBase + tx*4;
    int hg1 = hBase + 64 + tx*4;
    float4 bc0 = (hg0 < 300) ? *(const float4*)&bc[hg0] : make_float4(0.f,0.f,0.f,0.f);
    float4 bc1 = (hg1 < 300) ? *(const float4*)&bc[hg1] : make_float4(0.f,0.f,0.f,0.f);
    float bca[8] = {bc0.x,bc0.y,bc0.z,bc0.w,bc1.x,bc1.y,bc1.z,bc1.w};
    float sums[8] = {};
#pragma unroll
    for (int i = 0; i < 8; i++) {
        int r = (i < 4) ? ty*4 + i : 64 + ty*4 + i - 4;
        if (r < len) {
            const float* h1p = Hc1 + (size_t)sE[r]*300;
            float4 a0 = (hg0 < 300) ? *(const float4*)&h1p[hg0] : make_float4(0.f,0.f,0.f,0.f);
            float4 a1 = (hg1 < 300) ? *(const float4*)&h1p[hg1] : make_float4(0.f,0.f,0.f,0.f);
            float ad[8] = {a0.x,a0.y,a0.z,a0.w,a1.x,a1.y,a1.z,a1.w};
#pragma unroll
            for (int j = 0; j < 8; j++)
                sums[j] += fmaxf(acc[i][j] + ad[j] + bca[j], 0.f);
        }
    }
#pragma unroll
    for (int j = 0; j < 8; j++) {
        int pos = (j < 4) ? tx*4 + j : 64 + tx*4 + (j - 4);
        redsm[ty*132 + pos] = sums[j];
    }
    __syncthreads();
    if (t < 128) {
        float s = 0.f;
#pragma unroll
        for (int r = 0; r < 16; r++) s += redsm[r*132 + t];
        int hg = hBase + t;
        if (hg < 300) {
            float* outp = mode ? cc : cr;
            outp[b*HH + hg] = s;
        }
    }
}

// ============================================================
// 7) classifier head
// ============================================================
__global__ void k_cls(const float* __restrict__ cr,
                      const float* __restrict__ cc,
                      const float* __restrict__ Wcls,
                      const float* __restrict__ bcls,
                      const float* __restrict__ Wout,
                      const float* __restrict__ bout,
                      float* __restrict__ out) {
    int b = blockIdx.x;
    int t = threadIdx.x;              // 320 threads
    __shared__ float x[2*HH];
    for (int i = t; i < 2*HH; i += 320)
        x[i] = (i < HH) ? cr[b*HH + i] : cc[b*HH + i - HH];
    __syncthreads();
    float z = 0.f;
    if (t < HH) {
        float a0 = 0.f, a1 = 0.f, a2 = 0.f, a3 = 0.f;
#pragma unroll 4
        for (int k = 0; k < 2*HH; k += 4) {
            a0 += x[k+0]*Wcls[(k+0)*HH + t];
            a1 += x[k+1]*Wcls[(k+1)*HH + t];
            a2 += x[k+2]*Wcls[(k+2)*HH + t];
            a3 += x[k+3]*Wcls[(k+3)*HH + t];
        }
        z = fmaxf((a0+a1)+(a2+a3) + bcls[t], 0.f);
    }
    float s0 = (t < HH) ? z*Wout[t*2 + 0] : 0.f;
    float s1 = (t < HH) ? z*Wout[t*2 + 1] : 0.f;
#pragma unroll
    for (int o = 16; o; o >>= 1) {
        s0 += __shfl_down_sync(0xffffffffu, s0, o);
        s1 += __shfl_down_sync(0xffffffffu, s1, o);
    }
    __shared__ float r0[10], r1[10];
    if ((t & 31) == 0) { r0[t >> 5] = s0; r1[t >> 5] = s1; }
    __syncthreads();
    if (t == 0) {
        float a = 0.f, c = 0.f;
#pragma unroll
        for (int i = 0; i < 10; i++) { a += r0[i]; c += r1[i]; }
        out[b*2 + 0] = a + bout[0];
        out[b*2 + 1] = c + bout[1];
    }
}

// ============================================================
// launch
// ============================================================
extern "C" void kernel_launch(void* const* d_in, const int* in_sizes, int n_in,
                              void* d_out, int out_size) {
    const int*   data    = (const int*)  d_in[0];
    const int*   row_idx = (const int*)  d_in[1];
    const int*   col_idx = (const int*)  d_in[2];
    const int*   row_len = (const int*)  d_in[3];
    const int*   col_len = (const int*)  d_in[4];
    const float* emb     = (const float*)d_in[5];
    const float* W1      = (const float*)d_in[6];
    const float* b1      = (const float*)d_in[7];
    const float* W2      = (const float*)d_in[8];
    const float* b2      = (const float*)d_in[9];
    const float* Wc      = (const float*)d_in[10];
    const float* bc      = (const float*)d_in[11];
    const float* Wcls    = (const float*)d_in[12];
    const float* bcls    = (const float*)d_in[13];
    const float* Wout    = (const float*)d_in[14];
    const float* bout    = (const float*)d_in[15];
    float* out = (float*)d_out;

    float *enc, *h1, *henc, *Hc, *invh, *Kb, *Pb, *cr, *cc;
    cudaGetSymbolAddress((void**)&enc,  g_enc);
    cudaGetSymbolAddress((void**)&h1,   g_h1);
    cudaGetSymbolAddress((void**)&henc, g_henc);
    cudaGetSymbolAddress((void**)&Hc,   g_Hc);
    cudaGetSymbolAddress((void**)&invh, g_invh);
    cudaGetSymbolAddress((void**)&Kb,   g_Kmat);
    cudaGetSymbolAddress((void**)&Pb,   g_Pmat);
    cudaGetSymbolAddress((void**)&cr,   g_cr);
    cudaGetSymbolAddress((void**)&cc,   g_cc);
    float* Hc1 = Hc;
    float* Hc2 = Hc + (long)NSAMP*HH;

    // 1) embedding pool
    k_embed<<<NSAMP, 320>>>(data, emb, enc);
    // 2) FFN (serial chain on default stream)
    dim3 gF(3, 79, 1);
    k_sgemm128<true><<<gF, 256>>>(enc, W1, b1, h1,   NSAMP, HH, DD, 0, 0);
    k_sgemm128<true><<<gF, 256>>>(h1,  W2, b2, henc, NSAMP, HH, HH, 0, 0);

    // fork: Hc GEMM on side stream, overlapping invnorm/cost/sinkhorn
    cudaEventRecord(g_hx.eHenc, 0);
    cudaStreamWaitEvent(g_hx.sB, g_hx.eHenc, 0);
    dim3 gHc(3, 79, 2);
    k_sgemm128<false><<<gHc, 256, 0, g_hx.sB>>>(henc, Wc, nullptr, Hc,
                                                NSAMP, HH, HH, (long)HH*HH, (long)NSAMP*HH);
    cudaEventRecord(g_hx.eHc, g_hx.sB);

    // chain A on default stream
    k_invnorm<<<(NSAMP + 7)/8, 256>>>(henc, invh);
    k_cost<<<BB, 256>>>(henc, invh, row_idx, col_idx, row_len, col_len, Kb);
    int sink_smem = (128*132 + 128 + 128 + 512) * (int)sizeof(float);
    cudaFuncSetAttribute(k_sinkhorn, cudaFuncAttributeMaxDynamicSharedMemorySize, sink_smem);
    k_sinkhorn<<<BB, 128, sink_smem>>>(Kb, row_len, col_len, Pb);

    // join
    cudaStreamWaitEvent(0, g_hx.eHc, 0);
    k_pcmp<<<dim3(3, 2, BB), 256>>>(Pb, Hc1, Hc2, bc, row_idx, col_idx,
                                    row_len, col_len, cr, cc);
    k_cls<<<BB, 320>>>(cr, cc, Wcls, bcls, Wout, bout, out);
}

// round 4
// speedup vs baseline: 1.0611x; 1.0611x over previous
#include <cuda_runtime.h>
#include <math.h>
#include <mma.h>
using namespace nvcuda;

// ---- problem dims ----
#define NSAMP 10000
#define LTOK  32
#define DD    300
#define HH    300
#define BB    256
#define NMX   128
#define ITERS 50

// ---- scratch ----
__device__ float g_enc [NSAMP*DD];
__device__ float g_h1  [NSAMP*HH];
__device__ float g_henc[NSAMP*HH];
__device__ float g_Hc  [2*NSAMP*HH];
__device__ float g_invh[NSAMP];
__device__ float g_Kmat[BB*NMX*NMX];
__device__ float g_Pmat[BB*NMX*NMX];
__device__ float g_cr  [BB*HH];
__device__ float g_cc  [BB*HH];

// ---- streams/events created at static init ----
struct HxStreams {
    cudaStream_t sB;
    cudaEvent_t eHenc, eHc;
    HxStreams() {
        cudaStreamCreateWithFlags(&sB, cudaStreamNonBlocking);
        cudaEventCreateWithFlags(&eHenc, cudaEventDisableTiming);
        cudaEventCreateWithFlags(&eHc,   cudaEventDisableTiming);
    }
};
static HxStreams g_hx;

// ============================================================
// 1) embedding + masked mean pool
// ============================================================
__global__ void k_embed(const int* __restrict__ data,
                        const float* __restrict__ emb,
                        float* __restrict__ enc) {
    int s = blockIdx.x;
    int t = threadIdx.x;            // 320 threads
    __shared__ int toks[LTOK];
    if (t < LTOK) toks[t] = data[s*LTOK + t];
    __syncthreads();
    int cnt = 0;
#pragma unroll
    for (int l = 0; l < LTOK; l++) cnt += (toks[l] != 0);
    float inv = 1.0f / (float)(cnt > 0 ? cnt : 1);
    if (t < DD) {
        float acc = 0.f;
#pragma unroll
        for (int l = 0; l < LTOK; l++) {
            int tok = toks[l];
            if (tok != 0) acc += emb[tok*DD + t];
        }
        enc[s*DD + t] = acc * inv;
    }
}

// ============================================================
// 2) WMMA tf32 GEMM: 128x128 tile, BK=32, 8 warps (2M x 4N),
//    warp tile 64x32 = 4x2 m16n16k8 frags. fp32 accumulate.
//    C = [relu](A @ (B + z*bStride) + bias) -> C + z*cStride
// ============================================================
#define WG_AS   (128*36)          // one A stage (floats)
#define WG_BS   (32*132)          // one B stage
#define WG_SMEM ((2*WG_AS + 2*WG_BS)*4)   // bytes = 70656

template<bool RELU>
__global__ void __launch_bounds__(256)
k_wgemm(const float* __restrict__ A, const float* __restrict__ B,
        const float* __restrict__ bias, float* __restrict__ C,
        int M, int N, int K, long bStride, long cStride) {
    B += (long)blockIdx.z * bStride;
    C += (long)blockIdx.z * cStride;
    extern __shared__ float sm[];
    float* Asm = sm;                  // [2][128*36]
    float* Bsm = sm + 2*WG_AS;        // [2][32*132]
    float* Cs  = sm;                  // overlay [128*132]

    int t = threadIdx.x;
    int wid = t >> 5;
    int wm = wid >> 2, wn = wid & 3;  // 2 x 4 warp grid
    int mBase = blockIdx.y * 128, nBase = blockIdx.x * 128;

    wmma::fragment<wmma::accumulator, 16, 16, 8, float> acc[4][2];
#pragma unroll
    for (int i = 0; i < 4; i++)
#pragma unroll
        for (int j = 0; j < 2; j++) wmma::fill_fragment(acc[i][j], 0.f);

    int nT = (K + 31) >> 5;
    float4 ra[4], rb[4];

#define WG_LDG(k0)                                                          \
    {                                                                       \
        _Pragma("unroll")                                                   \
        for (int q = 0; q < 4; q++) {                                       \
            int idx = t + q*256;                                            \
            int m = idx >> 3, k4 = idx & 7;                                 \
            int gm = mBase + m, gk = (k0) + k4*4;                           \
            ra[q] = make_float4(0.f,0.f,0.f,0.f);                           \
            if (gm < M && gk < K) ra[q] = *(const float4*)&A[(size_t)gm*K + gk];\
        }                                                                   \
        _Pragma("unroll")                                                   \
        for (int q = 0; q < 4; q++) {                                       \
            int idx = t + q*256;                                            \
            int kr = idx >> 5, n4 = idx & 31;                               \
            int gk = (k0) + kr, gn = nBase + n4*4;                          \
            rb[q] = make_float4(0.f,0.f,0.f,0.f);                           \
            if (gk < K && gn < N) rb[q] = *(const float4*)&B[(size_t)gk*N + gn];\
        }                                                                   \
    }

#define WG_STS(buf)                                                         \
    {                                                                       \
        float* ap = Asm + (buf)*WG_AS;                                      \
        float* bp = Bsm + (buf)*WG_BS;                                      \
        _Pragma("unroll")                                                   \
        for (int q = 0; q < 4; q++) {                                       \
            int idx = t + q*256;                                            \
            int m = idx >> 3, k4 = idx & 7;                                 \
            float4 v = ra[q];                                               \
            v.x = wmma::__float_to_tf32(v.x); v.y = wmma::__float_to_tf32(v.y);\
            v.z = wmma::__float_to_tf32(v.z); v.w = wmma::__float_to_tf32(v.w);\
            *(float4*)&ap[m*36 + k4*4] = v;                                 \
        }                                                                   \
        _Pragma("unroll")                                                   \
        for (int q = 0; q < 4; q++) {                                       \
            int idx = t + q*256;                                            \
            int kr = idx >> 5, n4 = idx & 31;                               \
            float4 v = rb[q];                                               \
            v.x = wmma::__float_to_tf32(v.x); v.y = wmma::__float_to_tf32(v.y);\
            v.z = wmma::__float_to_tf32(v.z); v.w = wmma::__float_to_tf32(v.w);\
            *(float4*)&bp[kr*132 + n4*4] = v;                               \
        }                                                                   \
    }

    WG_LDG(0);
    WG_STS(0);
    __syncthreads();

    for (int ti = 0; ti < nT; ti++) {
        int cur = ti & 1;
        if (ti + 1 < nT) WG_LDG((ti+1)*32);
        const float* ap = Asm + cur*WG_AS;
        const float* bp = Bsm + cur*WG_BS;
#pragma unroll
        for (int ks = 0; ks < 4; ks++) {
            int k8 = ks*8;
            wmma::fragment<wmma::matrix_a, 16, 16, 8, wmma::precision::tf32, wmma::row_major> af[4];
            wmma::fragment<wmma::matrix_b, 16, 16, 8, wmma::precision::tf32, wmma::row_major> bf[2];
#pragma unroll
            for (int i = 0; i < 4; i++)
                wmma::load_matrix_sync(af[i], ap + (wm*64 + i*16)*36 + k8, 36);
#pragma unroll
            for (int j = 0; j < 2; j++)
                wmma::load_matrix_sync(bf[j], bp + k8*132 + wn*32 + j*16, 132);
#pragma unroll
            for (int i = 0; i < 4; i++)
#pragma unroll
                for (int j = 0; j < 2; j++)
                    wmma::mma_sync(acc[i][j], af[i], bf[j], acc[i][j]);
        }
        if (ti + 1 < nT) WG_STS(cur ^ 1);
        __syncthreads();
    }
#undef WG_LDG
#undef WG_STS

    // epilogue: frags -> smem -> bias/relu -> gmem
#pragma unroll
    for (int i = 0; i < 4; i++)
#pragma unroll
        for (int j = 0; j < 2; j++)
            wmma::store_matrix_sync(&Cs[(wm*64 + i*16)*132 + wn*32 + j*16],
                                    acc[i][j], 132, wmma::mem_row_major);
    __syncthreads();
#pragma unroll
    for (int q = 0; q < 16; q++) {
        int idx = t + q*256;
        int row = idx >> 5, c4 = idx & 31;
        int gm = mBase + row, gn = nBase + c4*4;
        if (gm < M && gn < N) {
            float4 v = *(float4*)&Cs[row*132 + c4*4];
            float4 bb = bias ? *(const float4*)&bias[gn] : make_float4(0.f,0.f,0.f,0.f);
            v.x += bb.x; v.y += bb.y; v.z += bb.z; v.w += bb.w;
            if (RELU) {
                v.x = fmaxf(v.x, 0.f); v.y = fmaxf(v.y, 0.f);
                v.z = fmaxf(v.z, 0.f); v.w = fmaxf(v.w, 0.f);
            }
            *(float4*)&C[(size_t)gm*N + gn] = v;
        }
    }
}

// ============================================================
// 3) per-sample inverse norm of henc
// ============================================================
__global__ void k_invnorm(const float* __restrict__ henc, float* __restrict__ invh) {
    int s = blockIdx.x * 8 + (threadIdx.x >> 5);
    int l = threadIdx.x & 31;
    if (s >= NSAMP) return;
    const float4* hp = (const float4*)(henc + (size_t)s*HH);
    float sq = 0.f;
    for (int d4 = l; d4 < 75; d4 += 32) {
        float4 v = hp[d4];
        sq += v.x*v.x + v.y*v.y + v.z*v.z + v.w*v.w;
    }
#pragma unroll
    for (int o = 16; o; o >>= 1) sq += __shfl_down_sync(0xffffffffu, sq, o);
    if (l == 0) invh[s] = 1.0f / (sqrtf(sq) + 1e-8f);
}

// ============================================================
// 4) fused gather + cosine cost + Gibbs kernel (fp32 scalar)
// ============================================================
__global__ void k_cost(const float* __restrict__ henc, const float* __restrict__ invh,
                       const int* __restrict__ ridx, const int* __restrict__ cidx,
                       const int* __restrict__ rlen, const int* __restrict__ clen,
                       float* __restrict__ Kout) {
    int b = blockIdx.x;
    __shared__ float As[2][16*132], Bs[2][16*132];
    __shared__ int sr[128], sc[128];
    __shared__ float sir[128], sic[128];
    int t = threadIdx.x, tx = t & 15, ty = t >> 4;
    if (t < 128) {
        int i = ridx[b*128 + t];
        sr[t] = i; sir[t] = invh[i];
    } else {
        int i = cidx[b*128 + (t-128)];
        sc[t-128] = i; sic[t-128] = invh[i];
    }
    __syncthreads();

#define CO_LOAD(k0, buf)                                                      \
    {                                                                         \
        _Pragma("unroll")                                                     \
        for (int p = 0; p < 2; p++) {                                         \
            int id = p*256 + t;                                               \
            int m = id >> 2, kq = id & 3;                                     \
            int gk = (k0) + kq*4;                                             \
            float4 va = make_float4(0.f,0.f,0.f,0.f), vb = va;                \
            if (gk < 300) {                                                   \
                va = *(const float4*)&henc[(size_t)sr[m]*300 + gk];           \
                vb = *(const float4*)&henc[(size_t)sc[m]*300 + gk];           \
            }                                                                 \
            As[buf][(kq*4+0)*132 + m] = va.x; As[buf][(kq*4+1)*132 + m] = va.y;\
            As[buf][(kq*4+2)*132 + m] = va.z; As[buf][(kq*4+3)*132 + m] = va.w;\
            Bs[buf][(kq*4+0)*132 + m] = vb.x; Bs[buf][(kq*4+1)*132 + m] = vb.y;\
            Bs[buf][(kq*4+2)*132 + m] = vb.z; Bs[buf][(kq*4+3)*132 + m] = vb.w;\
        }                                                                     \
    }

    float acc[8][8] = {};
    CO_LOAD(0, 0);
    __syncthreads();
    for (int ti = 0; ti < 19; ti++) {
        int cur = ti & 1;
        if (ti + 1 < 19) CO_LOAD((ti+1)*16, cur^1);
        const float* Asb = As[cur];
        const float* Bsb = Bs[cur];
#pragma unroll
        for (int kk = 0; kk < 16; kk++) {
            float4 a0 = *(const float4*)&Asb[kk*132 + ty*4];
            float4 a1 = *(const float4*)&Asb[kk*132 + 64 + ty*4];
            float4 b0 = *(const float4*)&Bsb[kk*132 + tx*4];
            float4 b1 = *(const float4*)&Bsb[kk*132 + 64 + tx*4];
            float av[8] = {a0.x,a0.y,a0.z,a0.w,a1.x,a1.y,a1.z,a1.w};
            float bv[8] = {b0.x,b0.y,b0.z,b0.w,b1.x,b1.y,b1.z,b1.w};
#pragma unroll
            for (int i = 0; i < 8; i++)
#pragma unroll
                for (int j = 0; j < 8; j++) acc[i][j] += av[i]*bv[j];
        }
        __syncthreads();
    }
#undef CO_LOAD
    int rl = rlen[b], cl = clen[b];
    float* out = Kout + (size_t)b*NMX*NMX;
#pragma unroll
    for (int i = 0; i < 8; i++) {
        int n = (i < 4) ? ty*4 + i : 64 + ty*4 + i - 4;
        float ir = sir[n];
        bool nv = (n < rl);
#pragma unroll
        for (int jh = 0; jh < 2; jh++) {
            float4 kv;
            float r[4];
#pragma unroll
            for (int j = 0; j < 4; j++) {
                int m = jh*64 + tx*4 + j;
                float dn = acc[i][jh*4+j] * ir * sic[m];
                r[j] = (nv && m < cl) ? __expf((dn - 1.0f) * 10.0f) : 0.f;
            }
            kv.x = r[0]; kv.y = r[1]; kv.z = r[2]; kv.w = r[3];
            *(float4*)&out[n*128 + jh*64 + tx*4] = kv;
        }
    }
}

// ============================================================
// 5) Sinkhorn (multiplicative), K in SMEM pad-132
// ============================================================
__global__ void k_sinkhorn(const float* __restrict__ Kg,
                           const int* __restrict__ rlen,
                           const int* __restrict__ clen,
                           float* __restrict__ P) {
    extern __shared__ float sm[];
    float* Ks  = sm;               // 128*132
    float* u   = Ks + 128*132;     // 128
    float* v   = u + 128;          // 128
    float* red = v + 128;          // 4*128
    int b = blockIdx.x, t = threadIdx.x;
    const float* Kb = Kg + (size_t)b*NMX*NMX;
#pragma unroll 4
    for (int i = 0; i < 128; i++) Ks[i*132 + t] = Kb[i*128 + t];
    int rl = rlen[b], cl = clen[b];
    float ra = 1.0f / (float)rl, rb = 1.0f / (float)cl;
    u[t] = (t < cl) ? 1.0f : 0.0f;
    __syncthreads();

    int w = t >> 5, l = t & 31;
    const float4* Kr4 = (const float4*)(Ks + t*132);
    const float4* u4  = (const float4*)u;
    for (int it = 0; it < ITERS; it++) {
        float4 s4 = make_float4(0.f,0.f,0.f,0.f);
#pragma unroll
        for (int m = 0; m < 32; m++) {
            float4 k4 = Kr4[m], uu = u4[m];
            s4.x += k4.x*uu.x; s4.y += k4.y*uu.y;
            s4.z += k4.z*uu.z; s4.w += k4.w*uu.w;
        }
        float s = (s4.x + s4.y) + (s4.z + s4.w);
        v[t] = (t < rl) ? ra / s : 0.f;
        __syncthreads();
        float4 q4 = make_float4(0.f,0.f,0.f,0.f);
#pragma unroll
        for (int r = 0; r < 32; r++) {
            int n = w*32 + r;
            float vn = v[n];
            float4 k4 = *(const float4*)(Ks + n*132 + l*4);
            q4.x += k4.x*vn; q4.y += k4.y*vn;
            q4.z += k4.z*vn; q4.w += k4.w*vn;
        }
        *(float4*)(red + w*128 + l*4) = q4;
        __syncthreads();
        float q = red[t] + red[128 + t] + red[256 + t] + red[384 + t];
        u[t] = (t < cl) ? rb / q : 0.f;
        __syncthreads();
    }
    float ut = u[t];
    float* Pb = P + (size_t)b*NMX*NMX;
#pragma unroll 4
    for (int i = 0; i < 128; i++)
        Pb[i*128 + t] = v[i] * Ks[i*132 + t] * ut;
}

// ============================================================
// 6) P-GEMM + compare epilogue (fp32 scalar)
// ============================================================
__global__ void k_pcmp(const float* __restrict__ P,
                       const float* __restrict__ Hc1, const float* __restrict__ Hc2,
                       const float* __restrict__ bc,
                       const int* __restrict__ ridx, const int* __restrict__ cidx,
                       const int* __restrict__ rlen, const int* __restrict__ clen,
                       float* __restrict__ cr, float* __restrict__ cc) {
    int b = blockIdx.z, mode = blockIdx.y;
    int hBase = blockIdx.x * 128;
    const int* gidxA = mode ? (ridx + b*128) : (cidx + b*128);
    const int* gidxE = mode ? (cidx + b*128) : (ridx + b*128);
    int len = mode ? clen[b] : rlen[b];
    const float* Pb = P + (size_t)b*NMX*NMX;

    __shared__ float As[2][16*132];
    __shared__ float Bs[2][16*128];
    __shared__ int sA[128], sE[128];
    __shared__ float redsm[16*132];
    int t = threadIdx.x, tx = t & 15, ty = t >> 4;
    if (t < 128) sA[t] = gidxA[t];
    else sE[t-128] = gidxE[t-128];
    __syncthreads();

#define PC_LOAD(k0, buf)                                                      \
    {                                                                         \
        if (mode == 0) {                                                      \
            _Pragma("unroll")                                                 \
            for (int p = 0; p < 2; p++) {                                     \
                int id = p*256 + t;                                           \
                int n = id >> 2, kq = id & 3;                                 \
                float4 vv = *(const float4*)&Pb[n*128 + (k0) + kq*4];         \
                As[buf][(kq*4+0)*132 + n] = vv.x;                             \
                As[buf][(kq*4+1)*132 + n] = vv.y;                             \
                As[buf][(kq*4+2)*132 + n] = vv.z;                             \
                As[buf][(kq*4+3)*132 + n] = vv.w;                             \
            }                                                                 \
        } else {                                                              \
            _Pragma("unroll")                                                 \
            for (int p = 0; p < 2; p++) {                                     \
                int id = p*256 + t;                                           \
                int kr = id >> 5, mq = id & 31;                               \
                float4 vv = *(const float4*)&Pb[((k0) + kr)*128 + mq*4];      \
                *(float4*)&As[buf][kr*132 + mq*4] = vv;                       \
            }                                                                 \
        }                                                                     \
        _Pragma("unroll")                                                     \
        for (int p = 0; p < 2; p++) {                                         \
            int id = p*256 + t;                                               \
            int kr = id >> 5, hq = id & 31;                                   \
            int hg = hBase + hq*4;                                            \
            float4 vv = make_float4(0.f,0.f,0.f,0.f);                         \
            if (hg < 300) vv = *(const float4*)&Hc2[(size_t)sA[(k0)+kr]*300 + hg];\
            *(float4*)&Bs[buf][kr*128 + hq*4] = vv;                           \
        }                                                                     \
    }

    float acc[8][8] = {};
    PC_LOAD(0, 0);
    __syncthreads();
    for (int ti = 0; ti < 8; ti++) {
        int cur = ti & 1;
        if (ti + 1 < 8) PC_LOAD((ti+1)*16, cur^1);
        const float* Asb = As[cur];
        const float* Bsb = Bs[cur];
#pragma unroll
        for (int kk = 0; kk < 16; kk++) {
            float4 a0 = *(const float4*)&Asb[kk*132 + ty*4];
            float4 a1 = *(const float4*)&Asb[kk*132 + 64 + ty*4];
            float4 b0 = *(const float4*)&Bsb[kk*128 + tx*4];
            float4 b1 = *(const float4*)&Bsb[kk*128 + 64 + tx*4];
            float av[8] = {a0.x,a0.y,a0.z,a0.w,a1.x,a1.y,a1.z,a1.w};
            float bv[8] = {b0.x,b0.y,b0.z,b0.w,b1.x,b1.y,b1.z,b1.w};
#pragma unroll
            for (int i = 0; i < 8; i++)
#pragma unroll
                for (int j = 0; j < 8; j++) acc[i][j] += av[i]*bv[j];
        }
        __syncthreads();
    }
#undef PC_LOAD

    int hg0 = hBase + tx*4;
    int hg1 = hBase + 64 + tx*4;
    float4 bc0 = (hg0 < 300) ? *(const float4*)&bc[hg0] : make_float4(0.f,0.f,0.f,0.f);
    float4 bc1 = (hg1 < 300) ? *(const float4*)&bc[hg1] : make_float4(0.f,0.f,0.f,0.f);
    float bca[8] = {bc0.x,bc0.y,bc0.z,bc0.w,bc1.x,bc1.y,bc1.z,bc1.w};
    float sums[8] = {};
#pragma unroll
    for (int i = 0; i < 8; i++) {
        int r = (i < 4) ? ty*4 + i : 64 + ty*4 + i - 4;
        if (r < len) {
            const float* h1p = Hc1 + (size_t)sE[r]*300;
            float4 a0 = (hg0 < 300) ? *(const float4*)&h1p[hg0] : make_float4(0.f,0.f,0.f,0.f);
            float4 a1 = (hg1 < 300) ? *(const float4*)&h1p[hg1] : make_float4(0.f,0.f,0.f,0.f);
            float ad[8] = {a0.x,a0.y,a0.z,a0.w,a1.x,a1.y,a1.z,a1.w};
#pragma unroll
            for (int j = 0; j < 8; j++)
                sums[j] += fmaxf(acc[i][j] + ad[j] + bca[j], 0.f);
        }
    }
#pragma unroll
    for (int j = 0; j < 8; j++) {
        int pos = (j < 4) ? tx*4 + j : 64 + tx*4 + (j - 4);
        redsm[ty*132 + pos] = sums[j];
    }
    __syncthreads();
    if (t < 128) {
        float s = 0.f;
#pragma unroll
        for (int r = 0; r < 16; r++) s += redsm[r*132 + t];
        int hg = hBase + t;
        if (hg < 300) {
            float* outp = mode ? cc : cr;
            outp[b*HH + hg] = s;
        }
    }
}

// ============================================================
// 7) classifier head
// ============================================================
__global__ void k_cls(const float* __restrict__ cr,
                      const float* __restrict__ cc,
                      const float* __restrict__ Wcls,
                      const float* __restrict__ bcls,
                      const float* __restrict__ Wout,
                      const float* __restrict__ bout,
                      float* __restrict__ out) {
    int b = blockIdx.x;
    int t = threadIdx.x;              // 320 threads
    __shared__ float x[2*HH];
    for (int i = t; i < 2*HH; i += 320)
        x[i] = (i < HH) ? cr[b*HH + i] : cc[b*HH + i - HH];
    __syncthreads();
    float z = 0.f;
    if (t < HH) {
        float a0 = 0.f, a1 = 0.f, a2 = 0.f, a3 = 0.f;
#pragma unroll 4
        for (int k = 0; k < 2*HH; k += 4) {
            a0 += x[k+0]*Wcls[(k+0)*HH + t];
            a1 += x[k+1]*Wcls[(k+1)*HH + t];
            a2 += x[k+2]*Wcls[(k+2)*HH + t];
            a3 += x[k+3]*Wcls[(k+3)*HH + t];
        }
        z = fmaxf((a0+a1)+(a2+a3) + bcls[t], 0.f);
    }
    float s0 = (t < HH) ? z*Wout[t*2 + 0] : 0.f;
    float s1 = (t < HH) ? z*Wout[t*2 + 1] : 0.f;
#pragma unroll
    for (int o = 16; o; o >>= 1) {
        s0 += __shfl_down_sync(0xffffffffu, s0, o);
        s1 += __shfl_down_sync(0xffffffffu, s1, o);
    }
    __shared__ float r0[10], r1[10];
    if ((t & 31) == 0) { r0[t >> 5] = s0; r1[t >> 5] = s1; }
    __syncthreads();
    if (t == 0) {
        float a = 0.f, c = 0.f;
#pragma unroll
        for (int i = 0; i < 10; i++) { a += r0[i]; c += r1[i]; }
        out[b*2 + 0] = a + bout[0];
        out[b*2 + 1] = c + bout[1];
    }
}

// ============================================================
// launch
// ============================================================
extern "C" void kernel_launch(void* const* d_in, const int* in_sizes, int n_in,
                              void* d_out, int out_size) {
    const int*   data    = (const int*)  d_in[0];
    const int*   row_idx = (const int*)  d_in[1];
    const int*   col_idx = (const int*)  d_in[2];
    const int*   row_len = (const int*)  d_in[3];
    const int*   col_len = (const int*)  d_in[4];
    const float* emb     = (const float*)d_in[5];
    const float* W1      = (const float*)d_in[6];
    const float* b1      = (const float*)d_in[7];
    const float* W2      = (const float*)d_in[8];
    const float* b2      = (const float*)d_in[9];
    const float* Wc      = (const float*)d_in[10];
    const float* bc      = (const float*)d_in[11];
    const float* Wcls    = (const float*)d_in[12];
    const float* bcls    = (const float*)d_in[13];
    const float* Wout    = (const float*)d_in[14];
    const float* bout    = (const float*)d_in[15];
    float* out = (float*)d_out;

    float *enc, *h1, *henc, *Hc, *invh, *Kb, *Pb, *cr, *cc;
    cudaGetSymbolAddress((void**)&enc,  g_enc);
    cudaGetSymbolAddress((void**)&h1,   g_h1);
    cudaGetSymbolAddress((void**)&henc, g_henc);
    cudaGetSymbolAddress((void**)&Hc,   g_Hc);
    cudaGetSymbolAddress((void**)&invh, g_invh);
    cudaGetSymbolAddress((void**)&Kb,   g_Kmat);
    cudaGetSymbolAddress((void**)&Pb,   g_Pmat);
    cudaGetSymbolAddress((void**)&cr,   g_cr);
    cudaGetSymbolAddress((void**)&cc,   g_cc);
    float* Hc1 = Hc;
    float* Hc2 = Hc + (long)NSAMP*HH;

    cudaFuncSetAttribute(k_wgemm<true>,  cudaFuncAttributeMaxDynamicSharedMemorySize, WG_SMEM);
    cudaFuncSetAttribute(k_wgemm<false>, cudaFuncAttributeMaxDynamicSharedMemorySize, WG_SMEM);

    // 1) embedding pool
    k_embed<<<NSAMP, 320>>>(data, emb, enc);
    // 2) FFN (tf32 tensor cores)
    dim3 gF(3, 79, 1);
    k_wgemm<true><<<gF, 256, WG_SMEM>>>(enc, W1, b1, h1,   NSAMP, HH, DD, 0, 0);
    k_wgemm<true><<<gF, 256, WG_SMEM>>>(h1,  W2, b2, henc, NSAMP, HH, HH, 0, 0);

    // fork: Hc GEMM (tf32) on side stream
    cudaEventRecord(g_hx.eHenc, 0);
    cudaStreamWaitEvent(g_hx.sB, g_hx.eHenc, 0);
    dim3 gHc(3, 79, 2);
    k_wgemm<false><<<gHc, 256, WG_SMEM, g_hx.sB>>>(henc, Wc, nullptr, Hc,
                                                   NSAMP, HH, HH, (long)HH*HH, (long)NSAMP*HH);
    cudaEventRecord(g_hx.eHc, g_hx.sB);

    // chain A on default stream (pure fp32, exp-critical)
    k_invnorm<<<(NSAMP + 7)/8, 256>>>(henc, invh);
    k_cost<<<BB, 256>>>(henc, invh, row_idx, col_idx, row_len, col_len, Kb);
    int sink_smem = (128*132 + 128 + 128 + 512) * (int)sizeof(float);
    cudaFuncSetAttribute(k_sinkhorn, cudaFuncAttributeMaxDynamicSharedMemorySize, sink_smem);
    k_sinkhorn<<<BB, 128, sink_smem>>>(Kb, row_len, col_len, Pb);

    // join
    cudaStreamWaitEvent(0, g_hx.eHc, 0);
    k_pcmp<<<dim3(3, 2, BB), 256>>>(Pb, Hc1, Hc2, bc, row_idx, col_idx,
                                    row_len, col_len, cr, cc);
    k_cls<<<BB, 320>>>(cr, cc, Wcls, bcls, Wout, bout, out);
}

// round 5
// speedup vs baseline: 1.0796x; 1.0175x over previous
#include <cuda_runtime.h>
#include <math.h>

// ---- problem dims ----
#define NSAMP 10000
#define LTOK  32
#define DD    300
#define HH    300
#define BB    256
#define NMX   128
#define ITERS 50

// ---- scratch ----
__device__ float g_enc [NSAMP*DD];
__device__ float g_h1  [NSAMP*HH];
__device__ float g_henc[NSAMP*HH];
__device__ float g_Hc  [2*NSAMP*HH];
__device__ float g_invh[NSAMP];
__device__ float g_Kmat[BB*NMX*NMX];
__device__ float g_Pmat[BB*NMX*NMX];
__device__ float g_cr  [BB*HH];
__device__ float g_cc  [BB*HH];

// ---- streams/events (static init, pre-checkpoint) ----
struct HxStreams {
    cudaStream_t sB;
    cudaEvent_t eHenc, eHc;
    HxStreams() {
        cudaStreamCreateWithFlags(&sB, cudaStreamNonBlocking);
        cudaEventCreateWithFlags(&eHenc, cudaEventDisableTiming);
        cudaEventCreateWithFlags(&eHc,   cudaEventDisableTiming);
    }
};
static HxStreams g_hx;

// ---- packed fp32x2 helpers (Blackwell FFMA2) ----
__device__ __forceinline__ unsigned long long f2pack(float lo, float hi) {
    unsigned long long r;
    asm("mov.b64 %0, {%1, %2};" : "=l"(r) : "f"(lo), "f"(hi));
    return r;
}
__device__ __forceinline__ void f2fma(unsigned long long& d,
                                      unsigned long long a, unsigned long long b) {
    asm("fma.rn.f32x2 %0, %1, %2, %0;" : "+l"(d) : "l"(a), "l"(b));
}
__device__ __forceinline__ float2 f2unpack(unsigned long long v) {
    float2 r;
    asm("mov.b64 {%0, %1}, %2;" : "=f"(r.x), "=f"(r.y) : "l"(v));
    return r;
}

// ============================================================
// 1) embedding + masked mean pool
// ============================================================
__global__ void k_embed(const int* __restrict__ data,
                        const float* __restrict__ emb,
                        float* __restrict__ enc) {
    int s = blockIdx.x;
    int t = threadIdx.x;            // 320 threads
    __shared__ int toks[LTOK];
    if (t < LTOK) toks[t] = data[s*LTOK + t];
    __syncthreads();
    int cnt = 0;
#pragma unroll
    for (int l = 0; l < LTOK; l++) cnt += (toks[l] != 0);
    float inv = 1.0f / (float)(cnt > 0 ? cnt : 1);
    if (t < DD) {
        float acc = 0.f;
#pragma unroll
        for (int l = 0; l < LTOK; l++) {
            int tok = toks[l];
            if (tok != 0) acc += emb[tok*DD + t];
        }
        enc[s*DD + t] = acc * inv;
    }
}

// ---- shared inner-product step: 8x8 tile via 32 FFMA2 ----
#define F2_STEP(Asb, Bsb, BSTR)                                             \
    {                                                                       \
        float4 a0 = *(const float4*)&(Asb)[kk*132 + ty*4];                  \
        float4 a1 = *(const float4*)&(Asb)[kk*132 + 64 + ty*4];             \
        float4 b0 = *(const float4*)&(Bsb)[kk*(BSTR) + tx*4];               \
        float4 b1 = *(const float4*)&(Bsb)[kk*(BSTR) + 64 + tx*4];          \
        unsigned long long bb0 = f2pack(b0.x, b0.y);                        \
        unsigned long long bb1 = f2pack(b0.z, b0.w);                        \
        unsigned long long bb2 = f2pack(b1.x, b1.y);                        \
        unsigned long long bb3 = f2pack(b1.z, b1.w);                        \
        float av[8] = {a0.x,a0.y,a0.z,a0.w,a1.x,a1.y,a1.z,a1.w};            \
        _Pragma("unroll")                                                   \
        for (int i = 0; i < 8; i++) {                                       \
            unsigned long long aa = f2pack(av[i], av[i]);                   \
            f2fma(acc2[i][0], aa, bb0);                                     \
            f2fma(acc2[i][1], aa, bb1);                                     \
            f2fma(acc2[i][2], aa, bb2);                                     \
            f2fma(acc2[i][3], aa, bb3);                                     \
        }                                                                   \
    }

// ============================================================
// 2) SGEMM 128x128x16, double-buffered, FFMA2 inner loop
// ============================================================
template<bool RELU>
__global__ void k_sgemm128(const float* __restrict__ A, const float* __restrict__ B,
                           const float* __restrict__ bias, float* __restrict__ C,
                           int M, int N, int K, long bStride, long cStride) {
    B += (long)blockIdx.z * bStride;
    C += (long)blockIdx.z * cStride;
    __shared__ float As[2][16*132];
    __shared__ float Bs[2][16*128];
    int t = threadIdx.x, tx = t & 15, ty = t >> 4;
    int mBase = blockIdx.y * 128, nBase = blockIdx.x * 128;
    unsigned long long acc2[8][4] = {};
    int nT = (K + 15) >> 4;

#define SG_LOAD(k0, buf)                                                    \
    {                                                                       \
        _Pragma("unroll")                                                   \
        for (int p = 0; p < 2; p++) {                                       \
            int id = p*256 + t;                                             \
            int m = id >> 2, kq = id & 3;                                   \
            int gm = mBase + m, gk = (k0) + kq*4;                           \
            float4 v = make_float4(0.f,0.f,0.f,0.f);                        \
            if (gm < M && gk < K) v = *(const float4*)&A[(size_t)gm*K + gk];\
            As[buf][(kq*4+0)*132 + m] = v.x;                                \
            As[buf][(kq*4+1)*132 + m] = v.y;                                \
            As[buf][(kq*4+2)*132 + m] = v.z;                                \
            As[buf][(kq*4+3)*132 + m] = v.w;                                \
        }                                                                   \
        _Pragma("unroll")                                                   \
        for (int p = 0; p < 2; p++) {                                       \
            int id = p*256 + t;                                             \
            int kr = id >> 5, nq = id & 31;                                 \
            int gk = (k0) + kr, gn = nBase + nq*4;                          \
            float4 v = make_float4(0.f,0.f,0.f,0.f);                        \
            if (gk < K && gn < N) v = *(const float4*)&B[(size_t)gk*N + gn];\
            *(float4*)&Bs[buf][kr*128 + nq*4] = v;                          \
        }                                                                   \
    }

    SG_LOAD(0, 0);
    __syncthreads();
    for (int ti = 0; ti < nT; ti++) {
        int cur = ti & 1;
        if (ti + 1 < nT) SG_LOAD((ti+1)*16, cur^1);
        const float* Asb = As[cur];
        const float* Bsb = Bs[cur];
#pragma unroll
        for (int kk = 0; kk < 16; kk++) F2_STEP(Asb, Bsb, 128)
        __syncthreads();
    }
#undef SG_LOAD
#pragma unroll
    for (int i = 0; i < 8; i++) {
        int gm = mBase + ((i < 4) ? ty*4 + i : 64 + ty*4 + i - 4);
        if (gm >= M) continue;
#pragma unroll
        for (int jh = 0; jh < 2; jh++) {
            int gn = nBase + jh*64 + tx*4;
            if (gn >= N) continue;
            float2 lo = f2unpack(acc2[i][jh*2+0]);
            float2 hi = f2unpack(acc2[i][jh*2+1]);
            float4 bb = bias ? *(const float4*)&bias[gn] : make_float4(0.f,0.f,0.f,0.f);
            float4 o;
            o.x = lo.x + bb.x; o.y = lo.y + bb.y;
            o.z = hi.x + bb.z; o.w = hi.y + bb.w;
            if (RELU) {
                o.x = fmaxf(o.x, 0.f); o.y = fmaxf(o.y, 0.f);
                o.z = fmaxf(o.z, 0.f); o.w = fmaxf(o.w, 0.f);
            }
            *(float4*)&C[(size_t)gm*N + gn] = o;
        }
    }
}

// ============================================================
// 3) per-sample inverse norm of henc
// ============================================================
__global__ void k_invnorm(const float* __restrict__ henc, float* __restrict__ invh) {
    int s = blockIdx.x * 8 + (threadIdx.x >> 5);
    int l = threadIdx.x & 31;
    if (s >= NSAMP) return;
    const float4* hp = (const float4*)(henc + (size_t)s*HH);
    float sq = 0.f;
    for (int d4 = l; d4 < 75; d4 += 32) {
        float4 v = hp[d4];
        sq += v.x*v.x + v.y*v.y + v.z*v.z + v.w*v.w;
    }
#pragma unroll
    for (int o = 16; o; o >>= 1) sq += __shfl_down_sync(0xffffffffu, sq, o);
    if (l == 0) invh[s] = 1.0f / (sqrtf(sq) + 1e-8f);
}

// ============================================================
// 4) fused gather + cosine cost + Gibbs kernel (FFMA2)
// ============================================================
__global__ void k_cost(const float* __restrict__ henc, const float* __restrict__ invh,
                       const int* __restrict__ ridx, const int* __restrict__ cidx,
                       const int* __restrict__ rlen, const int* __restrict__ clen,
                       float* __restrict__ Kout) {
    int b = blockIdx.x;
    __shared__ float As[2][16*132], Bs[2][16*132];
    __shared__ int sr[128], sc[128];
    __shared__ float sir[128], sic[128];
    int t = threadIdx.x, tx = t & 15, ty = t >> 4;
    if (t < 128) {
        int i = ridx[b*128 + t];
        sr[t] = i; sir[t] = invh[i];
    } else {
        int i = cidx[b*128 + (t-128)];
        sc[t-128] = i; sic[t-128] = invh[i];
    }
    __syncthreads();

#define CO_LOAD(k0, buf)                                                      \
    {                                                                         \
        _Pragma("unroll")                                                     \
        for (int p = 0; p < 2; p++) {                                         \
            int id = p*256 + t;                                               \
            int m = id >> 2, kq = id & 3;                                     \
            int gk = (k0) + kq*4;                                             \
            float4 va = make_float4(0.f,0.f,0.f,0.f), vb = va;                \
            if (gk < 300) {                                                   \
                va = *(const float4*)&henc[(size_t)sr[m]*300 + gk];           \
                vb = *(const float4*)&henc[(size_t)sc[m]*300 + gk];           \
            }                                                                 \
            As[buf][(kq*4+0)*132 + m] = va.x; As[buf][(kq*4+1)*132 + m] = va.y;\
            As[buf][(kq*4+2)*132 + m] = va.z; As[buf][(kq*4+3)*132 + m] = va.w;\
            Bs[buf][(kq*4+0)*132 + m] = vb.x; Bs[buf][(kq*4+1)*132 + m] = vb.y;\
            Bs[buf][(kq*4+2)*132 + m] = vb.z; Bs[buf][(kq*4+3)*132 + m] = vb.w;\
        }                                                                     \
    }

    unsigned long long acc2[8][4] = {};
    CO_LOAD(0, 0);
    __syncthreads();
    for (int ti = 0; ti < 19; ti++) {
        int cur = ti & 1;
        if (ti + 1 < 19) CO_LOAD((ti+1)*16, cur^1);
        const float* Asb = As[cur];
        const float* Bsb = Bs[cur];
#pragma unroll
        for (int kk = 0; kk < 16; kk++) F2_STEP(Asb, Bsb, 132)
        __syncthreads();
    }
#undef CO_LOAD
    int rl = rlen[b], cl = clen[b];
    float* out = Kout + (size_t)b*NMX*NMX;
#pragma unroll
    for (int i = 0; i < 8; i++) {
        int n = (i < 4) ? ty*4 + i : 64 + ty*4 + i - 4;
        float ir = sir[n];
        bool nv = (n < rl);
#pragma unroll
        for (int jh = 0; jh < 2; jh++) {
            float2 lo = f2unpack(acc2[i][jh*2+0]);
            float2 hi = f2unpack(acc2[i][jh*2+1]);
            float accv[4] = {lo.x, lo.y, hi.x, hi.y};
            float r[4];
#pragma unroll
            for (int j = 0; j < 4; j++) {
                int m = jh*64 + tx*4 + j;
                float dn = accv[j] * ir * sic[m];
                r[j] = (nv && m < cl) ? __expf((dn - 1.0f) * 10.0f) : 0.f;
            }
            float4 kv; kv.x = r[0]; kv.y = r[1]; kv.z = r[2]; kv.w = r[3];
            *(float4*)&out[n*128 + jh*64 + tx*4] = kv;
        }
    }
}

// ============================================================
// 5) Sinkhorn (multiplicative), K in SMEM pad-132
// ============================================================
__global__ void k_sinkhorn(const float* __restrict__ Kg,
                           const int* __restrict__ rlen,
                           const int* __restrict__ clen,
                           float* __restrict__ P) {
    extern __shared__ float sm[];
    float* Ks  = sm;               // 128*132
    float* u   = Ks + 128*132;     // 128
    float* v   = u + 128;          // 128
    float* red = v + 128;          // 4*128
    int b = blockIdx.x, t = threadIdx.x;
    const float* Kb = Kg + (size_t)b*NMX*NMX;
#pragma unroll 4
    for (int i = 0; i < 128; i++) Ks[i*132 + t] = Kb[i*128 + t];
    int rl = rlen[b], cl = clen[b];
    float ra = 1.0f / (float)rl, rb = 1.0f / (float)cl;
    u[t] = (t < cl) ? 1.0f : 0.0f;
    __syncthreads();

    int w = t >> 5, l = t & 31;
    const float4* Kr4 = (const float4*)(Ks + t*132);
    const float4* u4  = (const float4*)u;
    for (int it = 0; it < ITERS; it++) {
        float4 s4 = make_float4(0.f,0.f,0.f,0.f);
#pragma unroll
        for (int m = 0; m < 32; m++) {
            float4 k4 = Kr4[m], uu = u4[m];
            s4.x += k4.x*uu.x; s4.y += k4.y*uu.y;
            s4.z += k4.z*uu.z; s4.w += k4.w*uu.w;
        }
        float s = (s4.x + s4.y) + (s4.z + s4.w);
        v[t] = (t < rl) ? ra / s : 0.f;
        __syncthreads();
        float4 q4 = make_float4(0.f,0.f,0.f,0.f);
#pragma unroll
        for (int r = 0; r < 32; r++) {
            int n = w*32 + r;
            float vn = v[n];
            float4 k4 = *(const float4*)(Ks + n*132 + l*4);
            q4.x += k4.x*vn; q4.y += k4.y*vn;
            q4.z += k4.z*vn; q4.w += k4.w*vn;
        }
        *(float4*)(red + w*128 + l*4) = q4;
        __syncthreads();
        float q = red[t] + red[128 + t] + red[256 + t] + red[384 + t];
        u[t] = (t < cl) ? rb / q : 0.f;
        __syncthreads();
    }
    float ut = u[t];
    float* Pb = P + (size_t)b*NMX*NMX;
#pragma unroll 4
    for (int i = 0; i < 128; i++)
        Pb[i*128 + t] = v[i] * Ks[i*132 + t] * ut;
}

// ============================================================
// 6) P-GEMM + compare epilogue (FFMA2)
// ============================================================
__global__ void k_pcmp(const float* __restrict__ P,
                       const float* __restrict__ Hc1, const float* __restrict__ Hc2,
                       const float* __restrict__ bc,
                       const int* __restrict__ ridx, const int* __restrict__ cidx,
                       const int* __restrict__ rlen, const int* __restrict__ clen,
                       float* __restrict__ cr, float* __restrict__ cc) {
    int b = blockIdx.z, mode = blockIdx.y;
    int hBase = blockIdx.x * 128;
    const int* gidxA = mode ? (ridx + b*128) : (cidx + b*128);
    const int* gidxE = mode ? (cidx + b*128) : (ridx + b*128);
    int len = mode ? clen[b] : rlen[b];
    const float* Pb = P + (size_t)b*NMX*NMX;

    __shared__ float As[2][16*132];
    __shared__ float Bs[2][16*128];
    __shared__ int sA[128], sE[128];
    __shared__ float redsm[16*132];
    int t = threadIdx.x, tx = t & 15, ty = t >> 4;
    if (t < 128) sA[t] = gidxA[t];
    else sE[t-128] = gidxE[t-128];
    __syncthreads();

#define PC_LOAD(k0, buf)                                                      \
    {                                                                         \
        if (mode == 0) {                                                      \
            _Pragma("unroll")                                                 \
            for (int p = 0; p < 2; p++) {                                     \
                int id = p*256 + t;                                           \
                int n = id >> 2, kq = id & 3;                                 \
                float4 vv = *(const float4*)&Pb[n*128 + (k0) + kq*4];         \
                As[buf][(kq*4+0)*132 + n] = vv.x;                             \
                As[buf][(kq*4+1)*132 + n] = vv.y;                             \
                As[buf][(kq*4+2)*132 + n] = vv.z;                             \
                As[buf][(kq*4+3)*132 + n] = vv.w;                             \
            }                                                                 \
        } else {                                                              \
            _Pragma("unroll")                                                 \
            for (int p = 0; p < 2; p++) {                                     \
                int id = p*256 + t;                                           \
                int kr = id >> 5, mq = id & 31;                               \
                float4 vv = *(const float4*)&Pb[((k0) + kr)*128 + mq*4];      \
                *(float4*)&As[buf][kr*132 + mq*4] = vv;                       \
            }                                                                 \
        }                                                                     \
        _Pragma("unroll")                                                     \
        for (int p = 0; p < 2; p++) {                                         \
            int id = p*256 + t;                                               \
            int kr = id >> 5, hq = id & 31;                                   \
            int hg = hBase + hq*4;                                            \
            float4 vv = make_float4(0.f,0.f,0.f,0.f);                         \
            if (hg < 300) vv = *(const float4*)&Hc2[(size_t)sA[(k0)+kr]*300 + hg];\
            *(float4*)&Bs[buf][kr*128 + hq*4] = vv;                           \
        }                                                                     \
    }

    unsigned long long acc2[8][4] = {};
    PC_LOAD(0, 0);
    __syncthreads();
    for (int ti = 0; ti < 8; ti++) {
        int cur = ti & 1;
        if (ti + 1 < 8) PC_LOAD((ti+1)*16, cur^1);
        const float* Asb = As[cur];
        const float* Bsb = Bs[cur];
#pragma unroll
        for (int kk = 0; kk < 16; kk++) F2_STEP(Asb, Bsb, 128)
        __syncthreads();
    }
#undef PC_LOAD

    int hg0 = hBase + tx*4;
    int hg1 = hBase + 64 + tx*4;
    float4 bc0 = (hg0 < 300) ? *(const float4*)&bc[hg0] : make_float4(0.f,0.f,0.f,0.f);
    float4 bc1 = (hg1 < 300) ? *(const float4*)&bc[hg1] : make_float4(0.f,0.f,0.f,0.f);
    float bca[8] = {bc0.x,bc0.y,bc0.z,bc0.w,bc1.x,bc1.y,bc1.z,bc1.w};
    float sums[8] = {};
#pragma unroll
    for (int i = 0; i < 8; i++) {
        int r = (i < 4) ? ty*4 + i : 64 + ty*4 + i - 4;
        if (r < len) {
            float2 p0 = f2unpack(acc2[i][0]);
            float2 p1 = f2unpack(acc2[i][1]);
            float2 p2 = f2unpack(acc2[i][2]);
            float2 p3 = f2unpack(acc2[i][3]);
            float accv[8] = {p0.x,p0.y,p1.x,p1.y,p2.x,p2.y,p3.x,p3.y};
            const float* h1p = Hc1 + (size_t)sE[r]*300;
            float4 a0 = (hg0 < 300) ? *(const float4*)&h1p[hg0] : make_float4(0.f,0.f,0.f,0.f);
            float4 a1 = (hg1 < 300) ? *(const float4*)&h1p[hg1] : make_float4(0.f,0.f,0.f,0.f);
            float ad[8] = {a0.x,a0.y,a0.z,a0.w,a1.x,a1.y,a1.z,a1.w};
#pragma unroll
            for (int j = 0; j < 8; j++)
                sums[j] += fmaxf(accv[j] + ad[j] + bca[j], 0.f);
        }
    }
#pragma unroll
    for (int j = 0; j < 8; j++) {
        int pos = (j < 4) ? tx*4 + j : 64 + tx*4 + (j - 4);
        redsm[ty*132 + pos] = sums[j];
    }
    __syncthreads();
    if (t < 128) {
        float s = 0.f;
#pragma unroll
        for (int r = 0; r < 16; r++) s += redsm[r*132 + t];
        int hg = hBase + t;
        if (hg < 300) {
            float* outp = mode ? cc : cr;
            outp[b*HH + hg] = s;
        }
    }
}

// ============================================================
// 7) classifier head
// ============================================================
__global__ void k_cls(const float* __restrict__ cr,
                      const float* __restrict__ cc,
                      const float* __restrict__ Wcls,
                      const float* __restrict__ bcls,
                      const float* __restrict__ Wout,
                      const float* __restrict__ bout,
                      float* __restrict__ out) {
    int b = blockIdx.x;
    int t = threadIdx.x;              // 320 threads
    __shared__ float x[2*HH];
    for (int i = t; i < 2*HH; i += 320)
        x[i] = (i < HH) ? cr[b*HH + i] : cc[b*HH + i - HH];
    __syncthreads();
    float z = 0.f;
    if (t < HH) {
        float a0 = 0.f, a1 = 0.f, a2 = 0.f, a3 = 0.f;
#pragma unroll 4
        for (int k = 0; k < 2*HH; k += 4) {
            a0 += x[k+0]*Wcls[(k+0)*HH + t];
            a1 += x[k+1]*Wcls[(k+1)*HH + t];
            a2 += x[k+2]*Wcls[(k+2)*HH + t];
            a3 += x[k+3]*Wcls[(k+3)*HH + t];
        }
        z = fmaxf((a0+a1)+(a2+a3) + bcls[t], 0.f);
    }
    float s0 = (t < HH) ? z*Wout[t*2 + 0] : 0.f;
    float s1 = (t < HH) ? z*Wout[t*2 + 1] : 0.f;
#pragma unroll
    for (int o = 16; o; o >>= 1) {
        s0 += __shfl_down_sync(0xffffffffu, s0, o);
        s1 += __shfl_down_sync(0xffffffffu, s1, o);
    }
    __shared__ float r0[10], r1[10];
    if ((t & 31) == 0) { r0[t >> 5] = s0; r1[t >> 5] = s1; }
    __syncthreads();
    if (t == 0) {
        float a = 0.f, c = 0.f;
#pragma unroll
        for (int i = 0; i < 10; i++) { a += r0[i]; c += r1[i]; }
        out[b*2 + 0] = a + bout[0];
        out[b*2 + 1] = c + bout[1];
    }
}

// ============================================================
// launch
// ============================================================
extern "C" void kernel_launch(void* const* d_in, const int* in_sizes, int n_in,
                              void* d_out, int out_size) {
    const int*   data    = (const int*)  d_in[0];
    const int*   row_idx = (const int*)  d_in[1];
    const int*   col_idx = (const int*)  d_in[2];
    const int*   row_len = (const int*)  d_in[3];
    const int*   col_len = (const int*)  d_in[4];
    const float* emb     = (const float*)d_in[5];
    const float* W1      = (const float*)d_in[6];
    const float* b1      = (const float*)d_in[7];
    const float* W2      = (const float*)d_in[8];
    const float* b2      = (const float*)d_in[9];
    const float* Wc      = (const float*)d_in[10];
    const float* bc      = (const float*)d_in[11];
    const float* Wcls    = (const float*)d_in[12];
    const float* bcls    = (const float*)d_in[13];
    const float* Wout    = (const float*)d_in[14];
    const float* bout    = (const float*)d_in[15];
    float* out = (float*)d_out;

    float *enc, *h1, *henc, *Hc, *invh, *Kb, *Pb, *cr, *cc;
    cudaGetSymbolAddress((void**)&enc,  g_enc);
    cudaGetSymbolAddress((void**)&h1,   g_h1);
    cudaGetSymbolAddress((void**)&henc, g_henc);
    cudaGetSymbolAddress((void**)&Hc,   g_Hc);
    cudaGetSymbolAddress((void**)&invh, g_invh);
    cudaGetSymbolAddress((void**)&Kb,   g_Kmat);
    cudaGetSymbolAddress((void**)&Pb,   g_Pmat);
    cudaGetSymbolAddress((void**)&cr,   g_cr);
    cudaGetSymbolAddress((void**)&cc,   g_cc);
    float* Hc1 = Hc;
    float* Hc2 = Hc + (long)NSAMP*HH;

    // 1) embedding pool
    k_embed<<<NSAMP, 320>>>(data, emb, enc);
    // 2) FFN (FFMA2 scalar GEMM)
    dim3 gF(3, 79, 1);
    k_sgemm128<true><<<gF, 256>>>(enc, W1, b1, h1,   NSAMP, HH, DD, 0, 0);
    k_sgemm128<true><<<gF, 256>>>(h1,  W2, b2, henc, NSAMP, HH, HH, 0, 0);

    // fork: Hc GEMM on side stream
    cudaEventRecord(g_hx.eHenc, 0);
    cudaStreamWaitEvent(g_hx.sB, g_hx.eHenc, 0);
    dim3 gHc(3, 79, 2);
    k_sgemm128<false><<<gHc, 256, 0, g_hx.sB>>>(henc, Wc, nullptr, Hc,
                                                NSAMP, HH, HH, (long)HH*HH, (long)NSAMP*HH);
    cudaEventRecord(g_hx.eHc, g_hx.sB);

    // chain A on default stream
    k_invnorm<<<(NSAMP + 7)/8, 256>>>(henc, invh);
    k_cost<<<BB, 256>>>(henc, invh, row_idx, col_idx, row_len, col_len, Kb);
    int sink_smem = (128*132 + 128 + 128 + 512) * (int)sizeof(float);
    cudaFuncSetAttribute(k_sinkhorn, cudaFuncAttributeMaxDynamicSharedMemorySize, sink_smem);
    k_sinkhorn<<<BB, 128, sink_smem>>>(Kb, row_len, col_len, Pb);

    // join
    cudaStreamWaitEvent(0, g_hx.eHc, 0);
    k_pcmp<<<dim3(3, 2, BB), 256>>>(Pb, Hc1, Hc2, bc, row_idx, col_idx,
                                    row_len, col_len, cr, cc);
    k_cls<<<BB, 320>>>(cr, cc, Wcls, bcls, Wout, bout, out);
}

// round 6
// speedup vs baseline: 1.1677x; 1.0815x over previous
#include <cuda_runtime.h>
#include <math.h>
#include <mma.h>
using namespace nvcuda;

// ---- problem dims ----
#define NSAMP 10000
#define LTOK  32
#define DD    300
#define HH    300
#define BB    256
#define NMX   128
#define ITERS 50

// ---- scratch ----
__device__ float g_enc [NSAMP*DD];
__device__ float g_h1  [NSAMP*HH];
__device__ float g_henc[NSAMP*HH];
__device__ float g_Hc  [2*NSAMP*HH];
__device__ float g_invh[NSAMP];
__device__ float g_Kmat[BB*NMX*NMX];
__device__ float g_Pmat[BB*NMX*NMX];
__device__ float g_cr  [BB*HH];
__device__ float g_cc  [BB*HH];

// ---- streams/events (static init, pre-checkpoint) ----
struct HxStreams {
    cudaStream_t sB;
    cudaEvent_t eHenc, eHc;
    HxStreams() {
        cudaStreamCreateWithFlags(&sB, cudaStreamNonBlocking);
        cudaEventCreateWithFlags(&eHenc, cudaEventDisableTiming);
        cudaEventCreateWithFlags(&eHc,   cudaEventDisableTiming);
    }
};
static HxStreams g_hx;

// ---- cp.async helpers ----
__device__ __forceinline__ void cpa16(unsigned int dst, const void* src) {
    asm volatile("cp.async.ca.shared.global [%0], [%1], 16;" :: "r"(dst), "l"(src));
}
__device__ __forceinline__ void cpa_commit() {
    asm volatile("cp.async.commit_group;");
}
template<int NN> __device__ __forceinline__ void cpa_wait() {
    asm volatile("cp.async.wait_group %0;" :: "n"(NN));
}

#define F2TF(frag) { _Pragma("unroll") \
    for (int _e = 0; _e < (frag).num_elements; _e++) \
        (frag).x[_e] = wmma::__float_to_tf32((frag).x[_e]); }

// ============================================================
// 1) embedding + masked mean pool
// ============================================================
__global__ void k_embed(const int* __restrict__ data,
                        const float* __restrict__ emb,
                        float* __restrict__ enc) {
    int s = blockIdx.x;
    int t = threadIdx.x;            // 320 threads
    __shared__ int toks[LTOK];
    if (t < LTOK) toks[t] = data[s*LTOK + t];
    __syncthreads();
    int cnt = 0;
#pragma unroll
    for (int l = 0; l < LTOK; l++) cnt += (toks[l] != 0);
    float inv = 1.0f / (float)(cnt > 0 ? cnt : 1);
    if (t < DD) {
        float acc = 0.f;
#pragma unroll
        for (int l = 0; l < LTOK; l++) {
            int tok = toks[l];
            if (tok != 0) acc += emb[tok*DD + t];
        }
        enc[s*DD + t] = acc * inv;
    }
}

// ============================================================
// 2) WMMA v2 tf32 GEMM: 128x128, BK=16, cp.async double buffer,
//    8 warps (2x4), warp tile 64x32, 2 CTAs/SM target.
// ============================================================
#define SA   20
#define SB   132
#define ASTG (128*SA)     // 2560 floats
#define BSTG (16*SB)      // 2112 floats
#define WG2_SMEM (2*(ASTG+BSTG)*4)   // 37376 bytes

template<bool RELU>
__global__ void __launch_bounds__(256, 2)
k_wgemm2(const float* __restrict__ A, const float* __restrict__ B,
         const float* __restrict__ bias, float* __restrict__ C,
         int M, int N, int K, long bStride, long cStride) {
    B += (long)blockIdx.z * bStride;
    C += (long)blockIdx.z * cStride;
    extern __shared__ float sm[];
    unsigned int smb = (unsigned int)__cvta_generic_to_shared(sm);
    int t = threadIdx.x;
    int wid = t >> 5, wm = wid >> 2, wn = wid & 3;
    int mBase = blockIdx.y * 128, nBase = blockIdx.x * 128;
    int nT = (K + 15) >> 4;

    wmma::fragment<wmma::accumulator, 16, 16, 8, float> acc[4][2];
#pragma unroll
    for (int i = 0; i < 4; i++)
#pragma unroll
        for (int j = 0; j < 2; j++) wmma::fill_fragment(acc[i][j], 0.f);

#define W2_LOAD(k0, buf)                                                     \
    {                                                                        \
        _Pragma("unroll")                                                    \
        for (int p = 0; p < 2; p++) {                                        \
            int id = t + p*256;                                              \
            int m = id >> 2, c4 = id & 3;                                    \
            int gm = mBase + m, gk = (k0) + c4*4;                            \
            int off = (buf)*ASTG + m*SA + c4*4;                              \
            if (gm < M && gk < K) cpa16(smb + off*4, A + (size_t)gm*K + gk); \
            else *(float4*)(sm + off) = make_float4(0.f,0.f,0.f,0.f);        \
        }                                                                    \
        _Pragma("unroll")                                                    \
        for (int p = 0; p < 2; p++) {                                        \
            int id = t + p*256;                                              \
            int kr = id >> 5, n4 = id & 31;                                  \
            int gk = (k0) + kr, gn = nBase + n4*4;                           \
            int off = 2*ASTG + (buf)*BSTG + kr*SB + n4*4;                    \
            if (gk < K && gn < N) cpa16(smb + off*4, B + (size_t)gk*N + gn); \
            else *(float4*)(sm + off) = make_float4(0.f,0.f,0.f,0.f);        \
        }                                                                    \
        cpa_commit();                                                        \
    }

    W2_LOAD(0, 0);
    for (int ti = 0; ti < nT; ti++) {
        int cur = ti & 1;
        if (ti + 1 < nT) { W2_LOAD((ti+1)*16, cur^1); cpa_wait<1>(); }
        else             { cpa_wait<0>(); }
        __syncthreads();
        const float* ap = sm + cur*ASTG;
        const float* bp = sm + 2*ASTG + cur*BSTG;
#pragma unroll
        for (int ks = 0; ks < 2; ks++) {
            int k8 = ks*8;
            wmma::fragment<wmma::matrix_b, 16, 16, 8, wmma::precision::tf32, wmma::row_major> bf[2];
#pragma unroll
            for (int j = 0; j < 2; j++) {
                wmma::load_matrix_sync(bf[j], bp + k8*SB + wn*32 + j*16, SB);
                F2TF(bf[j]);
            }
#pragma unroll
            for (int i = 0; i < 4; i++) {
                wmma::fragment<wmma::matrix_a, 16, 16, 8, wmma::precision::tf32, wmma::row_major> af;
                wmma::load_matrix_sync(af, ap + (wm*64 + i*16)*SA + k8, SA);
                F2TF(af);
                wmma::mma_sync(acc[i][0], af, bf[0], acc[i][0]);
                wmma::mma_sync(acc[i][1], af, bf[1], acc[i][1]);
            }
        }
        __syncthreads();
    }
#undef W2_LOAD

    // epilogue in two phases, overlaying the stage smem (needs 64*132 <= stages)
#pragma unroll
    for (int ph = 0; ph < 2; ph++) {
        if (wm == ph) {
#pragma unroll
            for (int i = 0; i < 4; i++)
#pragma unroll
                for (int j = 0; j < 2; j++)
                    wmma::store_matrix_sync(sm + (i*16)*132 + wn*32 + j*16,
                                            acc[i][j], 132, wmma::mem_row_major);
        }
        __syncthreads();
#pragma unroll
        for (int q = 0; q < 8; q++) {
            int idx = t + q*256;
            int row = idx >> 5, c4 = idx & 31;
            int gm = mBase + ph*64 + row, gn = nBase + c4*4;
            if (gm < M && gn < N) {
                float4 v = *(float4*)&sm[row*132 + c4*4];
                float4 bb = bias ? *(const float4*)&bias[gn] : make_float4(0.f,0.f,0.f,0.f);
                v.x += bb.x; v.y += bb.y; v.z += bb.z; v.w += bb.w;
                if (RELU) {
                    v.x = fmaxf(v.x, 0.f); v.y = fmaxf(v.y, 0.f);
                    v.z = fmaxf(v.z, 0.f); v.w = fmaxf(v.w, 0.f);
                }
                *(float4*)&C[(size_t)gm*N + gn] = v;
            }
        }
        __syncthreads();
    }
}

// ============================================================
// 3) per-sample inverse norm of henc
// ============================================================
__global__ void k_invnorm(const float* __restrict__ henc, float* __restrict__ invh) {
    int s = blockIdx.x * 8 + (threadIdx.x >> 5);
    int l = threadIdx.x & 31;
    if (s >= NSAMP) return;
    const float4* hp = (const float4*)(henc + (size_t)s*HH);
    float sq = 0.f;
    for (int d4 = l; d4 < 75; d4 += 32) {
        float4 v = hp[d4];
        sq += v.x*v.x + v.y*v.y + v.z*v.z + v.w*v.w;
    }
#pragma unroll
    for (int o = 16; o; o >>= 1) sq += __shfl_down_sync(0xffffffffu, sq, o);
    if (l == 0) invh[s] = 1.0f / (sqrtf(sq) + 1e-8f);
}

// ============================================================
// 4) fused gather + cosine cost + Gibbs kernel (exact fp32)
// ============================================================
__global__ void k_cost(const float* __restrict__ henc, const float* __restrict__ invh,
                       const int* __restrict__ ridx, const int* __restrict__ cidx,
                       const int* __restrict__ rlen, const int* __restrict__ clen,
                       float* __restrict__ Kout) {
    int b = blockIdx.x;
    __shared__ float As[2][16*132], Bs[2][16*132];
    __shared__ int sr[128], sc[128];
    __shared__ float sir[128], sic[128];
    int t = threadIdx.x, tx = t & 15, ty = t >> 4;
    if (t < 128) {
        int i = ridx[b*128 + t];
        sr[t] = i; sir[t] = invh[i];
    } else {
        int i = cidx[b*128 + (t-128)];
        sc[t-128] = i; sic[t-128] = invh[i];
    }
    __syncthreads();

#define CO_LOAD(k0, buf)                                                      \
    {                                                                         \
        _Pragma("unroll")                                                     \
        for (int p = 0; p < 2; p++) {                                         \
            int id = p*256 + t;                                               \
            int m = id >> 2, kq = id & 3;                                     \
            int gk = (k0) + kq*4;                                             \
            float4 va = make_float4(0.f,0.f,0.f,0.f), vb = va;                \
            if (gk < 300) {                                                   \
                va = *(const float4*)&henc[(size_t)sr[m]*300 + gk];           \
                vb = *(const float4*)&henc[(size_t)sc[m]*300 + gk];           \
            }                                                                 \
            As[buf][(kq*4+0)*132 + m] = va.x; As[buf][(kq*4+1)*132 + m] = va.y;\
            As[buf][(kq*4+2)*132 + m] = va.z; As[buf][(kq*4+3)*132 + m] = va.w;\
            Bs[buf][(kq*4+0)*132 + m] = vb.x; Bs[buf][(kq*4+1)*132 + m] = vb.y;\
            Bs[buf][(kq*4+2)*132 + m] = vb.z; Bs[buf][(kq*4+3)*132 + m] = vb.w;\
        }                                                                     \
    }

    float acc[8][8] = {};
    CO_LOAD(0, 0);
    __syncthreads();
    for (int ti = 0; ti < 19; ti++) {
        int cur = ti & 1;
        if (ti + 1 < 19) CO_LOAD((ti+1)*16, cur^1);
        const float* Asb = As[cur];
        const float* Bsb = Bs[cur];
#pragma unroll
        for (int kk = 0; kk < 16; kk++) {
            float4 a0 = *(const float4*)&Asb[kk*132 + ty*4];
            float4 a1 = *(const float4*)&Asb[kk*132 + 64 + ty*4];
            float4 b0 = *(const float4*)&Bsb[kk*132 + tx*4];
            float4 b1 = *(const float4*)&Bsb[kk*132 + 64 + tx*4];
            float av[8] = {a0.x,a0.y,a0.z,a0.w,a1.x,a1.y,a1.z,a1.w};
            float bv[8] = {b0.x,b0.y,b0.z,b0.w,b1.x,b1.y,b1.z,b1.w};
#pragma unroll
            for (int i = 0; i < 8; i++)
#pragma unroll
                for (int j = 0; j < 8; j++) acc[i][j] += av[i]*bv[j];
        }
        __syncthreads();
    }
#undef CO_LOAD
    int rl = rlen[b], cl = clen[b];
    float* out = Kout + (size_t)b*NMX*NMX;
#pragma unroll
    for (int i = 0; i < 8; i++) {
        int n = (i < 4) ? ty*4 + i : 64 + ty*4 + i - 4;
        float ir = sir[n];
        bool nv = (n < rl);
#pragma unroll
        for (int jh = 0; jh < 2; jh++) {
            float r[4];
#pragma unroll
            for (int j = 0; j < 4; j++) {
                int m = jh*64 + tx*4 + j;
                float dn = acc[i][jh*4+j] * ir * sic[m];
                r[j] = (nv && m < cl) ? __expf((dn - 1.0f) * 10.0f) : 0.f;
            }
            float4 kv; kv.x = r[0]; kv.y = r[1]; kv.z = r[2]; kv.w = r[3];
            *(float4*)&out[n*128 + jh*64 + tx*4] = kv;
        }
    }
}

// ============================================================
// 5) Sinkhorn (multiplicative), K in SMEM pad-132
// ============================================================
__global__ void k_sinkhorn(const float* __restrict__ Kg,
                           const int* __restrict__ rlen,
                           const int* __restrict__ clen,
                           float* __restrict__ P) {
    extern __shared__ float sm[];
    float* Ks  = sm;               // 128*132
    float* u   = Ks + 128*132;     // 128
    float* v   = u + 128;          // 128
    float* red = v + 128;          // 4*128
    int b = blockIdx.x, t = threadIdx.x;
    const float* Kb = Kg + (size_t)b*NMX*NMX;
#pragma unroll 4
    for (int i = 0; i < 128; i++) Ks[i*132 + t] = Kb[i*128 + t];
    int rl = rlen[b], cl = clen[b];
    float ra = 1.0f / (float)rl, rb = 1.0f / (float)cl;
    u[t] = (t < cl) ? 1.0f : 0.0f;
    __syncthreads();

    int w = t >> 5, l = t & 31;
    const float4* Kr4 = (const float4*)(Ks + t*132);
    const float4* u4  = (const float4*)u;
    for (int it = 0; it < ITERS; it++) {
        float4 s4 = make_float4(0.f,0.f,0.f,0.f);
#pragma unroll
        for (int m = 0; m < 32; m++) {
            float4 k4 = Kr4[m], uu = u4[m];
            s4.x += k4.x*uu.x; s4.y += k4.y*uu.y;
            s4.z += k4.z*uu.z; s4.w += k4.w*uu.w;
        }
        float s = (s4.x + s4.y) + (s4.z + s4.w);
        v[t] = (t < rl) ? ra / s : 0.f;
        __syncthreads();
        float4 q4 = make_float4(0.f,0.f,0.f,0.f);
#pragma unroll
        for (int r = 0; r < 32; r++) {
            int n = w*32 + r;
            float vn = v[n];
            float4 k4 = *(const float4*)(Ks + n*132 + l*4);
            q4.x += k4.x*vn; q4.y += k4.y*vn;
            q4.z += k4.z*vn; q4.w += k4.w*vn;
        }
        *(float4*)(red + w*128 + l*4) = q4;
        __syncthreads();
        float q = red[t] + red[128 + t] + red[256 + t] + red[384 + t];
        u[t] = (t < cl) ? rb / q : 0.f;
        __syncthreads();
    }
    float ut = u[t];
    float* Pb = P + (size_t)b*NMX*NMX;
#pragma unroll 4
    for (int i = 0; i < 128; i++)
        Pb[i*128 + t] = v[i] * Ks[i*132 + t] * ut;
}

// ============================================================
// 6) P-GEMM (tf32 WMMA, A=P from gmem/L2) + fused compare epilogue
//    grid (3, 2, B): 128 rows x 128 h per CTA, K=128
// ============================================================
#define PC_SMEM (((2*BSTG > 64*132) ? 2*BSTG : 64*132)*4)

__global__ void __launch_bounds__(256, 2)
k_pcmp_w(const float* __restrict__ P,
         const float* __restrict__ Hc1, const float* __restrict__ Hc2,
         const float* __restrict__ bc,
         const int* __restrict__ ridx, const int* __restrict__ cidx,
         const int* __restrict__ rlen, const int* __restrict__ clen,
         float* __restrict__ cr, float* __restrict__ cc) {
    int b = blockIdx.z, mode = blockIdx.y;
    int hBase = blockIdx.x * 128;
    const int* gidxA = mode ? (ridx + b*128) : (cidx + b*128);
    const int* gidxE = mode ? (cidx + b*128) : (ridx + b*128);
    int len = mode ? clen[b] : rlen[b];
    const float* Pb = P + (size_t)b*NMX*NMX;

    extern __shared__ float sm[];
    unsigned int smb = (unsigned int)__cvta_generic_to_shared(sm);
    __shared__ int sA[128], sE[128];
    __shared__ float red2[256];
    int t = threadIdx.x;
    int wid = t >> 5, wm = wid >> 2, wn = wid & 3;
    if (t < 128) sA[t] = gidxA[t];
    else sE[t-128] = gidxE[t-128];
    __syncthreads();

    wmma::fragment<wmma::accumulator, 16, 16, 8, float> acc[4][2];
#pragma unroll
    for (int i = 0; i < 4; i++)
#pragma unroll
        for (int j = 0; j < 2; j++) wmma::fill_fragment(acc[i][j], 0.f);

#define PCW_LOADB(k0, buf)                                                   \
    {                                                                        \
        _Pragma("unroll")                                                    \
        for (int p = 0; p < 2; p++) {                                        \
            int id = t + p*256;                                              \
            int kr = id >> 5, n4 = id & 31;                                  \
            int gh = hBase + n4*4;                                           \
            int off = (buf)*BSTG + kr*SB + n4*4;                             \
            if (gh < 300) cpa16(smb + off*4, Hc2 + (size_t)sA[(k0)+kr]*300 + gh);\
            else *(float4*)(sm + off) = make_float4(0.f,0.f,0.f,0.f);        \
        }                                                                    \
        cpa_commit();                                                        \
    }

    PCW_LOADB(0, 0);
    for (int ti = 0; ti < 8; ti++) {
        int cur = ti & 1;
        if (ti + 1 < 8) { PCW_LOADB((ti+1)*16, cur^1); cpa_wait<1>(); }
        else            { cpa_wait<0>(); }
        __syncthreads();
        const float* bp = sm + cur*BSTG;
#pragma unroll
        for (int ks = 0; ks < 2; ks++) {
            int k8 = ti*16 + ks*8;
            wmma::fragment<wmma::matrix_b, 16, 16, 8, wmma::precision::tf32, wmma::row_major> bf[2];
#pragma unroll
            for (int j = 0; j < 2; j++) {
                wmma::load_matrix_sync(bf[j], bp + ks*8*SB + wn*32 + j*16, SB);
                F2TF(bf[j]);
            }
            if (mode == 0) {
#pragma unroll
                for (int i = 0; i < 4; i++) {
                    wmma::fragment<wmma::matrix_a, 16, 16, 8, wmma::precision::tf32, wmma::row_major> af;
                    wmma::load_matrix_sync(af, Pb + (size_t)(wm*64 + i*16)*128 + k8, 128);
                    F2TF(af);
                    wmma::mma_sync(acc[i][0], af, bf[0], acc[i][0]);
                    wmma::mma_sync(acc[i][1], af, bf[1], acc[i][1]);
                }
            } else {
#pragma unroll
                for (int i = 0; i < 4; i++) {
                    wmma::fragment<wmma::matrix_a, 16, 16, 8, wmma::precision::tf32, wmma::col_major> af;
                    wmma::load_matrix_sync(af, Pb + (size_t)k8*128 + wm*64 + i*16, 128);
                    F2TF(af);
                    wmma::mma_sync(acc[i][0], af, bf[0], acc[i][0]);
                    wmma::mma_sync(acc[i][1], af, bf[1], acc[i][1]);
                }
            }
        }
        __syncthreads();
    }
#undef PCW_LOADB

    // fused epilogue: relu(acc + Hc1[sE[r]] + bc) masked row-sum, two phases
    float colsum = 0.f;
    int hc = t & 127, rh = t >> 7;
    int hg = hBase + hc;
    float bcv = (hg < 300) ? bc[hg] : 0.f;
#pragma unroll
    for (int ph = 0; ph < 2; ph++) {
        if (wm == ph) {
#pragma unroll
            for (int i = 0; i < 4; i++)
#pragma unroll
                for (int j = 0; j < 2; j++)
                    wmma::store_matrix_sync(sm + (i*16)*132 + wn*32 + j*16,
                                            acc[i][j], 132, wmma::mem_row_major);
        }
        __syncthreads();
        if (hg < 300) {
            for (int r = rh*32; r < rh*32 + 32; r++) {
                int gr = ph*64 + r;
                if (gr < len)
                    colsum += fmaxf(sm[r*132 + hc] + Hc1[(size_t)sE[gr]*300 + hg] + bcv, 0.f);
            }
        }
        __syncthreads();
    }
    red2[t] = colsum;
    __syncthreads();
    if (t < 128 && hg < 300) {
        float* outp = mode ? cc : cr;
        outp[b*HH + hg] = red2[t] + red2[t + 128];
    }
}

// ============================================================
// 7) classifier head
// ============================================================
__global__ void k_cls(const float* __restrict__ cr,
                      const float* __restrict__ cc,
                      const float* __restrict__ Wcls,
                      const float* __restrict__ bcls,
                      const float* __restrict__ Wout,
                      const float* __restrict__ bout,
                      float* __restrict__ out) {
    int b = blockIdx.x;
    int t = threadIdx.x;              // 320 threads
    __shared__ float x[2*HH];
    for (int i = t; i < 2*HH; i += 320)
        x[i] = (i < HH) ? cr[b*HH + i] : cc[b*HH + i - HH];
    __syncthreads();
    float z = 0.f;
    if (t < HH) {
        float a0 = 0.f, a1 = 0.f, a2 = 0.f, a3 = 0.f;
#pragma unroll 4
        for (int k = 0; k < 2*HH; k += 4) {
            a0 += x[k+0]*Wcls[(k+0)*HH + t];
            a1 += x[k+1]*Wcls[(k+1)*HH + t];
            a2 += x[k+2]*Wcls[(k+2)*HH + t];
            a3 += x[k+3]*Wcls[(k+3)*HH + t];
        }
        z = fmaxf((a0+a1)+(a2+a3) + bcls[t], 0.f);
    }
    float s0 = (t < HH) ? z*Wout[t*2 + 0] : 0.f;
    float s1 = (t < HH) ? z*Wout[t*2 + 1] : 0.f;
#pragma unroll
    for (int o = 16; o; o >>= 1) {
        s0 += __shfl_down_sync(0xffffffffu, s0, o);
        s1 += __shfl_down_sync(0xffffffffu, s1, o);
    }
    __shared__ float r0[10], r1[10];
    if ((t & 31) == 0) { r0[t >> 5] = s0; r1[t >> 5] = s1; }
    __syncthreads();
    if (t == 0) {
        float a = 0.f, c = 0.f;
#pragma unroll
        for (int i = 0; i < 10; i++) { a += r0[i]; c += r1[i]; }
        out[b*2 + 0] = a + bout[0];
        out[b*2 + 1] = c + bout[1];
    }
}

// ============================================================
// launch
// ============================================================
extern "C" void kernel_launch(void* const* d_in, const int* in_sizes, int n_in,
                              void* d_out, int out_size) {
    const int*   data    = (const int*)  d_in[0];
    const int*   row_idx = (const int*)  d_in[1];
    const int*   col_idx = (const int*)  d_in[2];
    const int*   row_len = (const int*)  d_in[3];
    const int*   col_len = (const int*)  d_in[4];
    const float* emb     = (const float*)d_in[5];
    const float* W1      = (const float*)d_in[6];
    const float* b1      = (const float*)d_in[7];
    const float* W2      = (const float*)d_in[8];
    const float* b2      = (const float*)d_in[9];
    const float* Wc      = (const float*)d_in[10];
    const float* bc      = (const float*)d_in[11];
    const float* Wcls    = (const float*)d_in[12];
    const float* bcls    = (const float*)d_in[13];
    const float* Wout    = (const float*)d_in[14];
    const float* bout    = (const float*)d_in[15];
    float* out = (float*)d_out;

    float *enc, *h1, *henc, *Hc, *invh, *Kb, *Pb, *cr, *cc;
    cudaGetSymbolAddress((void**)&enc,  g_enc);
    cudaGetSymbolAddress((void**)&h1,   g_h1);
    cudaGetSymbolAddress((void**)&henc, g_henc);
    cudaGetSymbolAddress((void**)&Hc,   g_Hc);
    cudaGetSymbolAddress((void**)&invh, g_invh);
    cudaGetSymbolAddress((void**)&Kb,   g_Kmat);
    cudaGetSymbolAddress((void**)&Pb,   g_Pmat);
    cudaGetSymbolAddress((void**)&cr,   g_cr);
    cudaGetSymbolAddress((void**)&cc,   g_cc);
    float* Hc1 = Hc;
    float* Hc2 = Hc + (long)NSAMP*HH;

    cudaFuncSetAttribute(k_wgemm2<true>,  cudaFuncAttributeMaxDynamicSharedMemorySize, WG2_SMEM);
    cudaFuncSetAttribute(k_wgemm2<false>, cudaFuncAttributeMaxDynamicSharedMemorySize, WG2_SMEM);
    cudaFuncSetAttribute(k_pcmp_w, cudaFuncAttributeMaxDynamicSharedMemorySize, PC_SMEM);

    // 1) embedding pool
    k_embed<<<NSAMP, 320>>>(data, emb, enc);
    // 2) FFN (tf32 WMMA v2)
    dim3 gF(3, 79, 1);
    k_wgemm2<true><<<gF, 256, WG2_SMEM>>>(enc, W1, b1, h1,   NSAMP, HH, DD, 0, 0);
    k_wgemm2<true><<<gF, 256, WG2_SMEM>>>(h1,  W2, b2, henc, NSAMP, HH, HH, 0, 0);

    // fork: Hc GEMM on side stream
    cudaEventRecord(g_hx.eHenc, 0);
    cudaStreamWaitEvent(g_hx.sB, g_hx.eHenc, 0);
    dim3 gHc(3, 79, 2);
    k_wgemm2<false><<<gHc, 256, WG2_SMEM, g_hx.sB>>>(henc, Wc, nullptr, Hc,
                                                     NSAMP, HH, HH, (long)HH*HH, (long)NSAMP*HH);
    cudaEventRecord(g_hx.eHc, g_hx.sB);

    // chain A on default stream (exact fp32)
    k_invnorm<<<(NSAMP + 7)/8, 256>>>(henc, invh);
    k_cost<<<BB, 256>>>(henc, invh, row_idx, col_idx, row_len, col_len, Kb);
    int sink_smem = (128*132 + 128 + 128 + 512) * (int)sizeof(float);
    cudaFuncSetAttribute(k_sinkhorn, cudaFuncAttributeMaxDynamicSharedMemorySize, sink_smem);
    k_sinkhorn<<<BB, 128, sink_smem>>>(Kb, row_len, col_len, Pb);

    // join
    cudaStreamWaitEvent(0, g_hx.eHc, 0);
    k_pcmp_w<<<dim3(3, 2, BB), 256, PC_SMEM>>>(Pb, Hc1, Hc2, bc, row_idx, col_idx,
                                               row_len, col_len, cr, cc);
    k_cls<<<BB, 320>>>(cr, cc, Wcls, bcls, Wout, bout, out);
}

// round 8
// speedup vs baseline: 1.2035x; 1.0306x over previous
#include <cuda_runtime.h>
#include <math.h>
#include <mma.h>
using namespace nvcuda;

// ---- problem dims ----
#define NSAMP 10000
#define LTOK  32
#define DD    300
#define HH    300
#define BB    256
#define NMX   128
#define ITERS 50

// ---- scratch ----
__device__ float g_enc [NSAMP*DD];
__device__ float g_h1  [NSAMP*HH];
__device__ float g_henc[NSAMP*HH];
__device__ float g_Hc  [2*NSAMP*HH];
__device__ float g_invh[NSAMP];
__device__ float g_Pmat[BB*NMX*NMX];
__device__ float g_cr  [BB*HH];
__device__ float g_cc  [BB*HH];

// ---- streams/events (static init, pre-checkpoint) ----
struct HxStreams {
    cudaStream_t sB;
    cudaEvent_t eHenc, eHc;
    HxStreams() {
        cudaStreamCreateWithFlags(&sB, cudaStreamNonBlocking);
        cudaEventCreateWithFlags(&eHenc, cudaEventDisableTiming);
        cudaEventCreateWithFlags(&eHc,   cudaEventDisableTiming);
    }
};
static HxStreams g_hx;

// ---- cp.async helpers ----
__device__ __forceinline__ void cpa16(unsigned int dst, const void* src) {
    asm volatile("cp.async.ca.shared.global [%0], [%1], 16;" :: "r"(dst), "l"(src));
}
__device__ __forceinline__ void cpa_commit() {
    asm volatile("cp.async.commit_group;");
}
template<int NN> __device__ __forceinline__ void cpa_wait() {
    asm volatile("cp.async.wait_group %0;" :: "n"(NN));
}

// round-to-nearest fp32 -> tf32 on fragments (REQUIRED: truncation biases the chain)
#define F2TF(frag) { _Pragma("unroll") \
    for (int _e = 0; _e < (frag).num_elements; _e++) \
        (frag).x[_e] = wmma::__float_to_tf32((frag).x[_e]); }

// ============================================================
// 1) embedding + masked mean pool
// ============================================================
__global__ void k_embed(const int* __restrict__ data,
                        const float* __restrict__ emb,
                        float* __restrict__ enc) {
    int s = blockIdx.x;
    int t = threadIdx.x;            // 320 threads
    __shared__ int toks[LTOK];
    if (t < LTOK) toks[t] = data[s*LTOK + t];
    __syncthreads();
    int cnt = 0;
#pragma unroll
    for (int l = 0; l < LTOK; l++) cnt += (toks[l] != 0);
    float inv = 1.0f / (float)(cnt > 0 ? cnt : 1);
    if (t < DD) {
        float acc = 0.f;
#pragma unroll
        for (int l = 0; l < LTOK; l++) {
            int tok = toks[l];
            if (tok != 0) acc += emb[tok*DD + t];
        }
        enc[s*DD + t] = acc * inv;
    }
}

// ============================================================
// 2) WMMA tf32 GEMM (RN cvt): 128x128, BK=16, cp.async dbuf, 8 warps
// ============================================================
#define SA   20
#define SB   132
#define ASTG (128*SA)
#define BSTG (16*SB)
#define WG2_SMEM (2*(ASTG+BSTG)*4)

template<bool RELU>
__global__ void __launch_bounds__(256, 2)
k_wgemm2(const float* __restrict__ A, const float* __restrict__ B,
         const float* __restrict__ bias, float* __restrict__ C,
         int M, int N, int K, long bStride, long cStride) {
    B += (long)blockIdx.z * bStride;
    C += (long)blockIdx.z * cStride;
    extern __shared__ float sm[];
    unsigned int smb = (unsigned int)__cvta_generic_to_shared(sm);
    int t = threadIdx.x;
    int wid = t >> 5, wm = wid >> 2, wn = wid & 3;
    int mBase = blockIdx.y * 128, nBase = blockIdx.x * 128;
    int nT = (K + 15) >> 4;

    wmma::fragment<wmma::accumulator, 16, 16, 8, float> acc[4][2];
#pragma unroll
    for (int i = 0; i < 4; i++)
#pragma unroll
        for (int j = 0; j < 2; j++) wmma::fill_fragment(acc[i][j], 0.f);

#define W2_LOAD(k0, buf)                                                     \
    {                                                                        \
        _Pragma("unroll")                                                    \
        for (int p = 0; p < 2; p++) {                                        \
            int id = t + p*256;                                              \
            int m = id >> 2, c4 = id & 3;                                    \
            int gm = mBase + m, gk = (k0) + c4*4;                            \
            int off = (buf)*ASTG + m*SA + c4*4;                              \
            if (gm < M && gk < K) cpa16(smb + off*4, A + (size_t)gm*K + gk); \
            else *(float4*)(sm + off) = make_float4(0.f,0.f,0.f,0.f);        \
        }                                                                    \
        _Pragma("unroll")                                                    \
        for (int p = 0; p < 2; p++) {                                        \
            int id = t + p*256;                                              \
            int kr = id >> 5, n4 = id & 31;                                  \
            int gk = (k0) + kr, gn = nBase + n4*4;                           \
            int off = 2*ASTG + (buf)*BSTG + kr*SB + n4*4;                    \
            if (gk < K && gn < N) cpa16(smb + off*4, B + (size_t)gk*N + gn); \
            else *(float4*)(sm + off) = make_float4(0.f,0.f,0.f,0.f);        \
        }                                                                    \
        cpa_commit();                                                        \
    }

    W2_LOAD(0, 0);
    for (int ti = 0; ti < nT; ti++) {
        int cur = ti & 1;
        if (ti + 1 < nT) { W2_LOAD((ti+1)*16, cur^1); cpa_wait<1>(); }
        else             { cpa_wait<0>(); }
        __syncthreads();
        const float* ap = sm + cur*ASTG;
        const float* bp = sm + 2*ASTG + cur*BSTG;
#pragma unroll
        for (int ks = 0; ks < 2; ks++) {
            int k8 = ks*8;
            wmma::fragment<wmma::matrix_b, 16, 16, 8, wmma::precision::tf32, wmma::row_major> bf[2];
#pragma unroll
            for (int j = 0; j < 2; j++) {
                wmma::load_matrix_sync(bf[j], bp + k8*SB + wn*32 + j*16, SB);
                F2TF(bf[j]);
            }
#pragma unroll
            for (int i = 0; i < 4; i++) {
                wmma::fragment<wmma::matrix_a, 16, 16, 8, wmma::precision::tf32, wmma::row_major> af;
                wmma::load_matrix_sync(af, ap + (wm*64 + i*16)*SA + k8, SA);
                F2TF(af);
                wmma::mma_sync(acc[i][0], af, bf[0], acc[i][0]);
                wmma::mma_sync(acc[i][1], af, bf[1], acc[i][1]);
            }
        }
        __syncthreads();
    }
#undef W2_LOAD

#pragma unroll
    for (int ph = 0; ph < 2; ph++) {
        if (wm == ph) {
#pragma unroll
            for (int i = 0; i < 4; i++)
#pragma unroll
                for (int j = 0; j < 2; j++)
                    wmma::store_matrix_sync(sm + (i*16)*132 + wn*32 + j*16,
                                            acc[i][j], 132, wmma::mem_row_major);
        }
        __syncthreads();
#pragma unroll
        for (int q = 0; q < 8; q++) {
            int idx = t + q*256;
            int row = idx >> 5, c4 = idx & 31;
            int gm = mBase + ph*64 + row, gn = nBase + c4*4;
            if (gm < M && gn < N) {
                float4 v = *(float4*)&sm[row*132 + c4*4];
                float4 bb = bias ? *(const float4*)&bias[gn] : make_float4(0.f,0.f,0.f,0.f);
                v.x += bb.x; v.y += bb.y; v.z += bb.z; v.w += bb.w;
                if (RELU) {
                    v.x = fmaxf(v.x, 0.f); v.y = fmaxf(v.y, 0.f);
                    v.z = fmaxf(v.z, 0.f); v.w = fmaxf(v.w, 0.f);
                }
                *(float4*)&C[(size_t)gm*N + gn] = v;
            }
        }
        __syncthreads();
    }
}

// ============================================================
// 3) per-sample inverse norm of henc
// ============================================================
__global__ void k_invnorm(const float* __restrict__ henc, float* __restrict__ invh) {
    int s = blockIdx.x * 8 + (threadIdx.x >> 5);
    int l = threadIdx.x & 31;
    if (s >= NSAMP) return;
    const float4* hp = (const float4*)(henc + (size_t)s*HH);
    float sq = 0.f;
    for (int d4 = l; d4 < 75; d4 += 32) {
        float4 v = hp[d4];
        sq += v.x*v.x + v.y*v.y + v.z*v.z + v.w*v.w;
    }
#pragma unroll
    for (int o = 16; o; o >>= 1) sq += __shfl_down_sync(0xffffffffu, sq, o);
    if (l == 0) invh[s] = 1.0f / (sqrtf(sq) + 1e-8f);
}

// ============================================================
// 4) FUSED cost + Sinkhorn (exact fp32): K in SMEM, 50 iters, emit P
// ============================================================
#define CS_KS    (128*132)
#define CS_STAGE (2*16*132)
#define CS_SMEM  ((CS_KS + 2*CS_STAGE)*4)   // 101376 bytes

__global__ void __launch_bounds__(256, 2)
k_costsink(const float* __restrict__ henc, const float* __restrict__ invh,
           const int* __restrict__ ridx, const int* __restrict__ cidx,
           const int* __restrict__ rlen, const int* __restrict__ clen,
           float* __restrict__ P) {
    int b = blockIdx.x;
    extern __shared__ float sm[];
    float* Ks = sm;                    // 128*132
    float* As = sm + CS_KS;            // [2][16*132]
    float* Bs = As + CS_STAGE;         // [2][16*132]
    __shared__ int sr[128], sc[128];
    __shared__ float sir[128], sic[128];
    int t = threadIdx.x, tx = t & 15, ty = t >> 4;
    if (t < 128) {
        int i = ridx[b*128 + t];
        sr[t] = i; sir[t] = invh[i];
    } else {
        int i = cidx[b*128 + (t-128)];
        sc[t-128] = i; sic[t-128] = invh[i];
    }
    __syncthreads();

#define CO_LOAD(k0, buf)                                                      \
    {                                                                         \
        _Pragma("unroll")                                                     \
        for (int p = 0; p < 2; p++) {                                         \
            int id = p*256 + t;                                               \
            int m = id >> 2, kq = id & 3;                                     \
            int gk = (k0) + kq*4;                                             \
            float4 va = make_float4(0.f,0.f,0.f,0.f), vb = va;                \
            if (gk < 300) {                                                   \
                va = *(const float4*)&henc[(size_t)sr[m]*300 + gk];           \
                vb = *(const float4*)&henc[(size_t)sc[m]*300 + gk];           \
            }                                                                 \
            As[(buf)*2112 + (kq*4+0)*132 + m] = va.x;                         \
            As[(buf)*2112 + (kq*4+1)*132 + m] = va.y;                         \
            As[(buf)*2112 + (kq*4+2)*132 + m] = va.z;                         \
            As[(buf)*2112 + (kq*4+3)*132 + m] = va.w;                         \
            Bs[(buf)*2112 + (kq*4+0)*132 + m] = vb.x;                         \
            Bs[(buf)*2112 + (kq*4+1)*132 + m] = vb.y;                         \
            Bs[(buf)*2112 + (kq*4+2)*132 + m] = vb.z;                         \
            Bs[(buf)*2112 + (kq*4+3)*132 + m] = vb.w;                         \
        }                                                                     \
    }

    float acc[8][8] = {};
    CO_LOAD(0, 0);
    __syncthreads();
    for (int ti = 0; ti < 19; ti++) {
        int cur = ti & 1;
        if (ti + 1 < 19) CO_LOAD((ti+1)*16, cur^1);
        const float* Asb = As + cur*2112;
        const float* Bsb = Bs + cur*2112;
#pragma unroll
        for (int kk = 0; kk < 16; kk++) {
            float4 a0 = *(const float4*)&Asb[kk*132 + ty*4];
            float4 a1 = *(const float4*)&Asb[kk*132 + 64 + ty*4];
            float4 b0 = *(const float4*)&Bsb[kk*132 + tx*4];
            float4 b1 = *(const float4*)&Bsb[kk*132 + 64 + tx*4];
            float av[8] = {a0.x,a0.y,a0.z,a0.w,a1.x,a1.y,a1.z,a1.w};
            float bv[8] = {b0.x,b0.y,b0.z,b0.w,b1.x,b1.y,b1.z,b1.w};
#pragma unroll
            for (int i = 0; i < 8; i++)
#pragma unroll
                for (int j = 0; j < 8; j++) acc[i][j] += av[i]*bv[j];
        }
        __syncthreads();
    }
#undef CO_LOAD
    int rl = rlen[b], cl = clen[b];
#pragma unroll
    for (int i = 0; i < 8; i++) {
        int n = (i < 4) ? ty*4 + i : 64 + ty*4 + i - 4;
        float ir = sir[n];
        bool nv = (n < rl);
#pragma unroll
        for (int jh = 0; jh < 2; jh++) {
            float r[4];
#pragma unroll
            for (int j = 0; j < 4; j++) {
                int m = jh*64 + tx*4 + j;
                float dn = acc[i][jh*4+j] * ir * sic[m];
                r[j] = (nv && m < cl) ? __expf((dn - 1.0f) * 10.0f) : 0.f;
            }
            float4 kv; kv.x = r[0]; kv.y = r[1]; kv.z = r[2]; kv.w = r[3];
            *(float4*)&Ks[n*132 + jh*64 + tx*4] = kv;
        }
    }

    // ---- phase 2: Sinkhorn on smem K ----
    float* u   = As;          // 128
    float* v   = As + 128;    // 128
    float* red = As + 256;    // 1024
    float ra = 1.0f / (float)rl, rb = 1.0f / (float)cl;
    if (t < 128) u[t] = (t < cl) ? 1.0f : 0.0f;
    __syncthreads();

    int r128 = t & 127, half = t >> 7;
    int w8 = t >> 5, l32 = t & 31;
    const float4* Kr4 = (const float4*)(Ks + r128*132 + half*64);
    const float4* u4h = (const float4*)(u + half*64);
    for (int it = 0; it < ITERS; it++) {
        float4 s4 = make_float4(0.f,0.f,0.f,0.f);
#pragma unroll
        for (int m = 0; m < 16; m++) {
            float4 k4 = Kr4[m], uu = u4h[m];
            s4.x += k4.x*uu.x; s4.y += k4.y*uu.y;
            s4.z += k4.z*uu.z; s4.w += k4.w*uu.w;
        }
        red[half*128 + r128] = (s4.x + s4.y) + (s4.z + s4.w);
        __syncthreads();
        if (t < 128) {
            float s = red[t] + red[128 + t];
            v[t] = (t < rl) ? ra / s : 0.f;
        }
        __syncthreads();
        float4 q4 = make_float4(0.f,0.f,0.f,0.f);
#pragma unroll
        for (int rr = 0; rr < 16; rr++) {
            int n = w8*16 + rr;
            float vn = v[n];
            float4 k4 = *(const float4*)(Ks + n*132 + l32*4);
            q4.x += k4.x*vn; q4.y += k4.y*vn;
            q4.z += k4.z*vn; q4.w += k4.w*vn;
        }
        *(float4*)(red + w8*128 + l32*4) = q4;
        __syncthreads();
        if (t < 128) {
            float q = 0.f;
#pragma unroll
            for (int w = 0; w < 8; w++) q += red[w*128 + t];
            u[t] = (t < cl) ? rb / q : 0.f;
        }
        __syncthreads();
    }
    float ut = u[r128];
    float* Pb = P + (size_t)b*NMX*NMX;
    for (int i = half; i < 128; i += 2)
        Pb[i*128 + r128] = v[i] * Ks[i*132 + r128] * ut;
}

// ============================================================
// 5) P-GEMM (tf32 WMMA, RN cvt) + fused compare epilogue
// ============================================================
#define PC_SMEM (((2*BSTG > 64*132) ? 2*BSTG : 64*132)*4)

__global__ void __launch_bounds__(256, 2)
k_pcmp_w(const float* __restrict__ P,
         const float* __restrict__ Hc1, const float* __restrict__ Hc2,
         const float* __restrict__ bc,
         const int* __restrict__ ridx, const int* __restrict__ cidx,
         const int* __restrict__ rlen, const int* __restrict__ clen,
         float* __restrict__ cr, float* __restrict__ cc) {
    int b = blockIdx.z, mode = blockIdx.y;
    int hBase = blockIdx.x * 128;
    const int* gidxA = mode ? (ridx + b*128) : (cidx + b*128);
    const int* gidxE = mode ? (cidx + b*128) : (ridx + b*128);
    int len = mode ? clen[b] : rlen[b];
    const float* Pb = P + (size_t)b*NMX*NMX;

    extern __shared__ float sm[];
    unsigned int smb = (unsigned int)__cvta_generic_to_shared(sm);
    __shared__ int sA[128], sE[128];
    __shared__ float red2[256];
    int t = threadIdx.x;
    int wid = t >> 5, wm = wid >> 2, wn = wid & 3;
    if (t < 128) sA[t] = gidxA[t];
    else sE[t-128] = gidxE[t-128];
    __syncthreads();

    wmma::fragment<wmma::accumulator, 16, 16, 8, float> acc[4][2];
#pragma unroll
    for (int i = 0; i < 4; i++)
#pragma unroll
        for (int j = 0; j < 2; j++) wmma::fill_fragment(acc[i][j], 0.f);

#define PCW_LOADB(k0, buf)                                                   \
    {                                                                        \
        _Pragma("unroll")                                                    \
        for (int p = 0; p < 2; p++) {                                        \
            int id = t + p*256;                                              \
            int kr = id >> 5, n4 = id & 31;                                  \
            int gh = hBase + n4*4;                                           \
            int off = (buf)*BSTG + kr*SB + n4*4;                             \
            if (gh < 300) cpa16(smb + off*4, Hc2 + (size_t)sA[(k0)+kr]*300 + gh);\
            else *(float4*)(sm + off) = make_float4(0.f,0.f,0.f,0.f);        \
        }                                                                    \
        cpa_commit();                                                        \
    }

    PCW_LOADB(0, 0);
    for (int ti = 0; ti < 8; ti++) {
        int cur = ti & 1;
        if (ti + 1 < 8) { PCW_LOADB((ti+1)*16, cur^1); cpa_wait<1>(); }
        else            { cpa_wait<0>(); }
        __syncthreads();
        const float* bp = sm + cur*BSTG;
#pragma unroll
        for (int ks = 0; ks < 2; ks++) {
            int k8 = ti*16 + ks*8;
            wmma::fragment<wmma::matrix_b, 16, 16, 8, wmma::precision::tf32, wmma::row_major> bf[2];
#pragma unroll
            for (int j = 0; j < 2; j++) {
                wmma::load_matrix_sync(bf[j], bp + ks*8*SB + wn*32 + j*16, SB);
                F2TF(bf[j]);
            }
            if (mode == 0) {
#pragma unroll
                for (int i = 0; i < 4; i++) {
                    wmma::fragment<wmma::matrix_a, 16, 16, 8, wmma::precision::tf32, wmma::row_major> af;
                    wmma::load_matrix_sync(af, Pb + (size_t)(wm*64 + i*16)*128 + k8, 128);
                    F2TF(af);
                    wmma::mma_sync(acc[i][0], af, bf[0], acc[i][0]);
                    wmma::mma_sync(acc[i][1], af, bf[1], acc[i][1]);
                }
            } else {
#pragma unroll
                for (int i = 0; i < 4; i++) {
                    wmma::fragment<wmma::matrix_a, 16, 16, 8, wmma::precision::tf32, wmma::col_major> af;
                    wmma::load_matrix_sync(af, Pb + (size_t)k8*128 + wm*64 + i*16, 128);
                    F2TF(af);
                    wmma::mma_sync(acc[i][0], af, bf[0], acc[i][0]);
                    wmma::mma_sync(acc[i][1], af, bf[1], acc[i][1]);
                }
            }
        }
        __syncthreads();
    }
#undef PCW_LOADB

    float colsum = 0.f;
    int hc = t & 127, rh = t >> 7;
    int hg = hBase + hc;
    float bcv = (hg < 300) ? bc[hg] : 0.f;
#pragma unroll
    for (int ph = 0; ph < 2; ph++) {
        if (wm == ph) {
#pragma unroll
            for (int i = 0; i < 4; i++)
#pragma unroll
                for (int j = 0; j < 2; j++)
                    wmma::store_matrix_sync(sm + (i*16)*132 + wn*32 + j*16,
                                            acc[i][j], 132, wmma::mem_row_major);
        }
        __syncthreads();
        if (hg < 300) {
            for (int r = rh*32; r < rh*32 + 32; r++) {
                int gr = ph*64 + r;
                if (gr < len)
                    colsum += fmaxf(sm[r*132 + hc] + Hc1[(size_t)sE[gr]*300 + hg] + bcv, 0.f);
            }
        }
        __syncthreads();
    }
    red2[t] = colsum;
    __syncthreads();
    if (t < 128 && hg < 300) {
        float* outp = mode ? cc : cr;
        outp[b*HH + hg] = red2[t] + red2[t + 128];
    }
}

// ============================================================
// 6) classifier head
// ============================================================
__global__ void k_cls(const float* __restrict__ cr,
                      const float* __restrict__ cc,
                      const float* __restrict__ Wcls,
                      const float* __restrict__ bcls,
                      const float* __restrict__ Wout,
                      const float* __restrict__ bout,
                      float* __restrict__ out) {
    int b = blockIdx.x;
    int t = threadIdx.x;              // 320 threads
    __shared__ float x[2*HH];
    for (int i = t; i < 2*HH; i += 320)
        x[i] = (i < HH) ? cr[b*HH + i] : cc[b*HH + i - HH];
    __syncthreads();
    float z = 0.f;
    if (t < HH) {
        float a0 = 0.f, a1 = 0.f, a2 = 0.f, a3 = 0.f;
#pragma unroll 4
        for (int k = 0; k < 2*HH; k += 4) {
            a0 += x[k+0]*Wcls[(k+0)*HH + t];
            a1 += x[k+1]*Wcls[(k+1)*HH + t];
            a2 += x[k+2]*Wcls[(k+2)*HH + t];
            a3 += x[k+3]*Wcls[(k+3)*HH + t];
        }
        z = fmaxf((a0+a1)+(a2+a3) + bcls[t], 0.f);
    }
    float s0 = (t < HH) ? z*Wout[t*2 + 0] : 0.f;
    float s1 = (t < HH) ? z*Wout[t*2 + 1] : 0.f;
#pragma unroll
    for (int o = 16; o; o >>= 1) {
        s0 += __shfl_down_sync(0xffffffffu, s0, o);
        s1 += __shfl_down_sync(0xffffffffu, s1, o);
    }
    __shared__ float r0[10], r1[10];
    if ((t & 31) == 0) { r0[t >> 5] = s0; r1[t >> 5] = s1; }
    __syncthreads();
    if (t == 0) {
        float a = 0.f, c = 0.f;
#pragma unroll
        for (int i = 0; i < 10; i++) { a += r0[i]; c += r1[i]; }
        out[b*2 + 0] = a + bout[0];
        out[b*2 + 1] = c + bout[1];
    }
}

// ============================================================
// launch
// ============================================================
extern "C" void kernel_launch(void* const* d_in, const int* in_sizes, int n_in,
                              void* d_out, int out_size) {
    const int*   data    = (const int*)  d_in[0];
    const int*   row_idx = (const int*)  d_in[1];
    const int*   col_idx = (const int*)  d_in[2];
    const int*   row_len = (const int*)  d_in[3];
    const int*   col_len = (const int*)  d_in[4];
    const float* emb     = (const float*)d_in[5];
    const float* W1      = (const float*)d_in[6];
    const float* b1      = (const float*)d_in[7];
    const float* W2      = (const float*)d_in[8];
    const float* b2      = (const float*)d_in[9];
    const float* Wc      = (const float*)d_in[10];
    const float* bc      = (const float*)d_in[11];
    const float* Wcls    = (const float*)d_in[12];
    const float* bcls    = (const float*)d_in[13];
    const float* Wout    = (const float*)d_in[14];
    const float* bout    = (const float*)d_in[15];
    float* out = (float*)d_out;

    float *enc, *h1, *henc, *Hc, *invh, *Pb, *cr, *cc;
    cudaGetSymbolAddress((void**)&enc,  g_enc);
    cudaGetSymbolAddress((void**)&h1,   g_h1);
    cudaGetSymbolAddress((void**)&henc, g_henc);
    cudaGetSymbolAddress((void**)&Hc,   g_Hc);
    cudaGetSymbolAddress((void**)&invh, g_invh);
    cudaGetSymbolAddress((void**)&Pb,   g_Pmat);
    cudaGetSymbolAddress((void**)&cr,   g_cr);
    cudaGetSymbolAddress((void**)&cc,   g_cc);
    float* Hc1 = Hc;
    float* Hc2 = Hc + (long)NSAMP*HH;

    cudaFuncSetAttribute(k_wgemm2<true>,  cudaFuncAttributeMaxDynamicSharedMemorySize, WG2_SMEM);
    cudaFuncSetAttribute(k_wgemm2<false>, cudaFuncAttributeMaxDynamicSharedMemorySize, WG2_SMEM);
    cudaFuncSetAttribute(k_costsink, cudaFuncAttributeMaxDynamicSharedMemorySize, CS_SMEM);
    cudaFuncSetAttribute(k_pcmp_w, cudaFuncAttributeMaxDynamicSharedMemorySize, PC_SMEM);

    // 1) embedding pool
    k_embed<<<NSAMP, 320>>>(data, emb, enc);
    // 2) FFN (tf32 WMMA, RN cvt)
    dim3 gF(3, 79, 1);
    k_wgemm2<true><<<gF, 256, WG2_SMEM>>>(enc, W1, b1, h1,   NSAMP, HH, DD, 0, 0);
    k_wgemm2<true><<<gF, 256, WG2_SMEM>>>(h1,  W2, b2, henc, NSAMP, HH, HH, 0, 0);

    // fork: Hc GEMM on side stream
    cudaEventRecord(g_hx.eHenc, 0);
    cudaStreamWaitEvent(g_hx.sB, g_hx.eHenc, 0);
    dim3 gHc(3, 79, 2);
    k_wgemm2<false><<<gHc, 256, WG2_SMEM, g_hx.sB>>>(henc, Wc, nullptr, Hc,
                                                     NSAMP, HH, HH, (long)HH*HH, (long)NSAMP*HH);
    cudaEventRecord(g_hx.eHc, g_hx.sB);

    // chain A on default stream: fused cost+sinkhorn (exact fp32)
    k_invnorm<<<(NSAMP + 7)/8, 256>>>(henc, invh);
    k_costsink<<<BB, 256, CS_SMEM>>>(henc, invh, row_idx, col_idx,
                                     row_len, col_len, Pb);

    // join
    cudaStreamWaitEvent(0, g_hx.eHc, 0);
    k_pcmp_w<<<dim3(3, 2, BB), 256, PC_SMEM>>>(Pb, Hc1, Hc2, bc, row_idx, col_idx,
                                               row_len, col_len, cr, cc);
    k_cls<<<BB, 320>>>(cr, cc, Wcls, bcls, Wout, bout, out);
}

// round 9
// speedup vs baseline: 1.2152x; 1.0097x over previous
#include <cuda_runtime.h>
#include <math.h>
#include <mma.h>
using namespace nvcuda;

// ---- problem dims ----
#define NSAMP 10000
#define LTOK  32
#define DD    300
#define HH    300
#define BB    256
#define NMX   128
#define ITERS 50

// ---- scratch ----
__device__ float g_enc [NSAMP*DD];
__device__ float g_h1  [NSAMP*HH];
__device__ float g_henc[NSAMP*HH];
__device__ float g_henct[NSAMP*HH];
__device__ float g_Hc  [2*NSAMP*HH];
__device__ float g_Wr  [4*HH*HH];      // W1r | W2r | Wcr(600x300)
__device__ float g_invh[NSAMP];
__device__ float g_Pmat[BB*NMX*NMX];
__device__ float g_cr  [BB*HH];
__device__ float g_cc  [BB*HH];

// ---- streams/events (static init, pre-checkpoint) ----
struct HxStreams {
    cudaStream_t sB;
    cudaEvent_t eHenc, eHc;
    HxStreams() {
        cudaStreamCreateWithFlags(&sB, cudaStreamNonBlocking);
        cudaEventCreateWithFlags(&eHenc, cudaEventDisableTiming);
        cudaEventCreateWithFlags(&eHc,   cudaEventDisableTiming);
    }
};
static HxStreams g_hx;

// ---- cp.async helpers ----
__device__ __forceinline__ void cpa16(unsigned int dst, const void* src) {
    asm volatile("cp.async.ca.shared.global [%0], [%1], 16;" :: "r"(dst), "l"(src));
}
__device__ __forceinline__ void cpa_commit() {
    asm volatile("cp.async.commit_group;");
}
template<int NN> __device__ __forceinline__ void cpa_wait() {
    asm volatile("cp.async.wait_group %0;" :: "n"(NN));
}

// scalar RN fp32 -> tf32 (same op F2TF applied; hoisted to producers)
__device__ __forceinline__ float tf32r(float x) { return wmma::__float_to_tf32(x); }
__device__ __forceinline__ float4 tf32r4(float4 v) {
    v.x = tf32r(v.x); v.y = tf32r(v.y); v.z = tf32r(v.z); v.w = tf32r(v.w);
    return v;
}

// ============================================================
// 0) pre-round weights to tf32 (RN) into scratch
// ============================================================
__global__ void k_roundw(const float* __restrict__ W1, const float* __restrict__ W2,
                         const float* __restrict__ Wc, float* __restrict__ Wr) {
    int i = blockIdx.x * 256 + threadIdx.x;
    if (i < HH*HH)   Wr[i]           = tf32r(W1[i]);
    if (i < HH*HH)   Wr[HH*HH + i]   = tf32r(W2[i]);
    if (i < 2*HH*HH) Wr[2*HH*HH + i] = tf32r(Wc[i]);
}

// ============================================================
// 1) embedding + masked mean pool (output rounded to tf32)
// ============================================================
__global__ void k_embed(const int* __restrict__ data,
                        const float* __restrict__ emb,
                        float* __restrict__ enc) {
    int s = blockIdx.x;
    int t = threadIdx.x;            // 320 threads
    __shared__ int toks[LTOK];
    if (t < LTOK) toks[t] = data[s*LTOK + t];
    __syncthreads();
    int cnt = 0;
#pragma unroll
    for (int l = 0; l < LTOK; l++) cnt += (toks[l] != 0);
    float inv = 1.0f / (float)(cnt > 0 ? cnt : 1);
    if (t < DD) {
        float acc = 0.f;
#pragma unroll
        for (int l = 0; l < LTOK; l++) {
            int tok = toks[l];
            if (tok != 0) acc += emb[tok*DD + t];
        }
        enc[s*DD + t] = tf32r(acc * inv);
    }
}

// ============================================================
// 2) WMMA tf32 GEMM, no inner-loop cvt (inputs pre-rounded):
//    128x128, BK=16, cp.async dbuf, 8 warps.
//    round_mask bit z: round C output to tf32.  C2: extra rounded copy.
// ============================================================
#define SA   20
#define SB   132
#define ASTG (128*SA)
#define BSTG (16*SB)
#define WG2_SMEM (2*(ASTG+BSTG)*4)

template<bool RELU>
__global__ void __launch_bounds__(256, 2)
k_wgemm2(const float* __restrict__ A, const float* __restrict__ B,
         const float* __restrict__ bias, float* __restrict__ C, float* __restrict__ C2,
         int M, int N, int K, long bStride, long cStride, int round_mask) {
    B += (long)blockIdx.z * bStride;
    C += (long)blockIdx.z * cStride;
    bool rnd = (round_mask >> blockIdx.z) & 1;
    extern __shared__ float sm[];
    unsigned int smb = (unsigned int)__cvta_generic_to_shared(sm);
    int t = threadIdx.x;
    int wid = t >> 5, wm = wid >> 2, wn = wid & 3;
    int mBase = blockIdx.y * 128, nBase = blockIdx.x * 128;
    int nT = (K + 15) >> 4;

    wmma::fragment<wmma::accumulator, 16, 16, 8, float> acc[4][2];
#pragma unroll
    for (int i = 0; i < 4; i++)
#pragma unroll
        for (int j = 0; j < 2; j++) wmma::fill_fragment(acc[i][j], 0.f);

#define W2_LOAD(k0, buf)                                                     \
    {                                                                        \
        _Pragma("unroll")                                                    \
        for (int p = 0; p < 2; p++) {                                        \
            int id = t + p*256;                                              \
            int m = id >> 2, c4 = id & 3;                                    \
            int gm = mBase + m, gk = (k0) + c4*4;                            \
            int off = (buf)*ASTG + m*SA + c4*4;                              \
            if (gm < M && gk < K) cpa16(smb + off*4, A + (size_t)gm*K + gk); \
            else *(float4*)(sm + off) = make_float4(0.f,0.f,0.f,0.f);        \
        }                                                                    \
        _Pragma("unroll")                                                    \
        for (int p = 0; p < 2; p++) {                                        \
            int id = t + p*256;                                              \
            int kr = id >> 5, n4 = id & 31;                                  \
            int gk = (k0) + kr, gn = nBase + n4*4;                           \
            int off = 2*ASTG + (buf)*BSTG + kr*SB + n4*4;                    \
            if (gk < K && gn < N) cpa16(smb + off*4, B + (size_t)gk*N + gn); \
            else *(float4*)(sm + off) = make_float4(0.f,0.f,0.f,0.f);        \
        }                                                                    \
        cpa_commit();                                                        \
    }

    W2_LOAD(0, 0);
    for (int ti = 0; ti < nT; ti++) {
        int cur = ti & 1;
        if (ti + 1 < nT) { W2_LOAD((ti+1)*16, cur^1); cpa_wait<1>(); }
        else             { cpa_wait<0>(); }
        __syncthreads();
        const float* ap = sm + cur*ASTG;
        const float* bp = sm + 2*ASTG + cur*BSTG;
#pragma unroll
        for (int ks = 0; ks < 2; ks++) {
            int k8 = ks*8;
            wmma::fragment<wmma::matrix_b, 16, 16, 8, wmma::precision::tf32, wmma::row_major> bf[2];
#pragma unroll
            for (int j = 0; j < 2; j++)
                wmma::load_matrix_sync(bf[j], bp + k8*SB + wn*32 + j*16, SB);
#pragma unroll
            for (int i = 0; i < 4; i++) {
                wmma::fragment<wmma::matrix_a, 16, 16, 8, wmma::precision::tf32, wmma::row_major> af;
                wmma::load_matrix_sync(af, ap + (wm*64 + i*16)*SA + k8, SA);
                wmma::mma_sync(acc[i][0], af, bf[0], acc[i][0]);
                wmma::mma_sync(acc[i][1], af, bf[1], acc[i][1]);
            }
        }
        __syncthreads();
    }
#undef W2_LOAD

#pragma unroll
    for (int ph = 0; ph < 2; ph++) {
        if (wm == ph) {
#pragma unroll
            for (int i = 0; i < 4; i++)
#pragma unroll
                for (int j = 0; j < 2; j++)
                    wmma::store_matrix_sync(sm + (i*16)*132 + wn*32 + j*16,
                                            acc[i][j], 132, wmma::mem_row_major);
        }
        __syncthreads();
#pragma unroll
        for (int q = 0; q < 8; q++) {
            int idx = t + q*256;
            int row = idx >> 5, c4 = idx & 31;
            int gm = mBase + ph*64 + row, gn = nBase + c4*4;
            if (gm < M && gn < N) {
                float4 v = *(float4*)&sm[row*132 + c4*4];
                float4 bb = bias ? *(const float4*)&bias[gn] : make_float4(0.f,0.f,0.f,0.f);
                v.x += bb.x; v.y += bb.y; v.z += bb.z; v.w += bb.w;
                if (RELU) {
                    v.x = fmaxf(v.x, 0.f); v.y = fmaxf(v.y, 0.f);
                    v.z = fmaxf(v.z, 0.f); v.w = fmaxf(v.w, 0.f);
                }
                if (C2) {
                    *(float4*)&C[(size_t)gm*N + gn] = v;
                    *(float4*)&C2[(size_t)gm*N + gn] = tf32r4(v);
                } else {
                    if (rnd) v = tf32r4(v);
                    *(float4*)&C[(size_t)gm*N + gn] = v;
                }
            }
        }
        __syncthreads();
    }
}

// ============================================================
// 3) per-sample inverse norm of henc (exact fp32 input)
// ============================================================
__global__ void k_invnorm(const float* __restrict__ henc, float* __restrict__ invh) {
    int s = blockIdx.x * 8 + (threadIdx.x >> 5);
    int l = threadIdx.x & 31;
    if (s >= NSAMP) return;
    const float4* hp = (const float4*)(henc + (size_t)s*HH);
    float sq = 0.f;
    for (int d4 = l; d4 < 75; d4 += 32) {
        float4 v = hp[d4];
        sq += v.x*v.x + v.y*v.y + v.z*v.z + v.w*v.w;
    }
#pragma unroll
    for (int o = 16; o; o >>= 1) sq += __shfl_down_sync(0xffffffffu, sq, o);
    if (l == 0) invh[s] = 1.0f / (sqrtf(sq) + 1e-8f);
}

// ============================================================
// 4) FUSED cost + Sinkhorn (exact fp32); P output rounded to tf32
// ============================================================
#define CS_KS    (128*132)
#define CS_STAGE (2*16*132)
#define CS_SMEM  ((CS_KS + 2*CS_STAGE)*4)   // 101376 bytes

__global__ void __launch_bounds__(256, 2)
k_costsink(const float* __restrict__ henc, const float* __restrict__ invh,
           const int* __restrict__ ridx, const int* __restrict__ cidx,
           const int* __restrict__ rlen, const int* __restrict__ clen,
           float* __restrict__ P) {
    int b = blockIdx.x;
    extern __shared__ float sm[];
    float* Ks = sm;                    // 128*132
    float* As = sm + CS_KS;            // [2][16*132]
    float* Bs = As + CS_STAGE;         // [2][16*132]
    __shared__ int sr[128], sc[128];
    __shared__ float sir[128], sic[128];
    int t = threadIdx.x, tx = t & 15, ty = t >> 4;
    if (t < 128) {
        int i = ridx[b*128 + t];
        sr[t] = i; sir[t] = invh[i];
    } else {
        int i = cidx[b*128 + (t-128)];
        sc[t-128] = i; sic[t-128] = invh[i];
    }
    __syncthreads();

#define CO_LOAD(k0, buf)                                                      \
    {                                                                         \
        _Pragma("unroll")                                                     \
        for (int p = 0; p < 2; p++) {                                         \
            int id = p*256 + t;                                               \
            int m = id >> 2, kq = id & 3;                                     \
            int gk = (k0) + kq*4;                                             \
            float4 va = make_float4(0.f,0.f,0.f,0.f), vb = va;                \
            if (gk < 300) {                                                   \
                va = *(const float4*)&henc[(size_t)sr[m]*300 + gk];           \
                vb = *(const float4*)&henc[(size_t)sc[m]*300 + gk];           \
            }                                                                 \
            As[(buf)*2112 + (kq*4+0)*132 + m] = va.x;                         \
            As[(buf)*2112 + (kq*4+1)*132 + m] = va.y;                         \
            As[(buf)*2112 + (kq*4+2)*132 + m] = va.z;                         \
            As[(buf)*2112 + (kq*4+3)*132 + m] = va.w;                         \
            Bs[(buf)*2112 + (kq*4+0)*132 + m] = vb.x;                         \
            Bs[(buf)*2112 + (kq*4+1)*132 + m] = vb.y;                         \
            Bs[(buf)*2112 + (kq*4+2)*132 + m] = vb.z;                         \
            Bs[(buf)*2112 + (kq*4+3)*132 + m] = vb.w;                         \
        }                                                                     \
    }

    float acc[8][8] = {};
    CO_LOAD(0, 0);
    __syncthreads();
    for (int ti = 0; ti < 19; ti++) {
        int cur = ti & 1;
        if (ti + 1 < 19) CO_LOAD((ti+1)*16, cur^1);
        const float* Asb = As + cur*2112;
        const float* Bsb = Bs + cur*2112;
#pragma unroll
        for (int kk = 0; kk < 16; kk++) {
            float4 a0 = *(const float4*)&Asb[kk*132 + ty*4];
            float4 a1 = *(const float4*)&Asb[kk*132 + 64 + ty*4];
            float4 b0 = *(const float4*)&Bsb[kk*132 + tx*4];
            float4 b1 = *(const float4*)&Bsb[kk*132 + 64 + tx*4];
            float av[8] = {a0.x,a0.y,a0.z,a0.w,a1.x,a1.y,a1.z,a1.w};
            float bv[8] = {b0.x,b0.y,b0.z,b0.w,b1.x,b1.y,b1.z,b1.w};
#pragma unroll
            for (int i = 0; i < 8; i++)
#pragma unroll
                for (int j = 0; j < 8; j++) acc[i][j] += av[i]*bv[j];
        }
        __syncthreads();
    }
#undef CO_LOAD
    int rl = rlen[b], cl = clen[b];
#pragma unroll
    for (int i = 0; i < 8; i++) {
        int n = (i < 4) ? ty*4 + i : 64 + ty*4 + i - 4;
        float ir = sir[n];
        bool nv = (n < rl);
#pragma unroll
        for (int jh = 0; jh < 2; jh++) {
            float r[4];
#pragma unroll
            for (int j = 0; j < 4; j++) {
                int m = jh*64 + tx*4 + j;
                float dn = acc[i][jh*4+j] * ir * sic[m];
                r[j] = (nv && m < cl) ? __expf((dn - 1.0f) * 10.0f) : 0.f;
            }
            float4 kv; kv.x = r[0]; kv.y = r[1]; kv.z = r[2]; kv.w = r[3];
            *(float4*)&Ks[n*132 + jh*64 + tx*4] = kv;
        }
    }

    // ---- phase 2: Sinkhorn on smem K ----
    float* u   = As;          // 128
    float* v   = As + 128;    // 128
    float* red = As + 256;    // 1024
    float ra = 1.0f / (float)rl, rb = 1.0f / (float)cl;
    if (t < 128) u[t] = (t < cl) ? 1.0f : 0.0f;
    __syncthreads();

    int r128 = t & 127, half = t >> 7;
    int w8 = t >> 5, l32 = t & 31;
    const float4* Kr4 = (const float4*)(Ks + r128*132 + half*64);
    const float4* u4h = (const float4*)(u + half*64);
    for (int it = 0; it < ITERS; it++) {
        float4 s4 = make_float4(0.f,0.f,0.f,0.f);
#pragma unroll
        for (int m = 0; m < 16; m++) {
            float4 k4 = Kr4[m], uu = u4h[m];
            s4.x += k4.x*uu.x; s4.y += k4.y*uu.y;
            s4.z += k4.z*uu.z; s4.w += k4.w*uu.w;
        }
        red[half*128 + r128] = (s4.x + s4.y) + (s4.z + s4.w);
        __syncthreads();
        if (t < 128) {
            float s = red[t] + red[128 + t];
            v[t] = (t < rl) ? ra / s : 0.f;
        }
        __syncthreads();
        float4 q4 = make_float4(0.f,0.f,0.f,0.f);
#pragma unroll
        for (int rr = 0; rr < 16; rr++) {
            int n = w8*16 + rr;
            float vn = v[n];
            float4 k4 = *(const float4*)(Ks + n*132 + l32*4);
            q4.x += k4.x*vn; q4.y += k4.y*vn;
            q4.z += k4.z*vn; q4.w += k4.w*vn;
        }
        *(float4*)(red + w8*128 + l32*4) = q4;
        __syncthreads();
        if (t < 128) {
            float q = 0.f;
#pragma unroll
            for (int w = 0; w < 8; w++) q += red[w*128 + t];
            u[t] = (t < cl) ? rb / q : 0.f;
        }
        __syncthreads();
    }
    float ut = u[r128];
    float* Pb = P + (size_t)b*NMX*NMX;
    for (int i = half; i < 128; i += 2)
        Pb[i*128 + r128] = tf32r(v[i] * Ks[i*132 + r128] * ut);
}

// ============================================================
// 5) P-GEMM (tf32 WMMA, inputs pre-rounded) + fused compare epilogue
// ============================================================
#define PC_SMEM (((2*BSTG > 64*132) ? 2*BSTG : 64*132)*4)

__global__ void __launch_bounds__(256, 2)
k_pcmp_w(const float* __restrict__ P,
         const float* __restrict__ Hc1, const float* __restrict__ Hc2,
         const float* __restrict__ bc,
         const int* __restrict__ ridx, const int* __restrict__ cidx,
         const int* __restrict__ rlen, const int* __restrict__ clen,
         float* __restrict__ cr, float* __restrict__ cc) {
    int b = blockIdx.z, mode = blockIdx.y;
    int hBase = blockIdx.x * 128;
    const int* gidxA = mode ? (ridx + b*128) : (cidx + b*128);
    const int* gidxE = mode ? (cidx + b*128) : (ridx + b*128);
    int len = mode ? clen[b] : rlen[b];
    const float* Pb = P + (size_t)b*NMX*NMX;

    extern __shared__ float sm[];
    unsigned int smb = (unsigned int)__cvta_generic_to_shared(sm);
    __shared__ int sA[128], sE[128];
    __shared__ float red2[256];
    int t = threadIdx.x;
    int wid = t >> 5, wm = wid >> 2, wn = wid & 3;
    if (t < 128) sA[t] = gidxA[t];
    else sE[t-128] = gidxE[t-128];
    __syncthreads();

    wmma::fragment<wmma::accumulator, 16, 16, 8, float> acc[4][2];
#pragma unroll
    for (int i = 0; i < 4; i++)
#pragma unroll
        for (int j = 0; j < 2; j++) wmma::fill_fragment(acc[i][j], 0.f);

#define PCW_LOADB(k0, buf)                                                   \
    {                                                                        \
        _Pragma("unroll")                                                    \
        for (int p = 0; p < 2; p++) {                                        \
            int id = t + p*256;                                              \
            int kr = id >> 5, n4 = id & 31;                                  \
            int gh = hBase + n4*4;                                           \
            int off = (buf)*BSTG + kr*SB + n4*4;                             \
            if (gh < 300) cpa16(smb + off*4, Hc2 + (size_t)sA[(k0)+kr]*300 + gh);\
            else *(float4*)(sm + off) = make_float4(0.f,0.f,0.f,0.f);        \
        }                                                                    \
        cpa_commit();                                                        \
    }

    PCW_LOADB(0, 0);
    for (int ti = 0; ti < 8; ti++) {
        int cur = ti & 1;
        if (ti + 1 < 8) { PCW_LOADB((ti+1)*16, cur^1); cpa_wait<1>(); }
        else            { cpa_wait<0>(); }
        __syncthreads();
        const float* bp = sm + cur*BSTG;
#pragma unroll
        for (int ks = 0; ks < 2; ks++) {
            int k8 = ti*16 + ks*8;
            wmma::fragment<wmma::matrix_b, 16, 16, 8, wmma::precision::tf32, wmma::row_major> bf[2];
#pragma unroll
            for (int j = 0; j < 2; j++)
                wmma::load_matrix_sync(bf[j], bp + ks*8*SB + wn*32 + j*16, SB);
            if (mode == 0) {
#pragma unroll
                for (int i = 0; i < 4; i++) {
                    wmma::fragment<wmma::matrix_a, 16, 16, 8, wmma::precision::tf32, wmma::row_major> af;
                    wmma::load_matrix_sync(af, Pb + (size_t)(wm*64 + i*16)*128 + k8, 128);
                    wmma::mma_sync(acc[i][0], af, bf[0], acc[i][0]);
                    wmma::mma_sync(acc[i][1], af, bf[1], acc[i][1]);
                }
            } else {
#pragma unroll
                for (int i = 0; i < 4; i++) {
                    wmma::fragment<wmma::matrix_a, 16, 16, 8, wmma::precision::tf32, wmma::col_major> af;
                    wmma::load_matrix_sync(af, Pb + (size_t)k8*128 + wm*64 + i*16, 128);
                    wmma::mma_sync(acc[i][0], af, bf[0], acc[i][0]);
                    wmma::mma_sync(acc[i][1], af, bf[1], acc[i][1]);
                }
            }
        }
        __syncthreads();
    }
#undef PCW_LOADB

    float colsum = 0.f;
    int hc = t & 127, rh = t >> 7;
    int hg = hBase + hc;
    float bcv = (hg < 300) ? bc[hg] : 0.f;
#pragma unroll
    for (int ph = 0; ph < 2; ph++) {
        if (wm == ph) {
#pragma unroll
            for (int i = 0; i < 4; i++)
#pragma unroll
                for (int j = 0; j < 2; j++)
                    wmma::store_matrix_sync(sm + (i*16)*132 + wn*32 + j*16,
                                            acc[i][j], 132, wmma::mem_row_major);
        }
        __syncthreads();
        if (hg < 300) {
            for (int r = rh*32; r < rh*32 + 32; r++) {
                int gr = ph*64 + r;
                if (gr < len)
                    colsum += fmaxf(sm[r*132 + hc] + Hc1[(size_t)sE[gr]*300 + hg] + bcv, 0.f);
            }
        }
        __syncthreads();
    }
    red2[t] = colsum;
    __syncthreads();
    if (t < 128 && hg < 300) {
        float* outp = mode ? cc : cr;
        outp[b*HH + hg] = red2[t] + red2[t + 128];
    }
}

// ============================================================
// 6) classifier head
// ============================================================
__global__ void k_cls(const float* __restrict__ cr,
                      const float* __restrict__ cc,
                      const float* __restrict__ Wcls,
                      const float* __restrict__ bcls,
                      const float* __restrict__ Wout,
                      const float* __restrict__ bout,
                      float* __restrict__ out) {
    int b = blockIdx.x;
    int t = threadIdx.x;              // 320 threads
    __shared__ float x[2*HH];
    for (int i = t; i < 2*HH; i += 320)
        x[i] = (i < HH) ? cr[b*HH + i] : cc[b*HH + i - HH];
    __syncthreads();
    float z = 0.f;
    if (t < HH) {
        float a0 = 0.f, a1 = 0.f, a2 = 0.f, a3 = 0.f;
#pragma unroll 4
        for (int k = 0; k < 2*HH; k += 4) {
            a0 += x[k+0]*Wcls[(k+0)*HH + t];
            a1 += x[k+1]*Wcls[(k+1)*HH + t];
            a2 += x[k+2]*Wcls[(k+2)*HH + t];
            a3 += x[k+3]*Wcls[(k+3)*HH + t];
        }
        z = fmaxf((a0+a1)+(a2+a3) + bcls[t], 0.f);
    }
    float s0 = (t < HH) ? z*Wout[t*2 + 0] : 0.f;
    float s1 = (t < HH) ? z*Wout[t*2 + 1] : 0.f;
#pragma unroll
    for (int o = 16; o; o >>= 1) {
        s0 += __shfl_down_sync(0xffffffffu, s0, o);
        s1 += __shfl_down_sync(0xffffffffu, s1, o);
    }
    __shared__ float r0[10], r1[10];
    if ((t & 31) == 0) { r0[t >> 5] = s0; r1[t >> 5] = s1; }
    __syncthreads();
    if (t == 0) {
        float a = 0.f, c = 0.f;
#pragma unroll
        for (int i = 0; i < 10; i++) { a += r0[i]; c += r1[i]; }
        out[b*2 + 0] = a + bout[0];
        out[b*2 + 1] = c + bout[1];
    }
}

// ============================================================
// launch
// ============================================================
extern "C" void kernel_launch(void* const* d_in, const int* in_sizes, int n_in,
                              void* d_out, int out_size) {
    const int*   data    = (const int*)  d_in[0];
    const int*   row_idx = (const int*)  d_in[1];
    const int*   col_idx = (const int*)  d_in[2];
    const int*   row_len = (const int*)  d_in[3];
    const int*   col_len = (const int*)  d_in[4];
    const float* emb     = (const float*)d_in[5];
    const float* W1      = (const float*)d_in[6];
    const float* b1      = (const float*)d_in[7];
    const float* W2      = (const float*)d_in[8];
    const float* b2      = (const float*)d_in[9];
    const float* Wc      = (const float*)d_in[10];
    const float* bc      = (const float*)d_in[11];
    const float* Wcls    = (const float*)d_in[12];
    const float* bcls    = (const float*)d_in[13];
    const float* Wout    = (const float*)d_in[14];
    const float* bout    = (const float*)d_in[15];
    float* out = (float*)d_out;

    float *enc, *h1, *henc, *henct, *Hc, *Wr, *invh, *Pb, *cr, *cc;
    cudaGetSymbolAddress((void**)&enc,   g_enc);
    cudaGetSymbolAddress((void**)&h1,    g_h1);
    cudaGetSymbolAddress((void**)&henc,  g_henc);
    cudaGetSymbolAddress((void**)&henct, g_henct);
    cudaGetSymbolAddress((void**)&Hc,    g_Hc);
    cudaGetSymbolAddress((void**)&Wr,    g_Wr);
    cudaGetSymbolAddress((void**)&invh,  g_invh);
    cudaGetSymbolAddress((void**)&Pb,    g_Pmat);
    cudaGetSymbolAddress((void**)&cr,    g_cr);
    cudaGetSymbolAddress((void**)&cc,    g_cc);
    float* W1r = Wr;
    float* W2r = Wr + HH*HH;
    float* Wcr = Wr + 2*HH*HH;
    float* Hc1 = Hc;
    float* Hc2 = Hc + (long)NSAMP*HH;

    cudaFuncSetAttribute(k_wgemm2<true>,  cudaFuncAttributeMaxDynamicSharedMemorySize, WG2_SMEM);
    cudaFuncSetAttribute(k_wgemm2<false>, cudaFuncAttributeMaxDynamicSharedMemorySize, WG2_SMEM);
    cudaFuncSetAttribute(k_costsink, cudaFuncAttributeMaxDynamicSharedMemorySize, CS_SMEM);
    cudaFuncSetAttribute(k_pcmp_w, cudaFuncAttributeMaxDynamicSharedMemorySize, PC_SMEM);

    // 0) round weights into scratch (tiny)
    k_roundw<<<(2*HH*HH + 255)/256, 256>>>(W1, W2, Wc, Wr);
    // 1) embedding pool (enc rounded to tf32)
    k_embed<<<NSAMP, 320>>>(data, emb, enc);
    // 2) FFN: h1 rounded (mask=1); henc exact + henct rounded copy
    dim3 gF(3, 79, 1);
    k_wgemm2<true><<<gF, 256, WG2_SMEM>>>(enc, W1r, b1, h1, nullptr,
                                          NSAMP, HH, DD, 0, 0, 1);
    k_wgemm2<true><<<gF, 256, WG2_SMEM>>>(h1, W2r, b2, henc, henct,
                                          NSAMP, HH, HH, 0, 0, 0);

    // fork: Hc GEMM on side stream (A=henct pre-rounded; round Hc2 only, mask=2)
    cudaEventRecord(g_hx.eHenc, 0);
    cudaStreamWaitEvent(g_hx.sB, g_hx.eHenc, 0);
    dim3 gHc(3, 79, 2);
    k_wgemm2<false><<<gHc, 256, WG2_SMEM, g_hx.sB>>>(henct, Wcr, nullptr, Hc, nullptr,
                                                     NSAMP, HH, HH, (long)HH*HH,
                                                     (long)NSAMP*HH, 2);
    cudaEventRecord(g_hx.eHc, g_hx.sB);

    // chain A on default stream: fused cost+sinkhorn (exact fp32, P rounded out)
    k_invnorm<<<(NSAMP + 7)/8, 256>>>(henc, invh);
    k_costsink<<<BB, 256, CS_SMEM>>>(henc, invh, row_idx, col_idx,
                                     row_len, col_len, Pb);

    // join
    cudaStreamWaitEvent(0, g_hx.eHc, 0);
    k_pcmp_w<<<dim3(3, 2, BB), 256, PC_SMEM>>>(Pb, Hc1, Hc2, bc, row_idx, col_idx,
                                               row_len, col_len, cr, cc);
    k_cls<<<BB, 320>>>(cr, cc, Wcls, bcls, Wout, bout, out);
}

// round 10
// speedup vs baseline: 1.3423x; 1.1046x over previous
#include <cuda_runtime.h>
#include <math.h>
#include <mma.h>
using namespace nvcuda;

// ---- problem dims ----
#define NSAMP 10000
#define LTOK  32
#define DD    300
#define HH    300
#define BB    256
#define NMX   128
#define ITERS 50

// ---- scratch ----
__device__ float g_enc [NSAMP*DD];
__device__ float g_h1  [NSAMP*HH];
__device__ float g_henc[NSAMP*HH];
__device__ float g_henct[NSAMP*HH];
__device__ float g_Hc  [2*NSAMP*HH];
__device__ float g_Wr  [4*HH*HH];
__device__ float g_invh[NSAMP];
__device__ float g_Pmat[BB*NMX*NMX];
__device__ float g_cr  [BB*HH];
__device__ float g_cc  [BB*HH];

// ---- streams/events (static init, pre-checkpoint) ----
struct HxStreams {
    cudaStream_t sB;
    cudaEvent_t eHenc, eHc;
    HxStreams() {
        cudaStreamCreateWithFlags(&sB, cudaStreamNonBlocking);
        cudaEventCreateWithFlags(&eHenc, cudaEventDisableTiming);
        cudaEventCreateWithFlags(&eHc,   cudaEventDisableTiming);
    }
};
static HxStreams g_hx;

// ---- cp.async helpers ----
__device__ __forceinline__ void cpa16(unsigned int dst, const void* src) {
    asm volatile("cp.async.ca.shared.global [%0], [%1], 16;" :: "r"(dst), "l"(src));
}
__device__ __forceinline__ void cpa_commit() {
    asm volatile("cp.async.commit_group;");
}
template<int NN> __device__ __forceinline__ void cpa_wait() {
    asm volatile("cp.async.wait_group %0;" :: "n"(NN));
}

__device__ __forceinline__ float tf32r(float x) { return wmma::__float_to_tf32(x); }
__device__ __forceinline__ float4 tf32r4(float4 v) {
    v.x = tf32r(v.x); v.y = tf32r(v.y); v.z = tf32r(v.z); v.w = tf32r(v.w);
    return v;
}

// ============================================================
// 0) pre-round weights to tf32 (RN) into scratch
// ============================================================
__global__ void k_roundw(const float* __restrict__ W1, const float* __restrict__ W2,
                         const float* __restrict__ Wc, float* __restrict__ Wr) {
    int i = blockIdx.x * 256 + threadIdx.x;
    if (i < HH*HH)   Wr[i]           = tf32r(W1[i]);
    if (i < HH*HH)   Wr[HH*HH + i]   = tf32r(W2[i]);
    if (i < 2*HH*HH) Wr[2*HH*HH + i] = tf32r(Wc[i]);
}

// ============================================================
// 1) embedding + masked mean pool (output rounded to tf32)
// ============================================================
__global__ void k_embed(const int* __restrict__ data,
                        const float* __restrict__ emb,
                        float* __restrict__ enc) {
    int s = blockIdx.x;
    int t = threadIdx.x;            // 320 threads
    __shared__ int toks[LTOK];
    if (t < LTOK) toks[t] = data[s*LTOK + t];
    __syncthreads();
    int cnt = 0;
#pragma unroll
    for (int l = 0; l < LTOK; l++) cnt += (toks[l] != 0);
    float inv = 1.0f / (float)(cnt > 0 ? cnt : 1);
    if (t < DD) {
        float acc = 0.f;
#pragma unroll
        for (int l = 0; l < LTOK; l++) {
            int tok = toks[l];
            if (tok != 0) acc += emb[tok*DD + t];
        }
        enc[s*DD + t] = tf32r(acc * inv);
    }
}

// ============================================================
// 2) WMMA tf32 GEMM (inputs pre-rounded), 128x128, BK=16
// ============================================================
#define SA   20
#define SB   132
#define ASTG (128*SA)
#define BSTG (16*SB)
#define WG2_SMEM (2*(ASTG+BSTG)*4)

template<bool RELU>
__global__ void __launch_bounds__(256, 2)
k_wgemm2(const float* __restrict__ A, const float* __restrict__ B,
         const float* __restrict__ bias, float* __restrict__ C, float* __restrict__ C2,
         int M, int N, int K, long bStride, long cStride, int round_mask) {
    B += (long)blockIdx.z * bStride;
    C += (long)blockIdx.z * cStride;
    bool rnd = (round_mask >> blockIdx.z) & 1;
    extern __shared__ float sm[];
    unsigned int smb = (unsigned int)__cvta_generic_to_shared(sm);
    int t = threadIdx.x;
    int wid = t >> 5, wm = wid >> 2, wn = wid & 3;
    int mBase = blockIdx.y * 128, nBase = blockIdx.x * 128;
    int nT = (K + 15) >> 4;

    wmma::fragment<wmma::accumulator, 16, 16, 8, float> acc[4][2];
#pragma unroll
    for (int i = 0; i < 4; i++)
#pragma unroll
        for (int j = 0; j < 2; j++) wmma::fill_fragment(acc[i][j], 0.f);

#define W2_LOAD(k0, buf)                                                     \
    {                                                                        \
        _Pragma("unroll")                                                    \
        for (int p = 0; p < 2; p++) {                                        \
            int id = t + p*256;                                              \
            int m = id >> 2, c4 = id & 3;                                    \
            int gm = mBase + m, gk = (k0) + c4*4;                            \
            int off = (buf)*ASTG + m*SA + c4*4;                              \
            if (gm < M && gk < K) cpa16(smb + off*4, A + (size_t)gm*K + gk); \
            else *(float4*)(sm + off) = make_float4(0.f,0.f,0.f,0.f);        \
        }                                                                    \
        _Pragma("unroll")                                                    \
        for (int p = 0; p < 2; p++) {                                        \
            int id = t + p*256;                                              \
            int kr = id >> 5, n4 = id & 31;                                  \
            int gk = (k0) + kr, gn = nBase + n4*4;                           \
            int off = 2*ASTG + (buf)*BSTG + kr*SB + n4*4;                    \
            if (gk < K && gn < N) cpa16(smb + off*4, B + (size_t)gk*N + gn); \
            else *(float4*)(sm + off) = make_float4(0.f,0.f,0.f,0.f);        \
        }                                                                    \
        cpa_commit();                                                        \
    }

    W2_LOAD(0, 0);
    for (int ti = 0; ti < nT; ti++) {
        int cur = ti & 1;
        if (ti + 1 < nT) { W2_LOAD((ti+1)*16, cur^1); cpa_wait<1>(); }
        else             { cpa_wait<0>(); }
        __syncthreads();
        const float* ap = sm + cur*ASTG;
        const float* bp = sm + 2*ASTG + cur*BSTG;
#pragma unroll
        for (int ks = 0; ks < 2; ks++) {
            int k8 = ks*8;
            wmma::fragment<wmma::matrix_b, 16, 16, 8, wmma::precision::tf32, wmma::row_major> bf[2];
#pragma unroll
            for (int j = 0; j < 2; j++)
                wmma::load_matrix_sync(bf[j], bp + k8*SB + wn*32 + j*16, SB);
#pragma unroll
            for (int i = 0; i < 4; i++) {
                wmma::fragment<wmma::matrix_a, 16, 16, 8, wmma::precision::tf32, wmma::row_major> af;
                wmma::load_matrix_sync(af, ap + (wm*64 + i*16)*SA + k8, SA);
                wmma::mma_sync(acc[i][0], af, bf[0], acc[i][0]);
                wmma::mma_sync(acc[i][1], af, bf[1], acc[i][1]);
            }
        }
        __syncthreads();
    }
#undef W2_LOAD

#pragma unroll
    for (int ph = 0; ph < 2; ph++) {
        if (wm == ph) {
#pragma unroll
            for (int i = 0; i < 4; i++)
#pragma unroll
                for (int j = 0; j < 2; j++)
                    wmma::store_matrix_sync(sm + (i*16)*132 + wn*32 + j*16,
                                            acc[i][j], 132, wmma::mem_row_major);
        }
        __syncthreads();
#pragma unroll
        for (int q = 0; q < 8; q++) {
            int idx = t + q*256;
            int row = idx >> 5, c4 = idx & 31;
            int gm = mBase + ph*64 + row, gn = nBase + c4*4;
            if (gm < M && gn < N) {
                float4 v = *(float4*)&sm[row*132 + c4*4];
                float4 bb = bias ? *(const float4*)&bias[gn] : make_float4(0.f,0.f,0.f,0.f);
                v.x += bb.x; v.y += bb.y; v.z += bb.z; v.w += bb.w;
                if (RELU) {
                    v.x = fmaxf(v.x, 0.f); v.y = fmaxf(v.y, 0.f);
                    v.z = fmaxf(v.z, 0.f); v.w = fmaxf(v.w, 0.f);
                }
                if (C2) {
                    *(float4*)&C[(size_t)gm*N + gn] = v;
                    *(float4*)&C2[(size_t)gm*N + gn] = tf32r4(v);
                } else {
                    if (rnd) v = tf32r4(v);
                    *(float4*)&C[(size_t)gm*N + gn] = v;
                }
            }
        }
        __syncthreads();
    }
}

// ============================================================
// 3) per-sample inverse norm of henc
// ============================================================
__global__ void k_invnorm(const float* __restrict__ henc, float* __restrict__ invh) {
    int s = blockIdx.x * 8 + (threadIdx.x >> 5);
    int l = threadIdx.x & 31;
    if (s >= NSAMP) return;
    const float4* hp = (const float4*)(henc + (size_t)s*HH);
    float sq = 0.f;
    for (int d4 = l; d4 < 75; d4 += 32) {
        float4 v = hp[d4];
        sq += v.x*v.x + v.y*v.y + v.z*v.z + v.w*v.w;
    }
#pragma unroll
    for (int o = 16; o; o >>= 1) sq += __shfl_down_sync(0xffffffffu, sq, o);
    if (l == 0) invh[s] = 1.0f / (sqrtf(sq) + 1e-8f);
}

// ============================================================
// 4) FUSED cost + Sinkhorn (exact fp32); register-resident row pass
// ============================================================
#define CS_KS    (128*132)
#define CS_STAGE (2*16*132)
#define CS_SMEM  ((CS_KS + 2*CS_STAGE)*4)   // 101376 bytes

__global__ void __launch_bounds__(256, 2)
k_costsink(const float* __restrict__ henc, const float* __restrict__ invh,
           const int* __restrict__ ridx, const int* __restrict__ cidx,
           const int* __restrict__ rlen, const int* __restrict__ clen,
           float* __restrict__ P) {
    int b = blockIdx.x;
    extern __shared__ float sm[];
    float* Ks = sm;                    // 128*132
    float* As = sm + CS_KS;            // [2][16*132]
    float* Bs = As + CS_STAGE;         // [2][16*132]
    __shared__ int sr[128], sc[128];
    __shared__ float sir[128], sic[128];
    int t = threadIdx.x, tx = t & 15, ty = t >> 4;
    if (t < 128) {
        int i = ridx[b*128 + t];
        sr[t] = i; sir[t] = invh[i];
    } else {
        int i = cidx[b*128 + (t-128)];
        sc[t-128] = i; sic[t-128] = invh[i];
    }
    __syncthreads();

#define CO_LOAD(k0, buf)                                                      \
    {                                                                         \
        _Pragma("unroll")                                                     \
        for (int p = 0; p < 2; p++) {                                         \
            int id = p*256 + t;                                               \
            int m = id >> 2, kq = id & 3;                                     \
            int gk = (k0) + kq*4;                                             \
            float4 va = make_float4(0.f,0.f,0.f,0.f), vb = va;                \
            if (gk < 300) {                                                   \
                va = *(const float4*)&henc[(size_t)sr[m]*300 + gk];           \
                vb = *(const float4*)&henc[(size_t)sc[m]*300 + gk];           \
            }                                                                 \
            As[(buf)*2112 + (kq*4+0)*132 + m] = va.x;                         \
            As[(buf)*2112 + (kq*4+1)*132 + m] = va.y;                         \
            As[(buf)*2112 + (kq*4+2)*132 + m] = va.z;                         \
            As[(buf)*2112 + (kq*4+3)*132 + m] = va.w;                         \
            Bs[(buf)*2112 + (kq*4+0)*132 + m] = vb.x;                         \
            Bs[(buf)*2112 + (kq*4+1)*132 + m] = vb.y;                         \
            Bs[(buf)*2112 + (kq*4+2)*132 + m] = vb.z;                         \
            Bs[(buf)*2112 + (kq*4+3)*132 + m] = vb.w;                         \
        }                                                                     \
    }

    float acc[8][8] = {};
    CO_LOAD(0, 0);
    __syncthreads();
    for (int ti = 0; ti < 19; ti++) {
        int cur = ti & 1;
        if (ti + 1 < 19) CO_LOAD((ti+1)*16, cur^1);
        const float* Asb = As + cur*2112;
        const float* Bsb = Bs + cur*2112;
#pragma unroll
        for (int kk = 0; kk < 16; kk++) {
            float4 a0 = *(const float4*)&Asb[kk*132 + ty*4];
            float4 a1 = *(const float4*)&Asb[kk*132 + 64 + ty*4];
            float4 b0 = *(const float4*)&Bsb[kk*132 + tx*4];
            float4 b1 = *(const float4*)&Bsb[kk*132 + 64 + tx*4];
            float av[8] = {a0.x,a0.y,a0.z,a0.w,a1.x,a1.y,a1.z,a1.w};
            float bv[8] = {b0.x,b0.y,b0.z,b0.w,b1.x,b1.y,b1.z,b1.w};
#pragma unroll
            for (int i = 0; i < 8; i++)
#pragma unroll
                for (int j = 0; j < 8; j++) acc[i][j] += av[i]*bv[j];
        }
        __syncthreads();
    }
#undef CO_LOAD
    int rl = rlen[b], cl = clen[b];
#pragma unroll
    for (int i = 0; i < 8; i++) {
        int n = (i < 4) ? ty*4 + i : 64 + ty*4 + i - 4;
        float ir = sir[n];
        bool nv = (n < rl);
#pragma unroll
        for (int jh = 0; jh < 2; jh++) {
            float r[4];
#pragma unroll
            for (int j = 0; j < 4; j++) {
                int m = jh*64 + tx*4 + j;
                float dn = acc[i][jh*4+j] * ir * sic[m];
                r[j] = (nv && m < cl) ? __expf((dn - 1.0f) * 10.0f) : 0.f;
            }
            float4 kv; kv.x = r[0]; kv.y = r[1]; kv.z = r[2]; kv.w = r[3];
            *(float4*)&Ks[n*132 + jh*64 + tx*4] = kv;
        }
    }

    // ---- phase 2: Sinkhorn; row-pass K half-row in registers ----
    float* u   = As;          // 128
    float* v   = As + 128;    // 128
    float* red = As + 256;    // 1024
    float ra = 1.0f / (float)rl, rb = 1.0f / (float)cl;
    if (t < 128) u[t] = (t < cl) ? 1.0f : 0.0f;
    __syncthreads();

    int r128 = t & 127, half = t >> 7;
    int w8 = t >> 5, l32 = t & 31;
    const float* Krow = Ks + r128*132 + half*64;
    float4 Kreg[16];
#pragma unroll
    for (int m = 0; m < 16; m++) Kreg[m] = *(const float4*)&Krow[m*4];
    const float4* u4h = (const float4*)(u + half*64);

    for (int it = 0; it < ITERS; it++) {
        float4 s4 = make_float4(0.f,0.f,0.f,0.f);
#pragma unroll
        for (int m = 0; m < 16; m++) {
            float4 uu = u4h[m];
            s4.x += Kreg[m].x*uu.x; s4.y += Kreg[m].y*uu.y;
            s4.z += Kreg[m].z*uu.z; s4.w += Kreg[m].w*uu.w;
        }
        red[half*128 + r128] = (s4.x + s4.y) + (s4.z + s4.w);
        __syncthreads();
        if (t < 128) {
            float s = red[t] + red[128 + t];
            v[t] = (t < rl) ? ra / s : 0.f;
        }
        __syncthreads();
        float4 q4 = make_float4(0.f,0.f,0.f,0.f);
#pragma unroll
        for (int rr = 0; rr < 16; rr++) {
            int n = w8*16 + rr;
            float vn = v[n];
            float4 k4 = *(const float4*)(Ks + n*132 + l32*4);
            q4.x += k4.x*vn; q4.y += k4.y*vn;
            q4.z += k4.z*vn; q4.w += k4.w*vn;
        }
        *(float4*)(red + w8*128 + l32*4) = q4;
        __syncthreads();
        if (t < 128) {
            float q = 0.f;
#pragma unroll
            for (int w = 0; w < 8; w++) q += red[w*128 + t];
            u[t] = (t < cl) ? rb / q : 0.f;
        }
        __syncthreads();
    }
    float ut = u[r128];
    float* Pb = P + (size_t)b*NMX*NMX;
    for (int i = half; i < 128; i += 2)
        Pb[i*128 + r128] = tf32r(v[i] * Ks[i*132 + r128] * ut);
}

// ============================================================
// 5) P-GEMM: A (P) staged via cp.async into smem, + fused epilogue
// ============================================================
#define PASTG 2560                       // covers 128*20 (mode0) and 16*132 (mode1)
#define PC_SMEM ((2*PASTG + 2*BSTG)*4)   // 37376 bytes; epilogue 64*132 overlays

__global__ void __launch_bounds__(256, 2)
k_pcmp_w(const float* __restrict__ P,
         const float* __restrict__ Hc1, const float* __restrict__ Hc2,
         const float* __restrict__ bc,
         const int* __restrict__ ridx, const int* __restrict__ cidx,
         const int* __restrict__ rlen, const int* __restrict__ clen,
         float* __restrict__ cr, float* __restrict__ cc) {
    int b = blockIdx.z, mode = blockIdx.y;
    int hBase = blockIdx.x * 128;
    const int* gidxA = mode ? (ridx + b*128) : (cidx + b*128);
    const int* gidxE = mode ? (cidx + b*128) : (ridx + b*128);
    int len = mode ? clen[b] : rlen[b];
    const float* Pb = P + (size_t)b*NMX*NMX;

    extern __shared__ float sm[];
    unsigned int smb = (unsigned int)__cvta_generic_to_shared(sm);
    __shared__ int sA[128], sE[128];
    __shared__ float red2[256];
    int t = threadIdx.x;
    int wid = t >> 5, wm = wid >> 2, wn = wid & 3;
    if (t < 128) sA[t] = gidxA[t];
    else sE[t-128] = gidxE[t-128];
    __syncthreads();

    wmma::fragment<wmma::accumulator, 16, 16, 8, float> acc[4][2];
#pragma unroll
    for (int i = 0; i < 4; i++)
#pragma unroll
        for (int j = 0; j < 2; j++) wmma::fill_fragment(acc[i][j], 0.f);

#define PCW_LOAD(k0, buf)                                                    \
    {                                                                        \
        if (mode == 0) {                                                     \
            _Pragma("unroll")                                                \
            for (int p = 0; p < 2; p++) {                                    \
                int id = t + p*256;                                          \
                int n = id >> 2, c4 = id & 3;                                \
                int off = (buf)*PASTG + n*20 + c4*4;                         \
                cpa16(smb + off*4, Pb + n*128 + (k0) + c4*4);                \
            }                                                                \
        } else {                                                             \
            _Pragma("unroll")                                                \
            for (int p = 0; p < 2; p++) {                                    \
                int id = t + p*256;                                          \
                int kr = id >> 5, m4 = id & 31;                              \
                int off = (buf)*PASTG + kr*132 + m4*4;                       \
                cpa16(smb + off*4, Pb + ((k0) + kr)*128 + m4*4);             \
            }                                                                \
        }                                                                    \
        _Pragma("unroll")                                                    \
        for (int p = 0; p < 2; p++) {                                        \
            int id = t + p*256;                                              \
            int kr = id >> 5, n4 = id & 31;                                  \
            int gh = hBase + n4*4;                                           \
            int off = 2*PASTG + (buf)*BSTG + kr*SB + n4*4;                   \
            if (gh < 300) cpa16(smb + off*4, Hc2 + (size_t)sA[(k0)+kr]*300 + gh);\
            else *(float4*)(sm + off) = make_float4(0.f,0.f,0.f,0.f);        \
        }                                                                    \
        cpa_commit();                                                        \
    }

    PCW_LOAD(0, 0);
    for (int ti = 0; ti < 8; ti++) {
        int cur = ti & 1;
        if (ti + 1 < 8) { PCW_LOAD((ti+1)*16, cur^1); cpa_wait<1>(); }
        else            { cpa_wait<0>(); }
        __syncthreads();
        const float* ap = sm + cur*PASTG;
        const float* bp = sm + 2*PASTG + cur*BSTG;
#pragma unroll
        for (int ks = 0; ks < 2; ks++) {
            int k8 = ks*8;
            wmma::fragment<wmma::matrix_b, 16, 16, 8, wmma::precision::tf32, wmma::row_major> bf[2];
#pragma unroll
            for (int j = 0; j < 2; j++)
                wmma::load_matrix_sync(bf[j], bp + k8*SB + wn*32 + j*16, SB);
            if (mode == 0) {
#pragma unroll
                for (int i = 0; i < 4; i++) {
                    wmma::fragment<wmma::matrix_a, 16, 16, 8, wmma::precision::tf32, wmma::row_major> af;
                    wmma::load_matrix_sync(af, ap + (wm*64 + i*16)*20 + k8, 20);
                    wmma::mma_sync(acc[i][0], af, bf[0], acc[i][0]);
                    wmma::mma_sync(acc[i][1], af, bf[1], acc[i][1]);
                }
            } else {
#pragma unroll
                for (int i = 0; i < 4; i++) {
                    wmma::fragment<wmma::matrix_a, 16, 16, 8, wmma::precision::tf32, wmma::col_major> af;
                    wmma::load_matrix_sync(af, ap + k8*132 + wm*64 + i*16, 132);
                    wmma::mma_sync(acc[i][0], af, bf[0], acc[i][0]);
                    wmma::mma_sync(acc[i][1], af, bf[1], acc[i][1]);
                }
            }
        }
        __syncthreads();
    }
#undef PCW_LOAD

    float colsum = 0.f;
    int hc = t & 127, rh = t >> 7;
    int hg = hBase + hc;
    float bcv = (hg < 300) ? bc[hg] : 0.f;
#pragma unroll
    for (int ph = 0; ph < 2; ph++) {
        if (wm == ph) {
#pragma unroll
            for (int i = 0; i < 4; i++)
#pragma unroll
                for (int j = 0; j < 2; j++)
                    wmma::store_matrix_sync(sm + (i*16)*132 + wn*32 + j*16,
                                            acc[i][j], 132, wmma::mem_row_major);
        }
        __syncthreads();
        if (hg < 300) {
            for (int r = rh*32; r < rh*32 + 32; r++) {
                int gr = ph*64 + r;
                if (gr < len)
                    colsum += fmaxf(sm[r*132 + hc] + Hc1[(size_t)sE[gr]*300 + hg] + bcv, 0.f);
            }
        }
        __syncthreads();
    }
    red2[t] = colsum;
    __syncthreads();
    if (t < 128 && hg < 300) {
        float* outp = mode ? cc : cr;
        outp[b*HH + hg] = red2[t] + red2[t + 128];
    }
}

// ============================================================
// 6) classifier head
// ============================================================
__global__ void k_cls(const float* __restrict__ cr,
                      const float* __restrict__ cc,
                      const float* __restrict__ Wcls,
                      const float* __restrict__ bcls,
                      const float* __restrict__ Wout,
                      const float* __restrict__ bout,
                      float* __restrict__ out) {
    int b = blockIdx.x;
    int t = threadIdx.x;              // 320 threads
    __shared__ float x[2*HH];
    for (int i = t; i < 2*HH; i += 320)
        x[i] = (i < HH) ? cr[b*HH + i] : cc[b*HH + i - HH];
    __syncthreads();
    float z = 0.f;
    if (t < HH) {
        float a0 = 0.f, a1 = 0.f, a2 = 0.f, a3 = 0.f;
#pragma unroll 4
        for (int k = 0; k < 2*HH; k += 4) {
            a0 += x[k+0]*Wcls[(k+0)*HH + t];
            a1 += x[k+1]*Wcls[(k+1)*HH + t];
            a2 += x[k+2]*Wcls[(k+2)*HH + t];
            a3 += x[k+3]*Wcls[(k+3)*HH + t];
        }
        z = fmaxf((a0+a1)+(a2+a3) + bcls[t], 0.f);
    }
    float s0 = (t < HH) ? z*Wout[t*2 + 0] : 0.f;
    float s1 = (t < HH) ? z*Wout[t*2 + 1] : 0.f;
#pragma unroll
    for (int o = 16; o; o >>= 1) {
        s0 += __shfl_down_sync(0xffffffffu, s0, o);
        s1 += __shfl_down_sync(0xffffffffu, s1, o);
    }
    __shared__ float r0[10], r1[10];
    if ((t & 31) == 0) { r0[t >> 5] = s0; r1[t >> 5] = s1; }
    __syncthreads();
    if (t == 0) {
        float a = 0.f, c = 0.f;
#pragma unroll
        for (int i = 0; i < 10; i++) { a += r0[i]; c += r1[i]; }
        out[b*2 + 0] = a + bout[0];
        out[b*2 + 1] = c + bout[1];
    }
}

// ============================================================
// launch
// ============================================================
extern "C" void kernel_launch(void* const* d_in, const int* in_sizes, int n_in,
                              void* d_out, int out_size) {
    const int*   data    = (const int*)  d_in[0];
    const int*   row_idx = (const int*)  d_in[1];
    const int*   col_idx = (const int*)  d_in[2];
    const int*   row_len = (const int*)  d_in[3];
    const int*   col_len = (const int*)  d_in[4];
    const float* emb     = (const float*)d_in[5];
    const float* W1      = (const float*)d_in[6];
    const float* b1      = (const float*)d_in[7];
    const float* W2      = (const float*)d_in[8];
    const float* b2      = (const float*)d_in[9];
    const float* Wc      = (const float*)d_in[10];
    const float* bc      = (const float*)d_in[11];
    const float* Wcls    = (const float*)d_in[12];
    const float* bcls    = (const float*)d_in[13];
    const float* Wout    = (const float*)d_in[14];
    const float* bout    = (const float*)d_in[15];
    float* out = (float*)d_out;

    float *enc, *h1, *henc, *henct, *Hc, *Wr, *invh, *Pb, *cr, *cc;
    cudaGetSymbolAddress((void**)&enc,   g_enc);
    cudaGetSymbolAddress((void**)&h1,    g_h1);
    cudaGetSymbolAddress((void**)&henc,  g_henc);
    cudaGetSymbolAddress((void**)&henct, g_henct);
    cudaGetSymbolAddress((void**)&Hc,    g_Hc);
    cudaGetSymbolAddress((void**)&Wr,    g_Wr);
    cudaGetSymbolAddress((void**)&invh,  g_invh);
    cudaGetSymbolAddress((void**)&Pb,    g_Pmat);
    cudaGetSymbolAddress((void**)&cr,    g_cr);
    cudaGetSymbolAddress((void**)&cc,    g_cc);
    float* W1r = Wr;
    float* W2r = Wr + HH*HH;
    float* Wcr = Wr + 2*HH*HH;
    float* Hc1 = Hc;
    float* Hc2 = Hc + (long)NSAMP*HH;

    cudaFuncSetAttribute(k_wgemm2<true>,  cudaFuncAttributeMaxDynamicSharedMemorySize, WG2_SMEM);
    cudaFuncSetAttribute(k_wgemm2<false>, cudaFuncAttributeMaxDynamicSharedMemorySize, WG2_SMEM);
    cudaFuncSetAttribute(k_costsink, cudaFuncAttributeMaxDynamicSharedMemorySize, CS_SMEM);
    cudaFuncSetAttribute(k_pcmp_w, cudaFuncAttributeMaxDynamicSharedMemorySize, PC_SMEM);

    // 0) round weights into scratch
    k_roundw<<<(2*HH*HH + 255)/256, 256>>>(W1, W2, Wc, Wr);
    // 1) embedding pool (enc rounded to tf32)
    k_embed<<<NSAMP, 320>>>(data, emb, enc);
    // 2) FFN
    dim3 gF(3, 79, 1);
    k_wgemm2<true><<<gF, 256, WG2_SMEM>>>(enc, W1r, b1, h1, nullptr,
                                          NSAMP, HH, DD, 0, 0, 1);
    k_wgemm2<true><<<gF, 256, WG2_SMEM>>>(h1, W2r, b2, henc, henct,
                                          NSAMP, HH, HH, 0, 0, 0);

    // fork: Hc GEMM on side stream
    cudaEventRecord(g_hx.eHenc, 0);
    cudaStreamWaitEvent(g_hx.sB, g_hx.eHenc, 0);
    dim3 gHc(3, 79, 2);
    k_wgemm2<false><<<gHc, 256, WG2_SMEM, g_hx.sB>>>(henct, Wcr, nullptr, Hc, nullptr,
                                                     NSAMP, HH, HH, (long)HH*HH,
                                                     (long)NSAMP*HH, 2);
    cudaEventRecord(g_hx.eHc, g_hx.sB);

    // chain A: fused cost+sinkhorn (exact fp32)
    k_invnorm<<<(NSAMP + 7)/8, 256>>>(henc, invh);
    k_costsink<<<BB, 256, CS_SMEM>>>(henc, invh, row_idx, col_idx,
                                     row_len, col_len, Pb);

    // join
    cudaStreamWaitEvent(0, g_hx.eHc, 0);
    k_pcmp_w<<<dim3(3, 2, BB), 256, PC_SMEM>>>(Pb, Hc1, Hc2, bc, row_idx, col_idx,
                                               row_len, col_len, cr, cc);
    k_cls<<<BB, 320>>>(cr, cc, Wcls, bcls, Wout, bout, out);
}

// round 11
// speedup vs baseline: 1.3877x; 1.0338x over previous
#include <cuda_runtime.h>
#include <math.h>
#include <mma.h>
using namespace nvcuda;

// ---- problem dims ----
#define NSAMP 10000
#define LTOK  32
#define DD    300
#define HH    300
#define BB    256
#define NMX   128
#define ITERS 50

// ---- scratch ----
__device__ float g_enc [NSAMP*DD];
__device__ float g_h1  [NSAMP*HH];
__device__ float g_henc[NSAMP*HH];
__device__ float g_henct[NSAMP*HH];
__device__ float g_Hc  [2*NSAMP*HH];
__device__ float g_Wr  [4*HH*HH];
__device__ float g_invh[NSAMP];
__device__ float g_Pmat[BB*NMX*NMX];
__device__ float g_cr  [BB*HH];
__device__ float g_cc  [BB*HH];

// ---- streams/events (static init, pre-checkpoint) ----
struct HxStreams {
    cudaStream_t sB;
    cudaEvent_t eHenc, eHc;
    HxStreams() {
        cudaStreamCreateWithFlags(&sB, cudaStreamNonBlocking);
        cudaEventCreateWithFlags(&eHenc, cudaEventDisableTiming);
        cudaEventCreateWithFlags(&eHc,   cudaEventDisableTiming);
    }
};
static HxStreams g_hx;

// ---- cp.async helpers ----
__device__ __forceinline__ void cpa16(unsigned int dst, const void* src) {
    asm volatile("cp.async.ca.shared.global [%0], [%1], 16;" :: "r"(dst), "l"(src));
}
__device__ __forceinline__ void cpa_commit() {
    asm volatile("cp.async.commit_group;");
}
template<int NN> __device__ __forceinline__ void cpa_wait() {
    asm volatile("cp.async.wait_group %0;" :: "n"(NN));
}

__device__ __forceinline__ float tf32r(float x) { return wmma::__float_to_tf32(x); }
__device__ __forceinline__ float4 tf32r4(float4 v) {
    v.x = tf32r(v.x); v.y = tf32r(v.y); v.z = tf32r(v.z); v.w = tf32r(v.w);
    return v;
}

// ============================================================
// 0) pre-round weights to tf32 (RN) into scratch
// ============================================================
__global__ void k_roundw(const float* __restrict__ W1, const float* __restrict__ W2,
                         const float* __restrict__ Wc, float* __restrict__ Wr) {
    int i = blockIdx.x * 256 + threadIdx.x;
    if (i < HH*HH)   Wr[i]           = tf32r(W1[i]);
    if (i < HH*HH)   Wr[HH*HH + i]   = tf32r(W2[i]);
    if (i < 2*HH*HH) Wr[2*HH*HH + i] = tf32r(Wc[i]);
}

// ============================================================
// 1) embedding + masked mean pool (output rounded to tf32)
// ============================================================
__global__ void k_embed(const int* __restrict__ data,
                        const float* __restrict__ emb,
                        float* __restrict__ enc) {
    int s = blockIdx.x;
    int t = threadIdx.x;            // 320 threads
    __shared__ int toks[LTOK];
    if (t < LTOK) toks[t] = data[s*LTOK + t];
    __syncthreads();
    int cnt = 0;
#pragma unroll
    for (int l = 0; l < LTOK; l++) cnt += (toks[l] != 0);
    float inv = 1.0f / (float)(cnt > 0 ? cnt : 1);
    if (t < DD) {
        float acc = 0.f;
#pragma unroll
        for (int l = 0; l < LTOK; l++) {
            int tok = toks[l];
            if (tok != 0) acc += emb[tok*DD + t];
        }
        enc[s*DD + t] = tf32r(acc * inv);
    }
}

// ============================================================
// 2) WMMA tf32 GEMM (inputs pre-rounded), 128x128, BK=16
// ============================================================
#define SA   20
#define SB   132
#define ASTG (128*SA)
#define BSTG (16*SB)
#define WG2_SMEM (2*(ASTG+BSTG)*4)

template<bool RELU>
__global__ void __launch_bounds__(256, 2)
k_wgemm2(const float* __restrict__ A, const float* __restrict__ B,
         const float* __restrict__ bias, float* __restrict__ C, float* __restrict__ C2,
         int M, int N, int K, long bStride, long cStride, int round_mask) {
    B += (long)blockIdx.z * bStride;
    C += (long)blockIdx.z * cStride;
    bool rnd = (round_mask >> blockIdx.z) & 1;
    extern __shared__ float sm[];
    unsigned int smb = (unsigned int)__cvta_generic_to_shared(sm);
    int t = threadIdx.x;
    int wid = t >> 5, wm = wid >> 2, wn = wid & 3;
    int mBase = blockIdx.y * 128, nBase = blockIdx.x * 128;
    int nT = (K + 15) >> 4;

    wmma::fragment<wmma::accumulator, 16, 16, 8, float> acc[4][2];
#pragma unroll
    for (int i = 0; i < 4; i++)
#pragma unroll
        for (int j = 0; j < 2; j++) wmma::fill_fragment(acc[i][j], 0.f);

#define W2_LOAD(k0, buf)                                                     \
    {                                                                        \
        _Pragma("unroll")                                                    \
        for (int p = 0; p < 2; p++) {                                        \
            int id = t + p*256;                                              \
            int m = id >> 2, c4 = id & 3;                                    \
            int gm = mBase + m, gk = (k0) + c4*4;                            \
            int off = (buf)*ASTG + m*SA + c4*4;                              \
            if (gm < M && gk < K) cpa16(smb + off*4, A + (size_t)gm*K + gk); \
            else *(float4*)(sm + off) = make_float4(0.f,0.f,0.f,0.f);        \
        }                                                                    \
        _Pragma("unroll")                                                    \
        for (int p = 0; p < 2; p++) {                                        \
            int id = t + p*256;                                              \
            int kr = id >> 5, n4 = id & 31;                                  \
            int gk = (k0) + kr, gn = nBase + n4*4;                           \
            int off = 2*ASTG + (buf)*BSTG + kr*SB + n4*4;                    \
            if (gk < K && gn < N) cpa16(smb + off*4, B + (size_t)gk*N + gn); \
            else *(float4*)(sm + off) = make_float4(0.f,0.f,0.f,0.f);        \
        }                                                                    \
        cpa_commit();                                                        \
    }

    W2_LOAD(0, 0);
    for (int ti = 0; ti < nT; ti++) {
        int cur = ti & 1;
        if (ti + 1 < nT) { W2_LOAD((ti+1)*16, cur^1); cpa_wait<1>(); }
        else             { cpa_wait<0>(); }
        __syncthreads();
        const float* ap = sm + cur*ASTG;
        const float* bp = sm + 2*ASTG + cur*BSTG;
#pragma unroll
        for (int ks = 0; ks < 2; ks++) {
            int k8 = ks*8;
            wmma::fragment<wmma::matrix_b, 16, 16, 8, wmma::precision::tf32, wmma::row_major> bf[2];
#pragma unroll
            for (int j = 0; j < 2; j++)
                wmma::load_matrix_sync(bf[j], bp + k8*SB + wn*32 + j*16, SB);
#pragma unroll
            for (int i = 0; i < 4; i++) {
                wmma::fragment<wmma::matrix_a, 16, 16, 8, wmma::precision::tf32, wmma::row_major> af;
                wmma::load_matrix_sync(af, ap + (wm*64 + i*16)*SA + k8, SA);
                wmma::mma_sync(acc[i][0], af, bf[0], acc[i][0]);
                wmma::mma_sync(acc[i][1], af, bf[1], acc[i][1]);
            }
        }
        __syncthreads();
    }
#undef W2_LOAD

#pragma unroll
    for (int ph = 0; ph < 2; ph++) {
        if (wm == ph) {
#pragma unroll
            for (int i = 0; i < 4; i++)
#pragma unroll
                for (int j = 0; j < 2; j++)
                    wmma::store_matrix_sync(sm + (i*16)*132 + wn*32 + j*16,
                                            acc[i][j], 132, wmma::mem_row_major);
        }
        __syncthreads();
#pragma unroll
        for (int q = 0; q < 8; q++) {
            int idx = t + q*256;
            int row = idx >> 5, c4 = idx & 31;
            int gm = mBase + ph*64 + row, gn = nBase + c4*4;
            if (gm < M && gn < N) {
                float4 v = *(float4*)&sm[row*132 + c4*4];
                float4 bb = bias ? *(const float4*)&bias[gn] : make_float4(0.f,0.f,0.f,0.f);
                v.x += bb.x; v.y += bb.y; v.z += bb.z; v.w += bb.w;
                if (RELU) {
                    v.x = fmaxf(v.x, 0.f); v.y = fmaxf(v.y, 0.f);
                    v.z = fmaxf(v.z, 0.f); v.w = fmaxf(v.w, 0.f);
                }
                if (C2) {
                    *(float4*)&C[(size_t)gm*N + gn] = v;
                    *(float4*)&C2[(size_t)gm*N + gn] = tf32r4(v);
                } else {
                    if (rnd) v = tf32r4(v);
                    *(float4*)&C[(size_t)gm*N + gn] = v;
                }
            }
        }
        __syncthreads();
    }
}

// ============================================================
// 3) per-sample inverse norm of henc (exact fp32)
// ============================================================
__global__ void k_invnorm(const float* __restrict__ henc, float* __restrict__ invh) {
    int s = blockIdx.x * 8 + (threadIdx.x >> 5);
    int l = threadIdx.x & 31;
    if (s >= NSAMP) return;
    const float4* hp = (const float4*)(henc + (size_t)s*HH);
    float sq = 0.f;
    for (int d4 = l; d4 < 75; d4 += 32) {
        float4 v = hp[d4];
        sq += v.x*v.x + v.y*v.y + v.z*v.z + v.w*v.w;
    }
#pragma unroll
    for (int o = 16; o; o >>= 1) sq += __shfl_down_sync(0xffffffffu, sq, o);
    if (l == 0) invh[s] = 1.0f / (sqrtf(sq) + 1e-8f);
}

// ============================================================
// 4) FUSED cost (WMMA tf32 on henct) + masked exp + Sinkhorn
//    smem: Ks[128*132] | Ast[2][128*20] | Bst[2][128*20]
// ============================================================
#define CS_KS   (128*132)
#define CS_AST  (128*20)
#define CS_SMEM ((CS_KS + 4*CS_AST)*4)   // 108544 bytes

__global__ void __launch_bounds__(256, 2)
k_costsink(const float* __restrict__ henct, const float* __restrict__ invh,
           const int* __restrict__ ridx, const int* __restrict__ cidx,
           const int* __restrict__ rlen, const int* __restrict__ clen,
           float* __restrict__ P) {
    int b = blockIdx.x;
    extern __shared__ float sm[];
    float* Ks  = sm;                    // 128*132
    float* Ast = sm + CS_KS;            // [2][2560]
    float* Bst = Ast + 2*CS_AST;        // [2][2560]
    unsigned int smb = (unsigned int)__cvta_generic_to_shared(sm);
    __shared__ int sr[128], sc[128];
    __shared__ float sir[128], sic[128];
    int t = threadIdx.x;
    int wid = t >> 5, wm = wid >> 2, wn = wid & 3;
    if (t < 128) {
        int i = ridx[b*128 + t];
        sr[t] = i; sir[t] = invh[i];
    } else {
        int i = cidx[b*128 + (t-128)];
        sc[t-128] = i; sic[t-128] = invh[i];
    }
    __syncthreads();

    wmma::fragment<wmma::accumulator, 16, 16, 8, float> acc[4][2];
#pragma unroll
    for (int i = 0; i < 4; i++)
#pragma unroll
        for (int j = 0; j < 2; j++) wmma::fill_fragment(acc[i][j], 0.f);

    // stage A (gathered rows) m-major [128x16] ld20, B (gathered cols) n-major ld20
#define CSW_LOAD(k0, buf)                                                    \
    {                                                                        \
        _Pragma("unroll")                                                    \
        for (int p = 0; p < 2; p++) {                                        \
            int id = t + p*256;                                              \
            int m = id >> 2, c4 = id & 3;                                    \
            int gk = (k0) + c4*4;                                            \
            int offA = CS_KS + (buf)*CS_AST + m*20 + c4*4;                   \
            int offB = CS_KS + 2*CS_AST + (buf)*CS_AST + m*20 + c4*4;        \
            if (gk < 300) {                                                  \
                cpa16(smb + offA*4, henct + (size_t)sr[m]*300 + gk);         \
                cpa16(smb + offB*4, henct + (size_t)sc[m]*300 + gk);         \
            } else {                                                         \
                *(float4*)(sm + offA) = make_float4(0.f,0.f,0.f,0.f);        \
                *(float4*)(sm + offB) = make_float4(0.f,0.f,0.f,0.f);        \
            }                                                                \
        }                                                                    \
        cpa_commit();                                                        \
    }

    CSW_LOAD(0, 0);
    for (int ti = 0; ti < 19; ti++) {
        int cur = ti & 1;
        if (ti + 1 < 19) { CSW_LOAD((ti+1)*16, cur^1); cpa_wait<1>(); }
        else             { cpa_wait<0>(); }
        __syncthreads();
        const float* ap = Ast + cur*CS_AST;
        const float* bp = Bst + cur*CS_AST;
#pragma unroll
        for (int ks = 0; ks < 2; ks++) {
            int k8 = ks*8;
            wmma::fragment<wmma::matrix_b, 16, 16, 8, wmma::precision::tf32, wmma::col_major> bf[2];
#pragma unroll
            for (int j = 0; j < 2; j++)
                wmma::load_matrix_sync(bf[j], bp + (wn*32 + j*16)*20 + k8, 20);
#pragma unroll
            for (int i = 0; i < 4; i++) {
                wmma::fragment<wmma::matrix_a, 16, 16, 8, wmma::precision::tf32, wmma::row_major> af;
                wmma::load_matrix_sync(af, ap + (wm*64 + i*16)*20 + k8, 20);
                wmma::mma_sync(acc[i][0], af, bf[0], acc[i][0]);
                wmma::mma_sync(acc[i][1], af, bf[1], acc[i][1]);
            }
        }
        __syncthreads();
    }
#undef CSW_LOAD

    // dump raw dots into Ks
#pragma unroll
    for (int i = 0; i < 4; i++)
#pragma unroll
        for (int j = 0; j < 2; j++)
            wmma::store_matrix_sync(Ks + (wm*64 + i*16)*132 + wn*32 + j*16,
                                    acc[i][j], 132, wmma::mem_row_major);
    __syncthreads();

    // masked exp epilogue: thread = (row r128, half); keep values in Kreg
    int rl = rlen[b], cl = clen[b];
    int r128 = t & 127, half = t >> 7;
    float4 Kreg[16];
    if (r128 < rl) {
        float ir = sir[r128];
#pragma unroll
        for (int m4 = 0; m4 < 16; m4++) {
            int mm = half*64 + m4*4;
            float4 v4 = *(const float4*)&Ks[r128*132 + mm];
            v4.x = (mm+0 < cl) ? __expf((v4.x*ir*sic[mm+0] - 1.0f)*10.0f) : 0.f;
            v4.y = (mm+1 < cl) ? __expf((v4.y*ir*sic[mm+1] - 1.0f)*10.0f) : 0.f;
            v4.z = (mm+2 < cl) ? __expf((v4.z*ir*sic[mm+2] - 1.0f)*10.0f) : 0.f;
            v4.w = (mm+3 < cl) ? __expf((v4.w*ir*sic[mm+3] - 1.0f)*10.0f) : 0.f;
            Kreg[m4] = v4;
            *(float4*)&Ks[r128*132 + mm] = v4;
        }
    } else {
        float4 z4 = make_float4(0.f,0.f,0.f,0.f);
#pragma unroll
        for (int m4 = 0; m4 < 16; m4++) {
            Kreg[m4] = z4;
            *(float4*)&Ks[r128*132 + half*64 + m4*4] = z4;
        }
    }
    __syncthreads();

    // Sinkhorn: register row pass + smem col pass
    float* u   = Ast;          // 128
    float* v   = Ast + 128;    // 128
    float* red = Ast + 256;    // 1024
    float ra = 1.0f / (float)rl, rb = 1.0f / (float)cl;
    if (t < 128) u[t] = (t < cl) ? 1.0f : 0.0f;
    __syncthreads();

    int w8 = t >> 5, l32 = t & 31;
    const float4* u4h = (const float4*)(u + half*64);
    for (int it = 0; it < ITERS; it++) {
        float4 s4 = make_float4(0.f,0.f,0.f,0.f);
#pragma unroll
        for (int m = 0; m < 16; m++) {
            float4 uu = u4h[m];
            s4.x += Kreg[m].x*uu.x; s4.y += Kreg[m].y*uu.y;
            s4.z += Kreg[m].z*uu.z; s4.w += Kreg[m].w*uu.w;
        }
        red[half*128 + r128] = (s4.x + s4.y) + (s4.z + s4.w);
        __syncthreads();
        if (t < 128) {
            float s = red[t] + red[128 + t];
            v[t] = (t < rl) ? ra / s : 0.f;
        }
        __syncthreads();
        float4 q4 = make_float4(0.f,0.f,0.f,0.f);
#pragma unroll
        for (int rr = 0; rr < 16; rr++) {
            int n = w8*16 + rr;
            float vn = v[n];
            float4 k4 = *(const float4*)(Ks + n*132 + l32*4);
            q4.x += k4.x*vn; q4.y += k4.y*vn;
            q4.z += k4.z*vn; q4.w += k4.w*vn;
        }
        *(float4*)(red + w8*128 + l32*4) = q4;
        __syncthreads();
        if (t < 128) {
            float q = 0.f;
#pragma unroll
            for (int w = 0; w < 8; w++) q += red[w*128 + t];
            u[t] = (t < cl) ? rb / q : 0.f;
        }
        __syncthreads();
    }
    float ut = u[r128];
    float* Pb = P + (size_t)b*NMX*NMX;
    for (int i = half; i < 128; i += 2)
        Pb[i*128 + r128] = tf32r(v[i] * Ks[i*132 + r128] * ut);
}

// ============================================================
// 5) P-GEMM: A (P) staged via cp.async into smem, + fused epilogue
// ============================================================
#define PASTG 2560
#define PC_SMEM ((2*PASTG + 2*BSTG)*4)

__global__ void __launch_bounds__(256, 2)
k_pcmp_w(const float* __restrict__ P,
         const float* __restrict__ Hc1, const float* __restrict__ Hc2,
         const float* __restrict__ bc,
         const int* __restrict__ ridx, const int* __restrict__ cidx,
         const int* __restrict__ rlen, const int* __restrict__ clen,
         float* __restrict__ cr, float* __restrict__ cc) {
    int b = blockIdx.z, mode = blockIdx.y;
    int hBase = blockIdx.x * 128;
    const int* gidxA = mode ? (ridx + b*128) : (cidx + b*128);
    const int* gidxE = mode ? (cidx + b*128) : (ridx + b*128);
    int len = mode ? clen[b] : rlen[b];
    const float* Pb = P + (size_t)b*NMX*NMX;

    extern __shared__ float sm[];
    unsigned int smb = (unsigned int)__cvta_generic_to_shared(sm);
    __shared__ int sA[128], sE[128];
    __shared__ float red2[256];
    int t = threadIdx.x;
    int wid = t >> 5, wm = wid >> 2, wn = wid & 3;
    if (t < 128) sA[t] = gidxA[t];
    else sE[t-128] = gidxE[t-128];
    __syncthreads();

    wmma::fragment<wmma::accumulator, 16, 16, 8, float> acc[4][2];
#pragma unroll
    for (int i = 0; i < 4; i++)
#pragma unroll
        for (int j = 0; j < 2; j++) wmma::fill_fragment(acc[i][j], 0.f);

#define PCW_LOAD(k0, buf)                                                    \
    {                                                                        \
        if (mode == 0) {                                                     \
            _Pragma("unroll")                                                \
            for (int p = 0; p < 2; p++) {                                    \
                int id = t + p*256;                                          \
                int n = id >> 2, c4 = id & 3;                                \
                int off = (buf)*PASTG + n*20 + c4*4;                         \
                cpa16(smb + off*4, Pb + n*128 + (k0) + c4*4);                \
            }                                                                \
        } else {                                                             \
            _Pragma("unroll")                                                \
            for (int p = 0; p < 2; p++) {                                    \
                int id = t + p*256;                                          \
                int kr = id >> 5, m4 = id & 31;                              \
                int off = (buf)*PASTG + kr*132 + m4*4;                       \
                cpa16(smb + off*4, Pb + ((k0) + kr)*128 + m4*4);             \
            }                                                                \
        }                                                                    \
        _Pragma("unroll")                                                    \
        for (int p = 0; p < 2; p++) {                                        \
            int id = t + p*256;                                              \
            int kr = id >> 5, n4 = id & 31;                                  \
            int gh = hBase + n4*4;                                           \
            int off = 2*PASTG + (buf)*BSTG + kr*SB + n4*4;                   \
            if (gh < 300) cpa16(smb + off*4, Hc2 + (size_t)sA[(k0)+kr]*300 + gh);\
            else *(float4*)(sm + off) = make_float4(0.f,0.f,0.f,0.f);        \
        }                                                                    \
        cpa_commit();                                                        \
    }

    PCW_LOAD(0, 0);
    for (int ti = 0; ti < 8; ti++) {
        int cur = ti & 1;
        if (ti + 1 < 8) { PCW_LOAD((ti+1)*16, cur^1); cpa_wait<1>(); }
        else            { cpa_wait<0>(); }
        __syncthreads();
        const float* ap = sm + cur*PASTG;
        const float* bp = sm + 2*PASTG + cur*BSTG;
#pragma unroll
        for (int ks = 0; ks < 2; ks++) {
            int k8 = ks*8;
            wmma::fragment<wmma::matrix_b, 16, 16, 8, wmma::precision::tf32, wmma::row_major> bf[2];
#pragma unroll
            for (int j = 0; j < 2; j++)
                wmma::load_matrix_sync(bf[j], bp + k8*SB + wn*32 + j*16, SB);
            if (mode == 0) {
#pragma unroll
                for (int i = 0; i < 4; i++) {
                    wmma::fragment<wmma::matrix_a, 16, 16, 8, wmma::precision::tf32, wmma::row_major> af;
                    wmma::load_matrix_sync(af, ap + (wm*64 + i*16)*20 + k8, 20);
                    wmma::mma_sync(acc[i][0], af, bf[0], acc[i][0]);
                    wmma::mma_sync(acc[i][1], af, bf[1], acc[i][1]);
                }
            } else {
#pragma unroll
                for (int i = 0; i < 4; i++) {
                    wmma::fragment<wmma::matrix_a, 16, 16, 8, wmma::precision::tf32, wmma::col_major> af;
                    wmma::load_matrix_sync(af, ap + k8*132 + wm*64 + i*16, 132);
                    wmma::mma_sync(acc[i][0], af, bf[0], acc[i][0]);
                    wmma::mma_sync(acc[i][1], af, bf[1], acc[i][1]);
                }
            }
        }
        __syncthreads();
    }
#undef PCW_LOAD

    float colsum = 0.f;
    int hc = t & 127, rh = t >> 7;
    int hg = hBase + hc;
    float bcv = (hg < 300) ? bc[hg] : 0.f;
#pragma unroll
    for (int ph = 0; ph < 2; ph++) {
        if (wm == ph) {
#pragma unroll
            for (int i = 0; i < 4; i++)
#pragma unroll
                for (int j = 0; j < 2; j++)
                    wmma::store_matrix_sync(sm + (i*16)*132 + wn*32 + j*16,
                                            acc[i][j], 132, wmma::mem_row_major);
        }
        __syncthreads();
        if (hg < 300) {
            for (int r = rh*32; r < rh*32 + 32; r++) {
                int gr = ph*64 + r;
                if (gr < len)
                    colsum += fmaxf(sm[r*132 + hc] + Hc1[(size_t)sE[gr]*300 + hg] + bcv, 0.f);
            }
        }
        __syncthreads();
    }
    red2[t] = colsum;
    __syncthreads();
    if (t < 128 && hg < 300) {
        float* outp = mode ? cc : cr;
        outp[b*HH + hg] = red2[t] + red2[t + 128];
    }
}

// ============================================================
// 6) classifier head
// ============================================================
__global__ void k_cls(const float* __restrict__ cr,
                      const float* __restrict__ cc,
                      const float* __restrict__ Wcls,
                      const float* __restrict__ bcls,
                      const float* __restrict__ Wout,
                      const float* __restrict__ bout,
                      float* __restrict__ out) {
    int b = blockIdx.x;
    int t = threadIdx.x;              // 320 threads
    __shared__ float x[2*HH];
    for (int i = t; i < 2*HH; i += 320)
        x[i] = (i < HH) ? cr[b*HH + i] : cc[b*HH + i - HH];
    __syncthreads();
    float z = 0.f;
    if (t < HH) {
        float a0 = 0.f, a1 = 0.f, a2 = 0.f, a3 = 0.f;
#pragma unroll 4
        for (int k = 0; k < 2*HH; k += 4) {
            a0 += x[k+0]*Wcls[(k+0)*HH + t];
            a1 += x[k+1]*Wcls[(k+1)*HH + t];
            a2 += x[k+2]*Wcls[(k+2)*HH + t];
            a3 += x[k+3]*Wcls[(k+3)*HH + t];
        }
        z = fmaxf((a0+a1)+(a2+a3) + bcls[t], 0.f);
    }
    float s0 = (t < HH) ? z*Wout[t*2 + 0] : 0.f;
    float s1 = (t < HH) ? z*Wout[t*2 + 1] : 0.f;
#pragma unroll
    for (int o = 16; o; o >>= 1) {
        s0 += __shfl_down_sync(0xffffffffu, s0, o);
        s1 += __shfl_down_sync(0xffffffffu, s1, o);
    }
    __shared__ float r0[10], r1[10];
    if ((t & 31) == 0) { r0[t >> 5] = s0; r1[t >> 5] = s1; }
    __syncthreads();
    if (t == 0) {
        float a = 0.f, c = 0.f;
#pragma unroll
        for (int i = 0; i < 10; i++) { a += r0[i]; c += r1[i]; }
        out[b*2 + 0] = a + bout[0];
        out[b*2 + 1] = c + bout[1];
    }
}

// ============================================================
// launch
// ============================================================
extern "C" void kernel_launch(void* const* d_in, const int* in_sizes, int n_in,
                              void* d_out, int out_size) {
    const int*   data    = (const int*)  d_in[0];
    const int*   row_idx = (const int*)  d_in[1];
    const int*   col_idx = (const int*)  d_in[2];
    const int*   row_len = (const int*)  d_in[3];
    const int*   col_len = (const int*)  d_in[4];
    const float* emb     = (const float*)d_in[5];
    const float* W1      = (const float*)d_in[6];
    const float* b1      = (const float*)d_in[7];
    const float* W2      = (const float*)d_in[8];
    const float* b2      = (const float*)d_in[9];
    const float* Wc      = (const float*)d_in[10];
    const float* bc      = (const float*)d_in[11];
    const float* Wcls    = (const float*)d_in[12];
    const float* bcls    = (const float*)d_in[13];
    const float* Wout    = (const float*)d_in[14];
    const float* bout    = (const float*)d_in[15];
    float* out = (float*)d_out;

    float *enc, *h1, *henc, *henct, *Hc, *Wr, *invh, *Pb, *cr, *cc;
    cudaGetSymbolAddress((void**)&enc,   g_enc);
    cudaGetSymbolAddress((void**)&h1,    g_h1);
    cudaGetSymbolAddress((void**)&henc,  g_henc);
    cudaGetSymbolAddress((void**)&henct, g_henct);
    cudaGetSymbolAddress((void**)&Hc,    g_Hc);
    cudaGetSymbolAddress((void**)&Wr,    g_Wr);
    cudaGetSymbolAddress((void**)&invh,  g_invh);
    cudaGetSymbolAddress((void**)&Pb,    g_Pmat);
    cudaGetSymbolAddress((void**)&cr,    g_cr);
    cudaGetSymbolAddress((void**)&cc,    g_cc);
    float* W1r = Wr;
    float* W2r = Wr + HH*HH;
    float* Wcr = Wr + 2*HH*HH;
    float* Hc1 = Hc;
    float* Hc2 = Hc + (long)NSAMP*HH;

    cudaFuncSetAttribute(k_wgemm2<true>,  cudaFuncAttributeMaxDynamicSharedMemorySize, WG2_SMEM);
    cudaFuncSetAttribute(k_wgemm2<false>, cudaFuncAttributeMaxDynamicSharedMemorySize, WG2_SMEM);
    cudaFuncSetAttribute(k_costsink, cudaFuncAttributeMaxDynamicSharedMemorySize, CS_SMEM);
    cudaFuncSetAttribute(k_pcmp_w, cudaFuncAttributeMaxDynamicSharedMemorySize, PC_SMEM);

    // 0) round weights into scratch
    k_roundw<<<(2*HH*HH + 255)/256, 256>>>(W1, W2, Wc, Wr);
    // 1) embedding pool (enc rounded to tf32)
    k_embed<<<NSAMP, 320>>>(data, emb, enc);
    // 2) FFN
    dim3 gF(3, 79, 1);
    k_wgemm2<true><<<gF, 256, WG2_SMEM>>>(enc, W1r, b1, h1, nullptr,
                                          NSAMP, HH, DD, 0, 0, 1);
    k_wgemm2<true><<<gF, 256, WG2_SMEM>>>(h1, W2r, b2, henc, henct,
                                          NSAMP, HH, HH, 0, 0, 0);

    // fork: Hc GEMM on side stream
    cudaEventRecord(g_hx.eHenc, 0);
    cudaStreamWaitEvent(g_hx.sB, g_hx.eHenc, 0);
    dim3 gHc(3, 79, 2);
    k_wgemm2<false><<<gHc, 256, WG2_SMEM, g_hx.sB>>>(henct, Wcr, nullptr, Hc, nullptr,
                                                     NSAMP, HH, HH, (long)HH*HH,
                                                     (long)NSAMP*HH, 2);
    cudaEventRecord(g_hx.eHc, g_hx.sB);

    // chain A: fused WMMA cost + masked exp + Sinkhorn
    k_invnorm<<<(NSAMP + 7)/8, 256>>>(henc, invh);
    k_costsink<<<BB, 256, CS_SMEM>>>(henct, invh, row_idx, col_idx,
                                     row_len, col_len, Pb);

    // join
    cudaStreamWaitEvent(0, g_hx.eHc, 0);
    k_pcmp_w<<<dim3(3, 2, BB), 256, PC_SMEM>>>(Pb, Hc1, Hc2, bc, row_idx, col_idx,
                                               row_len, col_len, cr, cc);
    k_cls<<<BB, 320>>>(cr, cc, Wcls, bcls, Wout, bout, out);
}